// round 6
// baseline (speedup 1.0000x reference)
#include <cuda_runtime.h>
#include <cuda_bf16.h>
#include <math.h>
#include <stdint.h>

// ---------------- Problem constants ----------------
#define D_MODEL 1024
#define NHEAD   16
#define HDIM    64
#define DFF     4096
#define TM      512
#define TA      512
#define BATCH   32
#define NTOK    (TM * BATCH)   // 16384
#define NBEATS  64
#define LN_EPS  1e-5f

// ---------------- fp32 scratch ----------------
__device__ float g_tmp [NTOK * D_MODEL];
__device__ float g_x1  [NTOK * D_MODEL];
__device__ float g_x2  [NTOK * D_MODEL];
__device__ float g_ff2 [NTOK * D_MODEL];
__device__ float g_bias[TM * TA];

// ---------------- bf16 split scratch ----------------
__device__ __nv_bfloat16 g_Xhi [NTOK * D_MODEL];
__device__ __nv_bfloat16 g_Xlo [NTOK * D_MODEL];
__device__ __nv_bfloat16 g_Hhi [NTOK * DFF];
__device__ __nv_bfloat16 g_Hlo [NTOK * DFF];
__device__ __nv_bfloat16 g_QKVhi[NTOK * 3 * D_MODEL];
__device__ __nv_bfloat16 g_QKVlo[NTOK * 3 * D_MODEL];
__device__ __nv_bfloat16 g_KVhi[NTOK * 2 * D_MODEL];
__device__ __nv_bfloat16 g_KVlo[NTOK * 2 * D_MODEL];
__device__ __nv_bfloat16 g_CQhi[NTOK * D_MODEL];
__device__ __nv_bfloat16 g_CQlo[NTOK * D_MODEL];
__device__ __nv_bfloat16 g_Whi[16777216];
__device__ __nv_bfloat16 g_Wlo[16777216];

#define W_SAIN   0
#define W_SAOUT  3145728
#define W_CAIN   4194304
#define W_CAOUT  7340032
#define W_LIN1   8388608
#define W_LIN2  12582912
#define W_TOTAL 16777216

// ================= helpers (non-'a' PTX only) =================
__device__ __forceinline__ uint32_t smem_u32(const void* p) {
    uint32_t a;
    asm("{ .reg .u64 t; cvta.to.shared.u64 t, %1; cvt.u32.u64 %0, t; }" : "=r"(a) : "l"(p));
    return a;
}
__device__ __forceinline__ void cp_async16(uint32_t saddr, const void* g) {
    asm volatile("cp.async.cg.shared.global [%0], [%1], 16;" :: "r"(saddr), "l"(g));
}
__device__ __forceinline__ void cp_commit() {
    asm volatile("cp.async.commit_group;" ::: "memory");
}
__device__ __forceinline__ void ldsm_x4(uint32_t (&r)[4], uint32_t addr) {
    asm volatile("ldmatrix.sync.aligned.m8n8.x4.shared.b16 {%0,%1,%2,%3}, [%4];"
                 : "=r"(r[0]), "=r"(r[1]), "=r"(r[2]), "=r"(r[3]) : "r"(addr));
}
__device__ __forceinline__ void ldsm_x4_t(uint32_t (&r)[4], uint32_t addr) {
    asm volatile("ldmatrix.sync.aligned.m8n8.x4.trans.shared.b16 {%0,%1,%2,%3}, [%4];"
                 : "=r"(r[0]), "=r"(r[1]), "=r"(r[2]), "=r"(r[3]) : "r"(addr));
}
__device__ __forceinline__ void mma16816(float (&d)[4], const uint32_t (&a)[4],
                                         uint32_t b0, uint32_t b1) {
    asm volatile(
        "mma.sync.aligned.m16n8k16.row.col.f32.bf16.bf16.f32 "
        "{%0,%1,%2,%3}, {%4,%5,%6,%7}, {%8,%9}, {%0,%1,%2,%3};"
        : "+f"(d[0]), "+f"(d[1]), "+f"(d[2]), "+f"(d[3])
        : "r"(a[0]), "r"(a[1]), "r"(a[2]), "r"(a[3]), "r"(b0), "r"(b1));
}
__device__ __forceinline__ uint32_t pack_bf16x2(float x, float y) {
    return (uint32_t)__bfloat16_as_ushort(__float2bfloat16(x)) |
           ((uint32_t)__bfloat16_as_ushort(__float2bfloat16(y)) << 16);
}
__device__ __forceinline__ void split4(float4 v, uint2& uh, uint2& ul) {
    __nv_bfloat16 h0 = __float2bfloat16(v.x), h1 = __float2bfloat16(v.y);
    __nv_bfloat16 h2 = __float2bfloat16(v.z), h3 = __float2bfloat16(v.w);
    uh.x = (uint32_t)__bfloat16_as_ushort(h0) | ((uint32_t)__bfloat16_as_ushort(h1) << 16);
    uh.y = (uint32_t)__bfloat16_as_ushort(h2) | ((uint32_t)__bfloat16_as_ushort(h3) << 16);
    ul.x = pack_bf16x2(v.x - __bfloat162float(h0), v.y - __bfloat162float(h1));
    ul.y = pack_bf16x2(v.z - __bfloat162float(h2), v.w - __bfloat162float(h3));
}

// ================= converts =================
__global__ __launch_bounds__(256) void cvt_kernel(
    const float* __restrict__ src, __nv_bfloat16* __restrict__ hi,
    __nv_bfloat16* __restrict__ lo, int n)
{
    int i = (blockIdx.x * 256 + threadIdx.x) * 4;
    if (i >= n) return;
    uint2 uh, ul;
    split4(*(const float4*)(src + i), uh, ul);
    *(uint2*)(hi + i) = uh;
    *(uint2*)(lo + i) = ul;
}

// all six weight matrices in ONE launch (keeps ncu -s 5 on a GEMM)
__global__ __launch_bounds__(256) void wcvt_kernel(
    const float* __restrict__ w0, const float* __restrict__ w1,
    const float* __restrict__ w2, const float* __restrict__ w3,
    const float* __restrict__ w4, const float* __restrict__ w5,
    __nv_bfloat16* __restrict__ hi, __nv_bfloat16* __restrict__ lo)
{
    int i = (blockIdx.x * 256 + threadIdx.x) * 4;
    const float* src; int off;
    if      (i < W_SAOUT) { src = w0; off = W_SAIN; }
    else if (i < W_CAIN)  { src = w1; off = W_SAOUT; }
    else if (i < W_CAOUT) { src = w2; off = W_CAIN; }
    else if (i < W_LIN1)  { src = w3; off = W_CAOUT; }
    else if (i < W_LIN2)  { src = w4; off = W_LIN1; }
    else                  { src = w5; off = W_LIN2; }
    uint2 uh, ul;
    split4(*(const float4*)(src + (i - off)), uh, ul);
    *(uint2*)(hi + i) = uh;
    *(uint2*)(lo + i) = ul;
}

// ================= mma.sync GEMM =================
// C[M,N] = A[M,K]*B[N,K]^T + bias, 3-term split-bf16.
// CTA tile 128x256, warp tile 64x64 (8 warps: warp_m in {0,1}, warp_n in {0..3}).
// BK=32, 3 stages. Stage (48KB): Ahi@0 (8K), Alo@8K, Bhi@16K (16K), Blo@32K.
// Rows 64B wide; 16B chunk c of row r at r*64 + ((c^((r>>1)&3))<<4).
#define G_STAGE 49152
#define G_SMEM  (3 * G_STAGE)

__global__ __launch_bounds__(256, 1) void gemm_mma(
    const __nv_bfloat16* __restrict__ Ahi, const __nv_bfloat16* __restrict__ Alo,
    const __nv_bfloat16* __restrict__ Bhi, const __nv_bfloat16* __restrict__ Blo,
    const float* __restrict__ bias, float* __restrict__ Cf,
    __nv_bfloat16* __restrict__ Ohi, __nv_bfloat16* __restrict__ Olo,
    int N, int K, int act)
{
    extern __shared__ __align__(128) char smem[];
    const uint32_t sbase = smem_u32(smem);
    const int tid = threadIdx.x;
    const int lane = tid & 31, wid = tid >> 5;
    const int warp_m = wid & 1, warp_n = wid >> 1;
    const int m0 = blockIdx.y * 128, n0 = blockIdx.x * 256;

    float acc[4][8][4];
    #pragma unroll
    for (int t = 0; t < 4; t++)
        #pragma unroll
        for (int j = 0; j < 8; j++)
            #pragma unroll
            for (int e = 0; e < 4; e++) acc[t][j][e] = 0.0f;

    auto stage_load = [&](int ci, int st) {
        const uint32_t sb = sbase + st * G_STAGE;
        const int kk = ci * 32;
        #pragma unroll
        for (int it = 0; it < 2; it++) {               // A: 512 chunks
            int idx = tid + it * 256;
            int r = idx >> 2, c = idx & 3;
            uint32_t sw = r * 64 + ((c ^ ((r >> 1) & 3)) << 4);
            size_t go = (size_t)(m0 + r) * K + kk + c * 8;
            cp_async16(sb + sw,        Ahi + go);
            cp_async16(sb + 8192 + sw, Alo + go);
        }
        #pragma unroll
        for (int it = 0; it < 4; it++) {               // B: 1024 chunks
            int idx = tid + it * 256;
            int r = idx >> 2, c = idx & 3;
            uint32_t sw = r * 64 + ((c ^ ((r >> 1) & 3)) << 4);
            size_t go = (size_t)(n0 + r) * K + kk + c * 8;
            cp_async16(sb + 16384 + sw, Bhi + go);
            cp_async16(sb + 32768 + sw, Blo + go);
        }
        cp_commit();
    };

    const int lr = lane & 15;
    const int lseg = lane >> 4;
    int arow[4], brow[4];
    #pragma unroll
    for (int t = 0; t < 4; t++) arow[t] = warp_m * 64 + t * 16 + lr;
    #pragma unroll
    for (int u = 0; u < 4; u++) brow[u] = warp_n * 64 + u * 16 + lr;

    const int nch = K >> 5;
    stage_load(0, 0);
    stage_load(1, 1);

    for (int i = 0; i < nch; i++) {
        if (i < nch - 1) asm volatile("cp.async.wait_group 1;" ::: "memory");
        else             asm volatile("cp.async.wait_group 0;" ::: "memory");
        __syncthreads();
        if (i + 2 < nch) stage_load(i + 2, (i + 2) % 3);   // writes stage consumed at i-1

        const uint32_t sb = sbase + (i % 3) * G_STAGE;
        #pragma unroll
        for (int s = 0; s < 2; s++) {
            const int chunk = 2 * s + lseg;
            uint32_t ah[4][4], al[4][4];
            #pragma unroll
            for (int t = 0; t < 4; t++) {
                uint32_t a = sb + arow[t] * 64 + ((chunk ^ ((arow[t] >> 1) & 3)) << 4);
                ldsm_x4(ah[t], a);
                ldsm_x4(al[t], a + 8192);
            }
            #pragma unroll
            for (int u = 0; u < 4; u++) {
                uint32_t a = sb + 16384 + brow[u] * 64 + ((chunk ^ ((brow[u] >> 1) & 3)) << 4);
                uint32_t bh[4], bl[4];
                ldsm_x4(bh, a);
                ldsm_x4(bl, a + 16384);
                #pragma unroll
                for (int t = 0; t < 4; t++) {
                    mma16816(acc[t][2 * u],     ah[t], bh[0], bh[2]);
                    mma16816(acc[t][2 * u + 1], ah[t], bh[1], bh[3]);
                    mma16816(acc[t][2 * u],     ah[t], bl[0], bl[2]);
                    mma16816(acc[t][2 * u + 1], ah[t], bl[1], bl[3]);
                    mma16816(acc[t][2 * u],     al[t], bh[0], bh[2]);
                    mma16816(acc[t][2 * u + 1], al[t], bh[1], bh[3]);
                }
            }
        }
    }

    #pragma unroll
    for (int t = 0; t < 4; t++) {
        const int rbase = m0 + warp_m * 64 + t * 16 + (lane >> 2);
        #pragma unroll
        for (int j = 0; j < 8; j++) {
            const int col = n0 + warp_n * 64 + j * 8 + 2 * (lane & 3);
            const float b0 = __ldg(bias + col), b1 = __ldg(bias + col + 1);
            #pragma unroll
            for (int half = 0; half < 2; half++) {
                const int row = rbase + 8 * half;
                float v0 = acc[t][j][2 * half]     + b0;
                float v1 = acc[t][j][2 * half + 1] + b1;
                if (act) {
                    v0 = 0.5f * v0 * (1.0f + erff(v0 * 0.70710678118654752f));
                    v1 = 0.5f * v1 * (1.0f + erff(v1 * 0.70710678118654752f));
                }
                const size_t off = (size_t)row * N + col;
                if (Cf) {
                    *(float2*)(Cf + off) = make_float2(v0, v1);
                } else {
                    __nv_bfloat16 h0 = __float2bfloat16(v0);
                    __nv_bfloat16 h1 = __float2bfloat16(v1);
                    *(uint32_t*)(Ohi + off) =
                        (uint32_t)__bfloat16_as_ushort(h0) | ((uint32_t)__bfloat16_as_ushort(h1) << 16);
                    *(uint32_t*)(Olo + off) =
                        pack_bf16x2(v0 - __bfloat162float(h0), v1 - __bfloat162float(h1));
                }
            }
        }
    }
}

// ================= FA2-style attention on mma.sync =================
#define AT_BUF  32768
#define AT_SMEM (3 * AT_BUF)

__global__ __launch_bounds__(128) void attn_mma(
    const __nv_bfloat16* __restrict__ Qhi, const __nv_bfloat16* __restrict__ Qlo, int ldq, int qoff,
    const __nv_bfloat16* __restrict__ Khi, const __nv_bfloat16* __restrict__ Klo, int ldk, int koff,
    const __nv_bfloat16* __restrict__ Vhi, const __nv_bfloat16* __restrict__ Vlo, int ldv, int voff,
    __nv_bfloat16* __restrict__ Ohi, __nv_bfloat16* __restrict__ Olo,
    const float* __restrict__ bias, float scale)
{
    extern __shared__ __align__(128) char smem[];
    const uint32_t sbase = smem_u32(smem);
    const int tid = threadIdx.x, lane = tid & 31, w = tid >> 5;
    const int qt = blockIdx.x, bh = blockIdx.y;
    const int b = bh & (BATCH - 1), h = bh >> 5;

    #pragma unroll
    for (int it = 0; it < 4; it++) {
        int idx = tid + it * 128, r = idx >> 3, c = idx & 7;
        uint32_t sw = r * 128 + ((c ^ (r & 7)) << 4);
        size_t g = (size_t)((qt * 64 + r) * BATCH + b) * ldq + qoff + h * HDIM + c * 8;
        cp_async16(sbase + sw,        Qhi + g);
        cp_async16(sbase + 8192 + sw, Qlo + g);
    }
    cp_commit();
    asm volatile("cp.async.wait_group 0;" ::: "memory");
    __syncthreads();

    const int lr = lane & 15, ls = lane >> 4;
    uint32_t qh[4][4], ql[4][4];
    {
        int qrow = w * 16 + lr;
        #pragma unroll
        for (int kc = 0; kc < 4; kc++) {
            int chunk = 2 * kc + ls;
            uint32_t a = sbase + qrow * 128 + ((chunk ^ (qrow & 7)) << 4);
            ldsm_x4(qh[kc], a);
            ldsm_x4(ql[kc], a + 8192);
        }
    }
    __syncthreads();

    auto load_kt = [&](int kt, int st) {
        uint32_t sb = sbase + st * AT_BUF;
        #pragma unroll
        for (int it = 0; it < 4; it++) {
            int idx = tid + it * 128, r = idx >> 3, c = idx & 7;
            uint32_t sw = r * 128 + ((c ^ (r & 7)) << 4);
            size_t rowi = (size_t)((kt * 64 + r) * BATCH + b);
            size_t gk = rowi * ldk + koff + h * HDIM + c * 8;
            size_t gv = rowi * ldv + voff + h * HDIM + c * 8;
            cp_async16(sb + sw,         Khi + gk);
            cp_async16(sb + 8192 + sw,  Klo + gk);
            cp_async16(sb + 16384 + sw, Vhi + gv);
            cp_async16(sb + 24576 + sw, Vlo + gv);
        }
        cp_commit();
    };
    load_kt(0, 0);
    load_kt(1, 1);

    float o[8][4];
    #pragma unroll
    for (int t = 0; t < 8; t++)
        #pragma unroll
        for (int e = 0; e < 4; e++) o[t][e] = 0.0f;
    float mrow0 = -1e30f, mrow1 = -1e30f, lsum0 = 0.0f, lsum1 = 0.0f;

    const int vkbase = ((lane & 16) ? 8 : 0) + (lane & 7);
    const int vcsel  = (lane >> 3) & 1;

    for (int kt = 0; kt < 8; kt++) {
        if (kt < 7) asm volatile("cp.async.wait_group 1;" ::: "memory");
        else        asm volatile("cp.async.wait_group 0;" ::: "memory");
        __syncthreads();
        if (kt + 2 < 8) load_kt(kt + 2, (kt + 2) % 3);
        const uint32_t sb = sbase + (kt % 3) * AT_BUF;

        float s[8][4];
        #pragma unroll
        for (int t = 0; t < 8; t++)
            #pragma unroll
            for (int e = 0; e < 4; e++) s[t][e] = 0.0f;
        #pragma unroll
        for (int kc = 0; kc < 4; kc++) {
            #pragma unroll
            for (int u = 0; u < 4; u++) {
                int krow = u * 16 + lr, chunk = 2 * kc + ls;
                uint32_t a = sb + krow * 128 + ((chunk ^ (krow & 7)) << 4);
                uint32_t kh[4], kl[4];
                ldsm_x4(kh, a);
                ldsm_x4(kl, a + 8192);
                mma16816(s[2 * u],     qh[kc], kh[0], kh[2]);
                mma16816(s[2 * u + 1], qh[kc], kh[1], kh[3]);
                mma16816(s[2 * u],     qh[kc], kl[0], kl[2]);
                mma16816(s[2 * u + 1], qh[kc], kl[1], kl[3]);
                mma16816(s[2 * u],     ql[kc], kh[0], kh[2]);
                mma16816(s[2 * u + 1], ql[kc], kh[1], kh[3]);
            }
        }

        const int row0 = qt * 64 + w * 16 + (lane >> 2);
        if (bias) {
            #pragma unroll
            for (int t = 0; t < 8; t++) {
                int col = kt * 64 + t * 8 + 2 * (lane & 3);
                float2 b0 = *(const float2*)(bias + (size_t)row0 * TA + col);
                float2 b1 = *(const float2*)(bias + (size_t)(row0 + 8) * TA + col);
                s[t][0] = s[t][0] * scale + b0.x; s[t][1] = s[t][1] * scale + b0.y;
                s[t][2] = s[t][2] * scale + b1.x; s[t][3] = s[t][3] * scale + b1.y;
            }
        } else {
            #pragma unroll
            for (int t = 0; t < 8; t++)
                #pragma unroll
                for (int e = 0; e < 4; e++) s[t][e] *= scale;
        }

        float mx0 = -1e30f, mx1 = -1e30f;
        #pragma unroll
        for (int t = 0; t < 8; t++) {
            mx0 = fmaxf(mx0, fmaxf(s[t][0], s[t][1]));
            mx1 = fmaxf(mx1, fmaxf(s[t][2], s[t][3]));
        }
        mx0 = fmaxf(mx0, __shfl_xor_sync(0xffffffffu, mx0, 1));
        mx0 = fmaxf(mx0, __shfl_xor_sync(0xffffffffu, mx0, 2));
        mx1 = fmaxf(mx1, __shfl_xor_sync(0xffffffffu, mx1, 1));
        mx1 = fmaxf(mx1, __shfl_xor_sync(0xffffffffu, mx1, 2));
        float mn0 = fmaxf(mrow0, mx0), mn1 = fmaxf(mrow1, mx1);
        float a0 = __expf(mrow0 - mn0), a1 = __expf(mrow1 - mn1);
        mrow0 = mn0; mrow1 = mn1;

        float sum0 = 0.0f, sum1 = 0.0f;
        uint32_t phi[4][4], plo[4][4];
        #pragma unroll
        for (int t = 0; t < 8; t++) {
            float p0 = __expf(s[t][0] - mn0), p1 = __expf(s[t][1] - mn0);
            float p2 = __expf(s[t][2] - mn1), p3 = __expf(s[t][3] - mn1);
            sum0 += p0 + p1; sum1 += p2 + p3;
            __nv_bfloat16 h0 = __float2bfloat16(p0), h1 = __float2bfloat16(p1);
            __nv_bfloat16 h2 = __float2bfloat16(p2), h3 = __float2bfloat16(p3);
            const int kc = t >> 1, j = (t & 1) * 2;
            phi[kc][j]     = (uint32_t)__bfloat16_as_ushort(h0) | ((uint32_t)__bfloat16_as_ushort(h1) << 16);
            phi[kc][j + 1] = (uint32_t)__bfloat16_as_ushort(h2) | ((uint32_t)__bfloat16_as_ushort(h3) << 16);
            plo[kc][j]     = pack_bf16x2(p0 - __bfloat162float(h0), p1 - __bfloat162float(h1));
            plo[kc][j + 1] = pack_bf16x2(p2 - __bfloat162float(h2), p3 - __bfloat162float(h3));
        }
        sum0 += __shfl_xor_sync(0xffffffffu, sum0, 1);
        sum0 += __shfl_xor_sync(0xffffffffu, sum0, 2);
        sum1 += __shfl_xor_sync(0xffffffffu, sum1, 1);
        sum1 += __shfl_xor_sync(0xffffffffu, sum1, 2);
        lsum0 = lsum0 * a0 + sum0;
        lsum1 = lsum1 * a1 + sum1;
        #pragma unroll
        for (int t = 0; t < 8; t++) {
            o[t][0] *= a0; o[t][1] *= a0;
            o[t][2] *= a1; o[t][3] *= a1;
        }

        #pragma unroll
        for (int kc = 0; kc < 4; kc++) {
            int vkey = kc * 16 + vkbase;
            #pragma unroll
            for (int du = 0; du < 4; du++) {
                int chunk = 2 * du + vcsel;
                uint32_t a = sb + 16384 + vkey * 128 + ((chunk ^ (vkey & 7)) << 4);
                uint32_t vh[4], vl[4];
                ldsm_x4_t(vh, a);
                ldsm_x4_t(vl, a + 8192);
                mma16816(o[2 * du],     phi[kc], vh[0], vh[2]);
                mma16816(o[2 * du + 1], phi[kc], vh[1], vh[3]);
                mma16816(o[2 * du],     phi[kc], vl[0], vl[2]);
                mma16816(o[2 * du + 1], phi[kc], vl[1], vl[3]);
                mma16816(o[2 * du],     plo[kc], vh[0], vh[2]);
                mma16816(o[2 * du + 1], plo[kc], vh[1], vh[3]);
            }
        }
    }

    float inv0 = 1.0f / lsum0, inv1 = 1.0f / lsum1;
    const int row0 = qt * 64 + w * 16 + (lane >> 2);
    #pragma unroll
    for (int t = 0; t < 8; t++) {
        int col = t * 8 + 2 * (lane & 3);
        float v0 = o[t][0] * inv0, v1 = o[t][1] * inv0;
        float v2 = o[t][2] * inv1, v3 = o[t][3] * inv1;
        size_t off0 = (size_t)(row0 * BATCH + b) * D_MODEL + h * HDIM + col;
        size_t off1 = (size_t)((row0 + 8) * BATCH + b) * D_MODEL + h * HDIM + col;
        __nv_bfloat16 h0 = __float2bfloat16(v0), h1 = __float2bfloat16(v1);
        __nv_bfloat16 h2 = __float2bfloat16(v2), h3 = __float2bfloat16(v3);
        *(uint32_t*)(Ohi + off0) = (uint32_t)__bfloat16_as_ushort(h0) | ((uint32_t)__bfloat16_as_ushort(h1) << 16);
        *(uint32_t*)(Olo + off0) = pack_bf16x2(v0 - __bfloat162float(h0), v1 - __bfloat162float(h1));
        *(uint32_t*)(Ohi + off1) = (uint32_t)__bfloat16_as_ushort(h2) | ((uint32_t)__bfloat16_as_ushort(h3) << 16);
        *(uint32_t*)(Olo + off1) = pack_bf16x2(v2 - __bfloat162float(h2), v3 - __bfloat162float(h3));
    }
}

// ---------------- Bias precompute ----------------
__global__ void bias_kernel(const int* __restrict__ beats, float* __restrict__ out) {
    __shared__ int sb[NBEATS];
    int i = blockIdx.x;
    int j = threadIdx.x;
    if (threadIdx.x < NBEATS) sb[threadIdx.x] = beats[threadIdx.x];
    __syncthreads();
    float bb = 0.0f;
    #pragma unroll 8
    for (int n = 0; n < NBEATS; n++) {
        int bf = sb[n];
        if (j == bf) bb = fmaxf(bb, 2.0f);
        if (bf > 0      && j == bf - 1) bb = fmaxf(bb, 1.0f);
        if (bf < TA - 1 && j == bf + 1) bb = fmaxf(bb, 1.0f);
    }
    float scale = (float)(TA - 1) / (float)(TM - 1);
    float d = (float)i * scale - (float)j;
    out[i * TA + j] = -(d * d) * (1.0f / 32.0f) + bb;
}

// ---------------- Fused residual + LayerNorm (+ optional bf16 split out) ----------------
__global__ __launch_bounds__(256) void add_ln_kernel(
    const float* __restrict__ A, const float* __restrict__ Bv,
    const float* __restrict__ gatePtr,
    const float* __restrict__ gamma, const float* __restrict__ beta,
    float* __restrict__ out,
    __nv_bfloat16* __restrict__ ohi, __nv_bfloat16* __restrict__ olo)
{
    int t = blockIdx.x;
    int tid = threadIdx.x;
    float gscale = gatePtr ? tanhf(*gatePtr) : 1.0f;
    const float4* a4 = (const float4*)(A  + (size_t)t * D_MODEL);
    const float4* b4 = (const float4*)(Bv + (size_t)t * D_MODEL);
    float4 av = a4[tid], bv = b4[tid];
    float x0 = av.x + gscale * bv.x;
    float x1 = av.y + gscale * bv.y;
    float x2 = av.z + gscale * bv.z;
    float x3 = av.w + gscale * bv.w;
    float s  = x0 + x1 + x2 + x3;
    float ss = x0 * x0 + x1 * x1 + x2 * x2 + x3 * x3;

    __shared__ float rs[8], rss[8];
    #pragma unroll
    for (int o = 16; o > 0; o >>= 1) {
        s  += __shfl_xor_sync(0xffffffffu, s,  o);
        ss += __shfl_xor_sync(0xffffffffu, ss, o);
    }
    if ((tid & 31) == 0) { rs[tid >> 5] = s; rss[tid >> 5] = ss; }
    __syncthreads();
    float stot = 0.0f, sstot = 0.0f;
    #pragma unroll
    for (int i = 0; i < 8; i++) { stot += rs[i]; sstot += rss[i]; }
    float mean = stot * (1.0f / D_MODEL);
    float var  = sstot * (1.0f / D_MODEL) - mean * mean;
    float rstd = rsqrtf(var + LN_EPS);

    const float4* g4 = (const float4*)gamma;
    const float4* be4 = (const float4*)beta;
    float4 g = g4[tid], be = be4[tid];
    float4 o;
    o.x = (x0 - mean) * rstd * g.x + be.x;
    o.y = (x1 - mean) * rstd * g.y + be.y;
    o.z = (x2 - mean) * rstd * g.z + be.z;
    o.w = (x3 - mean) * rstd * g.w + be.w;
    ((float4*)(out + (size_t)t * D_MODEL))[tid] = o;
    if (ohi) {
        uint2 uh, ul;
        split4(o, uh, ul);
        ((uint2*)(ohi + (size_t)t * D_MODEL))[tid] = uh;
        ((uint2*)(olo + (size_t)t * D_MODEL))[tid] = ul;
    }
}

// ---------------- Launch ----------------
extern "C" void kernel_launch(void* const* d_in, const int* in_sizes, int n_in,
                              void* d_out, int out_size) {
    const float* src      = (const float*)d_in[0];
    const float* audio    = (const float*)d_in[1];
    const int*   beats    = (const int*)  d_in[2];
    const float* sa_in_w  = (const float*)d_in[3];
    const float* sa_in_b  = (const float*)d_in[4];
    const float* sa_out_w = (const float*)d_in[5];
    const float* sa_out_b = (const float*)d_in[6];
    const float* ca_in_w  = (const float*)d_in[7];
    const float* ca_in_b  = (const float*)d_in[8];
    const float* ca_out_w = (const float*)d_in[9];
    const float* ca_out_b = (const float*)d_in[10];
    const float* gate     = (const float*)d_in[11];
    const float* n1_g     = (const float*)d_in[12];
    const float* n1_b     = (const float*)d_in[13];
    const float* nc_g     = (const float*)d_in[14];
    const float* nc_b     = (const float*)d_in[15];
    const float* n2_g     = (const float*)d_in[16];
    const float* n2_b     = (const float*)d_in[17];
    const float* lin1_w   = (const float*)d_in[18];
    const float* lin1_b   = (const float*)d_in[19];
    const float* lin2_w   = (const float*)d_in[20];
    const float* lin2_b   = (const float*)d_in[21];
    float* out = (float*)d_out;

    float *tmp, *x1, *x2, *ff2, *bias;
    __nv_bfloat16 *Xhi, *Xlo, *Hhi, *Hlo, *Whi, *Wlo;
    __nv_bfloat16 *QKVhi, *QKVlo, *KVhi, *KVlo, *CQhi, *CQlo;
    cudaGetSymbolAddress((void**)&tmp,  g_tmp);
    cudaGetSymbolAddress((void**)&x1,   g_x1);
    cudaGetSymbolAddress((void**)&x2,   g_x2);
    cudaGetSymbolAddress((void**)&ff2,  g_ff2);
    cudaGetSymbolAddress((void**)&bias, g_bias);
    cudaGetSymbolAddress((void**)&Xhi,  g_Xhi);
    cudaGetSymbolAddress((void**)&Xlo,  g_Xlo);
    cudaGetSymbolAddress((void**)&Hhi,  g_Hhi);
    cudaGetSymbolAddress((void**)&Hlo,  g_Hlo);
    cudaGetSymbolAddress((void**)&Whi,  g_Whi);
    cudaGetSymbolAddress((void**)&Wlo,  g_Wlo);
    cudaGetSymbolAddress((void**)&QKVhi, g_QKVhi);
    cudaGetSymbolAddress((void**)&QKVlo, g_QKVlo);
    cudaGetSymbolAddress((void**)&KVhi,  g_KVhi);
    cudaGetSymbolAddress((void**)&KVlo,  g_KVlo);
    cudaGetSymbolAddress((void**)&CQhi,  g_CQhi);
    cudaGetSymbolAddress((void**)&CQlo,  g_CQlo);

    cudaFuncSetAttribute(gemm_mma, cudaFuncAttributeMaxDynamicSharedMemorySize, G_SMEM);
    cudaFuncSetAttribute(attn_mma, cudaFuncAttributeMaxDynamicSharedMemorySize, AT_SMEM);

    const int CVT_B = 256 * 4;
    #define CVT(srcp, hip, lop, n) cvt_kernel<<<(n) / CVT_B, 256>>>(srcp, hip, lop, n)
    #define GEMM(ahi, alo, bhi, blo, bp, cf, ohi, olo, Nn, Kk, act) \
        gemm_mma<<<dim3((Nn) / 256, NTOK / 128), 256, G_SMEM>>>(ahi, alo, bhi, blo, bp, cf, ohi, olo, Nn, Kk, act)
    #define BF16_NULL (__nv_bfloat16*)nullptr

    // 0) bias; 1) all-weights convert; 2) src convert
    bias_kernel<<<TM, TA>>>(beats, bias);
    wcvt_kernel<<<W_TOTAL / CVT_B, 256>>>(sa_in_w, sa_out_w, ca_in_w, ca_out_w,
                                          lin1_w, lin2_w, Whi, Wlo);
    CVT(src, Xhi, Xlo, NTOK * D_MODEL);

    // 3) SA packed QKV (split-bf16 output)
    GEMM(Xhi, Xlo, Whi + W_SAIN, Wlo + W_SAIN, sa_in_b, (float*)nullptr,
         QKVhi, QKVlo, 3 * D_MODEL, D_MODEL, 0);

    // 4) SA attention -> X (split)
    attn_mma<<<dim3(TM / 64, BATCH * NHEAD), 128, AT_SMEM>>>(
        QKVhi, QKVlo, 3 * D_MODEL, 0,
        QKVhi, QKVlo, 3 * D_MODEL, D_MODEL,
        QKVhi, QKVlo, 3 * D_MODEL, 2 * D_MODEL,
        Xhi, Xlo, nullptr, 0.125f);

    // 5) SA out-proj  (<- ncu -s 5 profiles this launch)
    GEMM(Xhi, Xlo, Whi + W_SAOUT, Wlo + W_SAOUT, sa_out_b, tmp,
         BF16_NULL, BF16_NULL, D_MODEL, D_MODEL, 0);

    // 6) x1 = LN1(src + sa), fused split for CA-Q input
    add_ln_kernel<<<NTOK, 256>>>(src, tmp, nullptr, n1_g, n1_b, x1, Xhi, Xlo);

    // 7) CA Q-proj
    GEMM(Xhi, Xlo, Whi + W_CAIN, Wlo + W_CAIN, ca_in_b, (float*)nullptr,
         CQhi, CQlo, D_MODEL, D_MODEL, 0);

    // 8) audio convert; 9) CA KV-proj
    CVT(audio, Xhi, Xlo, NTOK * D_MODEL);
    GEMM(Xhi, Xlo, Whi + W_CAIN + (size_t)D_MODEL * D_MODEL, Wlo + W_CAIN + (size_t)D_MODEL * D_MODEL,
         ca_in_b + D_MODEL, (float*)nullptr, KVhi, KVlo, 2 * D_MODEL, D_MODEL, 0);

    // 10) CA attention (biased) -> X (split)
    attn_mma<<<dim3(TM / 64, BATCH * NHEAD), 128, AT_SMEM>>>(
        CQhi, CQlo, D_MODEL, 0,
        KVhi, KVlo, 2 * D_MODEL, 0,
        KVhi, KVlo, 2 * D_MODEL, D_MODEL,
        Xhi, Xlo, bias, 0.125f);

    // 11) CA out-proj
    GEMM(Xhi, Xlo, Whi + W_CAOUT, Wlo + W_CAOUT, ca_out_b, tmp,
         BF16_NULL, BF16_NULL, D_MODEL, D_MODEL, 0);

    // 12) x2 = LNc(x1 + tanh(gate)*cross), fused split for FFN1 input
    add_ln_kernel<<<NTOK, 256>>>(x1, tmp, gate, nc_g, nc_b, x2, Xhi, Xlo);

    // 13) FFN1 (GELU, split out); 14) FFN2
    GEMM(Xhi, Xlo, Whi + W_LIN1, Wlo + W_LIN1, lin1_b, (float*)nullptr, Hhi, Hlo,
         DFF, D_MODEL, 1);
    GEMM(Hhi, Hlo, Whi + W_LIN2, Wlo + W_LIN2, lin2_b, ff2,
         BF16_NULL, BF16_NULL, D_MODEL, DFF, 0);

    // 15) out = LN2(x2 + ff)
    add_ln_kernel<<<NTOK, 256>>>(x2, ff2, nullptr, n2_g, n2_b, out,
                                 BF16_NULL, BF16_NULL);
}

// round 7
// speedup vs baseline: 1.0843x; 1.0843x over previous
#include <cuda_runtime.h>
#include <cuda_bf16.h>
#include <math.h>
#include <stdint.h>

// ---------------- Problem constants ----------------
#define D_MODEL 1024
#define NHEAD   16
#define HDIM    64
#define DFF     4096
#define TM      512
#define TA      512
#define BATCH   32
#define NTOK    (TM * BATCH)   // 16384
#define NBEATS  64
#define LN_EPS  1e-5f

// ---------------- fp32 scratch ----------------
__device__ float g_tmp [NTOK * D_MODEL];
__device__ float g_x1  [NTOK * D_MODEL];
__device__ float g_x2  [NTOK * D_MODEL];
__device__ float g_ff2 [NTOK * D_MODEL];
__device__ float g_bias[TM * TA];

// ---------------- bf16 split scratch ----------------
__device__ __nv_bfloat16 g_Xhi [NTOK * D_MODEL];
__device__ __nv_bfloat16 g_Xlo [NTOK * D_MODEL];
__device__ __nv_bfloat16 g_Hhi [NTOK * DFF];
__device__ __nv_bfloat16 g_Hlo [NTOK * DFF];
__device__ __nv_bfloat16 g_QKVhi[NTOK * 3 * D_MODEL];
__device__ __nv_bfloat16 g_QKVlo[NTOK * 3 * D_MODEL];
__device__ __nv_bfloat16 g_KVhi[NTOK * 2 * D_MODEL];
__device__ __nv_bfloat16 g_KVlo[NTOK * 2 * D_MODEL];
__device__ __nv_bfloat16 g_CQhi[NTOK * D_MODEL];
__device__ __nv_bfloat16 g_CQlo[NTOK * D_MODEL];
__device__ __nv_bfloat16 g_Whi[16777216];
__device__ __nv_bfloat16 g_Wlo[16777216];

#define W_SAIN   0
#define W_SAOUT  3145728
#define W_CAIN   4194304
#define W_CAOUT  7340032
#define W_LIN1   8388608
#define W_LIN2  12582912
#define W_TOTAL 16777216

// ================= helpers (non-'a' PTX only) =================
__device__ __forceinline__ uint32_t smem_u32(const void* p) {
    uint32_t a;
    asm("{ .reg .u64 t; cvta.to.shared.u64 t, %1; cvt.u32.u64 %0, t; }" : "=r"(a) : "l"(p));
    return a;
}
__device__ __forceinline__ void cp_async16(uint32_t saddr, const void* g) {
    asm volatile("cp.async.cg.shared.global [%0], [%1], 16;" :: "r"(saddr), "l"(g));
}
__device__ __forceinline__ void cp_commit() {
    asm volatile("cp.async.commit_group;" ::: "memory");
}
__device__ __forceinline__ void ldsm_x4(uint32_t (&r)[4], uint32_t addr) {
    asm volatile("ldmatrix.sync.aligned.m8n8.x4.shared.b16 {%0,%1,%2,%3}, [%4];"
                 : "=r"(r[0]), "=r"(r[1]), "=r"(r[2]), "=r"(r[3]) : "r"(addr));
}
__device__ __forceinline__ void ldsm_x4_t(uint32_t (&r)[4], uint32_t addr) {
    asm volatile("ldmatrix.sync.aligned.m8n8.x4.trans.shared.b16 {%0,%1,%2,%3}, [%4];"
                 : "=r"(r[0]), "=r"(r[1]), "=r"(r[2]), "=r"(r[3]) : "r"(addr));
}
__device__ __forceinline__ void mma16816(float (&d)[4], const uint32_t (&a)[4],
                                         uint32_t b0, uint32_t b1) {
    asm volatile(
        "mma.sync.aligned.m16n8k16.row.col.f32.bf16.bf16.f32 "
        "{%0,%1,%2,%3}, {%4,%5,%6,%7}, {%8,%9}, {%0,%1,%2,%3};"
        : "+f"(d[0]), "+f"(d[1]), "+f"(d[2]), "+f"(d[3])
        : "r"(a[0]), "r"(a[1]), "r"(a[2]), "r"(a[3]), "r"(b0), "r"(b1));
}
__device__ __forceinline__ uint32_t pack_bf16x2(float x, float y) {
    return (uint32_t)__bfloat16_as_ushort(__float2bfloat16(x)) |
           ((uint32_t)__bfloat16_as_ushort(__float2bfloat16(y)) << 16);
}
__device__ __forceinline__ void split4(float4 v, uint2& uh, uint2& ul) {
    __nv_bfloat16 h0 = __float2bfloat16(v.x), h1 = __float2bfloat16(v.y);
    __nv_bfloat16 h2 = __float2bfloat16(v.z), h3 = __float2bfloat16(v.w);
    uh.x = (uint32_t)__bfloat16_as_ushort(h0) | ((uint32_t)__bfloat16_as_ushort(h1) << 16);
    uh.y = (uint32_t)__bfloat16_as_ushort(h2) | ((uint32_t)__bfloat16_as_ushort(h3) << 16);
    ul.x = pack_bf16x2(v.x - __bfloat162float(h0), v.y - __bfloat162float(h1));
    ul.y = pack_bf16x2(v.z - __bfloat162float(h2), v.w - __bfloat162float(h3));
}

// ================= converts =================
__global__ __launch_bounds__(256) void cvt_kernel(
    const float* __restrict__ src, __nv_bfloat16* __restrict__ hi,
    __nv_bfloat16* __restrict__ lo, int n)
{
    int i = (blockIdx.x * 256 + threadIdx.x) * 4;
    if (i >= n) return;
    uint2 uh, ul;
    split4(*(const float4*)(src + i), uh, ul);
    *(uint2*)(hi + i) = uh;
    *(uint2*)(lo + i) = ul;
}

__global__ __launch_bounds__(256) void wcvt_kernel(
    const float* __restrict__ w0, const float* __restrict__ w1,
    const float* __restrict__ w2, const float* __restrict__ w3,
    const float* __restrict__ w4, const float* __restrict__ w5,
    __nv_bfloat16* __restrict__ hi, __nv_bfloat16* __restrict__ lo)
{
    int i = (blockIdx.x * 256 + threadIdx.x) * 4;
    const float* src; int off;
    if      (i < W_SAOUT) { src = w0; off = W_SAIN; }
    else if (i < W_CAIN)  { src = w1; off = W_SAOUT; }
    else if (i < W_CAOUT) { src = w2; off = W_CAIN; }
    else if (i < W_LIN1)  { src = w3; off = W_CAOUT; }
    else if (i < W_LIN2)  { src = w4; off = W_LIN1; }
    else                  { src = w5; off = W_LIN2; }
    uint2 uh, ul;
    split4(*(const float4*)(src + (i - off)), uh, ul);
    *(uint2*)(hi + i) = uh;
    *(uint2*)(lo + i) = ul;
}

// ================= mma.sync GEMM =================
// C[M,N] = A[M,K]*B[N,K]^T + bias, 3-term split-bf16. CTA 128x128 (warp 32x64),
// BK=32, 4 stages. Term-major MMA issue to break RAW chains on accumulators.
#define G_STAGE 32768
#define G_SMEM  (4 * G_STAGE)

__global__ __launch_bounds__(256, 1) void gemm_mma(
    const __nv_bfloat16* __restrict__ Ahi, const __nv_bfloat16* __restrict__ Alo,
    const __nv_bfloat16* __restrict__ Bhi, const __nv_bfloat16* __restrict__ Blo,
    const float* __restrict__ bias, float* __restrict__ Cf,
    __nv_bfloat16* __restrict__ Ohi, __nv_bfloat16* __restrict__ Olo,
    int N, int K, int act)
{
    extern __shared__ __align__(128) char smem[];
    const uint32_t sbase = smem_u32(smem);
    const int tid = threadIdx.x;
    const int lane = tid & 31, wid = tid >> 5;
    const int warp_m = wid & 3, warp_n = wid >> 2;
    const int m0 = blockIdx.y * 128, n0 = blockIdx.x * 128;

    float acc[2][8][4];
    #pragma unroll
    for (int t = 0; t < 2; t++)
        #pragma unroll
        for (int j = 0; j < 8; j++)
            #pragma unroll
            for (int e = 0; e < 4; e++) acc[t][j][e] = 0.0f;

    int lr0 = tid >> 2,         lc0 = tid & 3;
    int lr1 = (tid + 256) >> 2, lc1 = tid & 3;
    uint32_t lsw0 = lr0 * 64 + ((lc0 ^ ((lr0 >> 1) & 3)) << 4);
    uint32_t lsw1 = lr1 * 64 + ((lc1 ^ ((lr1 >> 1) & 3)) << 4);

    auto stage_load = [&](int ci, int st) {
        const uint32_t sb = sbase + st * G_STAGE;
        const int kk = ci * 32;
        {
            size_t goA = (size_t)(m0 + lr0) * K + kk + lc0 * 8;
            size_t goB = (size_t)(n0 + lr0) * K + kk + lc0 * 8;
            cp_async16(sb + lsw0,         Ahi + goA);
            cp_async16(sb + 8192 + lsw0,  Alo + goA);
            cp_async16(sb + 16384 + lsw0, Bhi + goB);
            cp_async16(sb + 24576 + lsw0, Blo + goB);
        }
        {
            size_t goA = (size_t)(m0 + lr1) * K + kk + lc1 * 8;
            size_t goB = (size_t)(n0 + lr1) * K + kk + lc1 * 8;
            cp_async16(sb + lsw1,         Ahi + goA);
            cp_async16(sb + 8192 + lsw1,  Alo + goA);
            cp_async16(sb + 16384 + lsw1, Bhi + goB);
            cp_async16(sb + 24576 + lsw1, Blo + goB);
        }
        cp_commit();
    };

    const int lr = lane & 15;
    const int lseg = lane >> 4;
    int arow[2], brow[4];
    #pragma unroll
    for (int t = 0; t < 2; t++) arow[t] = warp_m * 32 + t * 16 + lr;
    #pragma unroll
    for (int u = 0; u < 4; u++) brow[u] = warp_n * 64 + u * 16 + lr;

    const int nch = K >> 5;
    stage_load(0, 0);
    stage_load(1, 1);
    stage_load(2, 2);

    for (int i = 0; i < nch; i++) {
        if (i <= nch - 3)      asm volatile("cp.async.wait_group 2;" ::: "memory");
        else if (i == nch - 2) asm volatile("cp.async.wait_group 1;" ::: "memory");
        else                   asm volatile("cp.async.wait_group 0;" ::: "memory");
        __syncthreads();
        if (i + 3 < nch) stage_load(i + 3, (i + 3) & 3);

        const uint32_t sb = sbase + (i & 3) * G_STAGE;
        #pragma unroll
        for (int s = 0; s < 2; s++) {
            const int chunk = 2 * s + lseg;
            uint32_t ah[2][4], al[2][4], bh[4][4], bl[4][4];
            #pragma unroll
            for (int t = 0; t < 2; t++) {
                uint32_t a = sb + arow[t] * 64 + ((chunk ^ ((arow[t] >> 1) & 3)) << 4);
                ldsm_x4(ah[t], a);
                ldsm_x4(al[t], a + 8192);
            }
            #pragma unroll
            for (int u = 0; u < 4; u++) {
                uint32_t a = sb + 16384 + brow[u] * 64 + ((chunk ^ ((brow[u] >> 1) & 3)) << 4);
                ldsm_x4(bh[u], a);
                ldsm_x4(bl[u], a + 8192);
            }
            // term-major: each acc reg written once per 16-mma block (no RAW chains)
            #pragma unroll
            for (int t = 0; t < 2; t++)
                #pragma unroll
                for (int u = 0; u < 4; u++) {
                    mma16816(acc[t][2 * u],     ah[t], bh[u][0], bh[u][2]);
                    mma16816(acc[t][2 * u + 1], ah[t], bh[u][1], bh[u][3]);
                }
            #pragma unroll
            for (int t = 0; t < 2; t++)
                #pragma unroll
                for (int u = 0; u < 4; u++) {
                    mma16816(acc[t][2 * u],     ah[t], bl[u][0], bl[u][2]);
                    mma16816(acc[t][2 * u + 1], ah[t], bl[u][1], bl[u][3]);
                }
            #pragma unroll
            for (int t = 0; t < 2; t++)
                #pragma unroll
                for (int u = 0; u < 4; u++) {
                    mma16816(acc[t][2 * u],     al[t], bh[u][0], bh[u][2]);
                    mma16816(acc[t][2 * u + 1], al[t], bh[u][1], bh[u][3]);
                }
        }
    }

    #pragma unroll
    for (int t = 0; t < 2; t++) {
        const int rbase = m0 + warp_m * 32 + t * 16 + (lane >> 2);
        #pragma unroll
        for (int j = 0; j < 8; j++) {
            const int col = n0 + warp_n * 64 + j * 8 + 2 * (lane & 3);
            const float b0 = __ldg(bias + col), b1 = __ldg(bias + col + 1);
            #pragma unroll
            for (int half = 0; half < 2; half++) {
                const int row = rbase + 8 * half;
                float v0 = acc[t][j][2 * half]     + b0;
                float v1 = acc[t][j][2 * half + 1] + b1;
                if (act) {
                    v0 = 0.5f * v0 * (1.0f + erff(v0 * 0.70710678118654752f));
                    v1 = 0.5f * v1 * (1.0f + erff(v1 * 0.70710678118654752f));
                }
                const size_t off = (size_t)row * N + col;
                if (Cf) {
                    *(float2*)(Cf + off) = make_float2(v0, v1);
                } else {
                    __nv_bfloat16 h0 = __float2bfloat16(v0);
                    __nv_bfloat16 h1 = __float2bfloat16(v1);
                    *(uint32_t*)(Ohi + off) =
                        (uint32_t)__bfloat16_as_ushort(h0) | ((uint32_t)__bfloat16_as_ushort(h1) << 16);
                    *(uint32_t*)(Olo + off) =
                        pack_bf16x2(v0 - __bfloat162float(h0), v1 - __bfloat162float(h1));
                }
            }
        }
    }
}

// ================= FA2-style attention on mma.sync =================
#define AT_BUF  32768
#define AT_SMEM (3 * AT_BUF)

__global__ __launch_bounds__(128) void attn_mma(
    const __nv_bfloat16* __restrict__ Qhi, const __nv_bfloat16* __restrict__ Qlo, int ldq, int qoff,
    const __nv_bfloat16* __restrict__ Khi, const __nv_bfloat16* __restrict__ Klo, int ldk, int koff,
    const __nv_bfloat16* __restrict__ Vhi, const __nv_bfloat16* __restrict__ Vlo, int ldv, int voff,
    __nv_bfloat16* __restrict__ Ohi, __nv_bfloat16* __restrict__ Olo,
    const float* __restrict__ bias, float scale)
{
    extern __shared__ __align__(128) char smem[];
    const uint32_t sbase = smem_u32(smem);
    const int tid = threadIdx.x, lane = tid & 31, w = tid >> 5;
    const int qt = blockIdx.x, bh = blockIdx.y;
    const int b = bh & (BATCH - 1), h = bh >> 5;

    #pragma unroll
    for (int it = 0; it < 4; it++) {
        int idx = tid + it * 128, r = idx >> 3, c = idx & 7;
        uint32_t sw = r * 128 + ((c ^ (r & 7)) << 4);
        size_t g = (size_t)((qt * 64 + r) * BATCH + b) * ldq + qoff + h * HDIM + c * 8;
        cp_async16(sbase + sw,        Qhi + g);
        cp_async16(sbase + 8192 + sw, Qlo + g);
    }
    cp_commit();
    asm volatile("cp.async.wait_group 0;" ::: "memory");
    __syncthreads();

    const int lr = lane & 15, ls = lane >> 4;
    uint32_t qh[4][4], ql[4][4];
    {
        int qrow = w * 16 + lr;
        #pragma unroll
        for (int kc = 0; kc < 4; kc++) {
            int chunk = 2 * kc + ls;
            uint32_t a = sbase + qrow * 128 + ((chunk ^ (qrow & 7)) << 4);
            ldsm_x4(qh[kc], a);
            ldsm_x4(ql[kc], a + 8192);
        }
    }
    __syncthreads();

    auto load_kt = [&](int kt, int st) {
        uint32_t sb = sbase + st * AT_BUF;
        #pragma unroll
        for (int it = 0; it < 4; it++) {
            int idx = tid + it * 128, r = idx >> 3, c = idx & 7;
            uint32_t sw = r * 128 + ((c ^ (r & 7)) << 4);
            size_t rowi = (size_t)((kt * 64 + r) * BATCH + b);
            size_t gk = rowi * ldk + koff + h * HDIM + c * 8;
            size_t gv = rowi * ldv + voff + h * HDIM + c * 8;
            cp_async16(sb + sw,         Khi + gk);
            cp_async16(sb + 8192 + sw,  Klo + gk);
            cp_async16(sb + 16384 + sw, Vhi + gv);
            cp_async16(sb + 24576 + sw, Vlo + gv);
        }
        cp_commit();
    };
    load_kt(0, 0);
    load_kt(1, 1);

    float o[8][4];
    #pragma unroll
    for (int t = 0; t < 8; t++)
        #pragma unroll
        for (int e = 0; e < 4; e++) o[t][e] = 0.0f;
    float mrow0 = -1e30f, mrow1 = -1e30f, lsum0 = 0.0f, lsum1 = 0.0f;

    const int vkbase = ((lane & 16) ? 8 : 0) + (lane & 7);
    const int vcsel  = (lane >> 3) & 1;

    for (int kt = 0; kt < 8; kt++) {
        if (kt < 7) asm volatile("cp.async.wait_group 1;" ::: "memory");
        else        asm volatile("cp.async.wait_group 0;" ::: "memory");
        __syncthreads();
        if (kt + 2 < 8) load_kt(kt + 2, (kt + 2) % 3);
        const uint32_t sb = sbase + (kt % 3) * AT_BUF;

        // ---- S = Q K^T, term-major
        float s[8][4];
        #pragma unroll
        for (int t = 0; t < 8; t++)
            #pragma unroll
            for (int e = 0; e < 4; e++) s[t][e] = 0.0f;
        #pragma unroll
        for (int kc = 0; kc < 4; kc++) {
            uint32_t kh[4][4], kl[4][4];
            #pragma unroll
            for (int u = 0; u < 4; u++) {
                int krow = u * 16 + lr, chunk = 2 * kc + ls;
                uint32_t a = sb + krow * 128 + ((chunk ^ (krow & 7)) << 4);
                ldsm_x4(kh[u], a);
                ldsm_x4(kl[u], a + 8192);
            }
            #pragma unroll
            for (int u = 0; u < 4; u++) {
                mma16816(s[2 * u],     qh[kc], kh[u][0], kh[u][2]);
                mma16816(s[2 * u + 1], qh[kc], kh[u][1], kh[u][3]);
            }
            #pragma unroll
            for (int u = 0; u < 4; u++) {
                mma16816(s[2 * u],     qh[kc], kl[u][0], kl[u][2]);
                mma16816(s[2 * u + 1], qh[kc], kl[u][1], kl[u][3]);
            }
            #pragma unroll
            for (int u = 0; u < 4; u++) {
                mma16816(s[2 * u],     ql[kc], kh[u][0], kh[u][2]);
                mma16816(s[2 * u + 1], ql[kc], kh[u][1], kh[u][3]);
            }
        }

        const int row0 = qt * 64 + w * 16 + (lane >> 2);
        if (bias) {
            #pragma unroll
            for (int t = 0; t < 8; t++) {
                int col = kt * 64 + t * 8 + 2 * (lane & 3);
                float2 b0 = *(const float2*)(bias + (size_t)row0 * TA + col);
                float2 b1 = *(const float2*)(bias + (size_t)(row0 + 8) * TA + col);
                s[t][0] = s[t][0] * scale + b0.x; s[t][1] = s[t][1] * scale + b0.y;
                s[t][2] = s[t][2] * scale + b1.x; s[t][3] = s[t][3] * scale + b1.y;
            }
        } else {
            #pragma unroll
            for (int t = 0; t < 8; t++)
                #pragma unroll
                for (int e = 0; e < 4; e++) s[t][e] *= scale;
        }

        float mx0 = -1e30f, mx1 = -1e30f;
        #pragma unroll
        for (int t = 0; t < 8; t++) {
            mx0 = fmaxf(mx0, fmaxf(s[t][0], s[t][1]));
            mx1 = fmaxf(mx1, fmaxf(s[t][2], s[t][3]));
        }
        mx0 = fmaxf(mx0, __shfl_xor_sync(0xffffffffu, mx0, 1));
        mx0 = fmaxf(mx0, __shfl_xor_sync(0xffffffffu, mx0, 2));
        mx1 = fmaxf(mx1, __shfl_xor_sync(0xffffffffu, mx1, 1));
        mx1 = fmaxf(mx1, __shfl_xor_sync(0xffffffffu, mx1, 2));
        float mn0 = fmaxf(mrow0, mx0), mn1 = fmaxf(mrow1, mx1);
        float a0 = __expf(mrow0 - mn0), a1 = __expf(mrow1 - mn1);
        mrow0 = mn0; mrow1 = mn1;

        float sum0 = 0.0f, sum1 = 0.0f;
        uint32_t phi[4][4], plo[4][4];
        #pragma unroll
        for (int t = 0; t < 8; t++) {
            float p0 = __expf(s[t][0] - mn0), p1 = __expf(s[t][1] - mn0);
            float p2 = __expf(s[t][2] - mn1), p3 = __expf(s[t][3] - mn1);
            sum0 += p0 + p1; sum1 += p2 + p3;
            __nv_bfloat16 h0 = __float2bfloat16(p0), h1 = __float2bfloat16(p1);
            __nv_bfloat16 h2 = __float2bfloat16(p2), h3 = __float2bfloat16(p3);
            const int kc = t >> 1, j = (t & 1) * 2;
            phi[kc][j]     = (uint32_t)__bfloat16_as_ushort(h0) | ((uint32_t)__bfloat16_as_ushort(h1) << 16);
            phi[kc][j + 1] = (uint32_t)__bfloat16_as_ushort(h2) | ((uint32_t)__bfloat16_as_ushort(h3) << 16);
            plo[kc][j]     = pack_bf16x2(p0 - __bfloat162float(h0), p1 - __bfloat162float(h1));
            plo[kc][j + 1] = pack_bf16x2(p2 - __bfloat162float(h2), p3 - __bfloat162float(h3));
        }
        sum0 += __shfl_xor_sync(0xffffffffu, sum0, 1);
        sum0 += __shfl_xor_sync(0xffffffffu, sum0, 2);
        sum1 += __shfl_xor_sync(0xffffffffu, sum1, 1);
        sum1 += __shfl_xor_sync(0xffffffffu, sum1, 2);
        lsum0 = lsum0 * a0 + sum0;
        lsum1 = lsum1 * a1 + sum1;
        #pragma unroll
        for (int t = 0; t < 8; t++) {
            o[t][0] *= a0; o[t][1] *= a0;
            o[t][2] *= a1; o[t][3] *= a1;
        }

        // ---- O += P V, term-major per kc
        #pragma unroll
        for (int kc = 0; kc < 4; kc++) {
            int vkey = kc * 16 + vkbase;
            uint32_t vh[4][4], vl[4][4];
            #pragma unroll
            for (int du = 0; du < 4; du++) {
                int chunk = 2 * du + vcsel;
                uint32_t a = sb + 16384 + vkey * 128 + ((chunk ^ (vkey & 7)) << 4);
                ldsm_x4_t(vh[du], a);
                ldsm_x4_t(vl[du], a + 8192);
            }
            #pragma unroll
            for (int du = 0; du < 4; du++) {
                mma16816(o[2 * du],     phi[kc], vh[du][0], vh[du][2]);
                mma16816(o[2 * du + 1], phi[kc], vh[du][1], vh[du][3]);
            }
            #pragma unroll
            for (int du = 0; du < 4; du++) {
                mma16816(o[2 * du],     phi[kc], vl[du][0], vl[du][2]);
                mma16816(o[2 * du + 1], phi[kc], vl[du][1], vl[du][3]);
            }
            #pragma unroll
            for (int du = 0; du < 4; du++) {
                mma16816(o[2 * du],     plo[kc], vh[du][0], vh[du][2]);
                mma16816(o[2 * du + 1], plo[kc], vh[du][1], vh[du][3]);
            }
        }
    }

    float inv0 = 1.0f / lsum0, inv1 = 1.0f / lsum1;
    const int row0 = qt * 64 + w * 16 + (lane >> 2);
    #pragma unroll
    for (int t = 0; t < 8; t++) {
        int col = t * 8 + 2 * (lane & 3);
        float v0 = o[t][0] * inv0, v1 = o[t][1] * inv0;
        float v2 = o[t][2] * inv1, v3 = o[t][3] * inv1;
        size_t off0 = (size_t)(row0 * BATCH + b) * D_MODEL + h * HDIM + col;
        size_t off1 = (size_t)((row0 + 8) * BATCH + b) * D_MODEL + h * HDIM + col;
        __nv_bfloat16 h0 = __float2bfloat16(v0), h1 = __float2bfloat16(v1);
        __nv_bfloat16 h2 = __float2bfloat16(v2), h3 = __float2bfloat16(v3);
        *(uint32_t*)(Ohi + off0) = (uint32_t)__bfloat16_as_ushort(h0) | ((uint32_t)__bfloat16_as_ushort(h1) << 16);
        *(uint32_t*)(Olo + off0) = pack_bf16x2(v0 - __bfloat162float(h0), v1 - __bfloat162float(h1));
        *(uint32_t*)(Ohi + off1) = (uint32_t)__bfloat16_as_ushort(h2) | ((uint32_t)__bfloat16_as_ushort(h3) << 16);
        *(uint32_t*)(Olo + off1) = pack_bf16x2(v2 - __bfloat162float(h2), v3 - __bfloat162float(h3));
    }
}

// ---------------- Bias precompute ----------------
__global__ void bias_kernel(const int* __restrict__ beats, float* __restrict__ out) {
    __shared__ int sb[NBEATS];
    int i = blockIdx.x;
    int j = threadIdx.x;
    if (threadIdx.x < NBEATS) sb[threadIdx.x] = beats[threadIdx.x];
    __syncthreads();
    float bb = 0.0f;
    #pragma unroll 8
    for (int n = 0; n < NBEATS; n++) {
        int bf = sb[n];
        if (j == bf) bb = fmaxf(bb, 2.0f);
        if (bf > 0      && j == bf - 1) bb = fmaxf(bb, 1.0f);
        if (bf < TA - 1 && j == bf + 1) bb = fmaxf(bb, 1.0f);
    }
    float scale = (float)(TA - 1) / (float)(TM - 1);
    float d = (float)i * scale - (float)j;
    out[i * TA + j] = -(d * d) * (1.0f / 32.0f) + bb;
}

// ---------------- Fused residual + LayerNorm (+ optional bf16 split out) ----------------
__global__ __launch_bounds__(256) void add_ln_kernel(
    const float* __restrict__ A, const float* __restrict__ Bv,
    const float* __restrict__ gatePtr,
    const float* __restrict__ gamma, const float* __restrict__ beta,
    float* __restrict__ out,
    __nv_bfloat16* __restrict__ ohi, __nv_bfloat16* __restrict__ olo)
{
    int t = blockIdx.x;
    int tid = threadIdx.x;
    float gscale = gatePtr ? tanhf(*gatePtr) : 1.0f;
    const float4* a4 = (const float4*)(A  + (size_t)t * D_MODEL);
    const float4* b4 = (const float4*)(Bv + (size_t)t * D_MODEL);
    float4 av = a4[tid], bv = b4[tid];
    float x0 = av.x + gscale * bv.x;
    float x1 = av.y + gscale * bv.y;
    float x2 = av.z + gscale * bv.z;
    float x3 = av.w + gscale * bv.w;
    float s  = x0 + x1 + x2 + x3;
    float ss = x0 * x0 + x1 * x1 + x2 * x2 + x3 * x3;

    __shared__ float rs[8], rss[8];
    #pragma unroll
    for (int o = 16; o > 0; o >>= 1) {
        s  += __shfl_xor_sync(0xffffffffu, s,  o);
        ss += __shfl_xor_sync(0xffffffffu, ss, o);
    }
    if ((tid & 31) == 0) { rs[tid >> 5] = s; rss[tid >> 5] = ss; }
    __syncthreads();
    float stot = 0.0f, sstot = 0.0f;
    #pragma unroll
    for (int i = 0; i < 8; i++) { stot += rs[i]; sstot += rss[i]; }
    float mean = stot * (1.0f / D_MODEL);
    float var  = sstot * (1.0f / D_MODEL) - mean * mean;
    float rstd = rsqrtf(var + LN_EPS);

    const float4* g4 = (const float4*)gamma;
    const float4* be4 = (const float4*)beta;
    float4 g = g4[tid], be = be4[tid];
    float4 o;
    o.x = (x0 - mean) * rstd * g.x + be.x;
    o.y = (x1 - mean) * rstd * g.y + be.y;
    o.z = (x2 - mean) * rstd * g.z + be.z;
    o.w = (x3 - mean) * rstd * g.w + be.w;
    ((float4*)(out + (size_t)t * D_MODEL))[tid] = o;
    if (ohi) {
        uint2 uh, ul;
        split4(o, uh, ul);
        ((uint2*)(ohi + (size_t)t * D_MODEL))[tid] = uh;
        ((uint2*)(olo + (size_t)t * D_MODEL))[tid] = ul;
    }
}

// ---------------- Launch ----------------
extern "C" void kernel_launch(void* const* d_in, const int* in_sizes, int n_in,
                              void* d_out, int out_size) {
    const float* src      = (const float*)d_in[0];
    const float* audio    = (const float*)d_in[1];
    const int*   beats    = (const int*)  d_in[2];
    const float* sa_in_w  = (const float*)d_in[3];
    const float* sa_in_b  = (const float*)d_in[4];
    const float* sa_out_w = (const float*)d_in[5];
    const float* sa_out_b = (const float*)d_in[6];
    const float* ca_in_w  = (const float*)d_in[7];
    const float* ca_in_b  = (const float*)d_in[8];
    const float* ca_out_w = (const float*)d_in[9];
    const float* ca_out_b = (const float*)d_in[10];
    const float* gate     = (const float*)d_in[11];
    const float* n1_g     = (const float*)d_in[12];
    const float* n1_b     = (const float*)d_in[13];
    const float* nc_g     = (const float*)d_in[14];
    const float* nc_b     = (const float*)d_in[15];
    const float* n2_g     = (const float*)d_in[16];
    const float* n2_b     = (const float*)d_in[17];
    const float* lin1_w   = (const float*)d_in[18];
    const float* lin1_b   = (const float*)d_in[19];
    const float* lin2_w   = (const float*)d_in[20];
    const float* lin2_b   = (const float*)d_in[21];
    float* out = (float*)d_out;

    float *tmp, *x1, *x2, *ff2, *bias;
    __nv_bfloat16 *Xhi, *Xlo, *Hhi, *Hlo, *Whi, *Wlo;
    __nv_bfloat16 *QKVhi, *QKVlo, *KVhi, *KVlo, *CQhi, *CQlo;
    cudaGetSymbolAddress((void**)&tmp,  g_tmp);
    cudaGetSymbolAddress((void**)&x1,   g_x1);
    cudaGetSymbolAddress((void**)&x2,   g_x2);
    cudaGetSymbolAddress((void**)&ff2,  g_ff2);
    cudaGetSymbolAddress((void**)&bias, g_bias);
    cudaGetSymbolAddress((void**)&Xhi,  g_Xhi);
    cudaGetSymbolAddress((void**)&Xlo,  g_Xlo);
    cudaGetSymbolAddress((void**)&Hhi,  g_Hhi);
    cudaGetSymbolAddress((void**)&Hlo,  g_Hlo);
    cudaGetSymbolAddress((void**)&Whi,  g_Whi);
    cudaGetSymbolAddress((void**)&Wlo,  g_Wlo);
    cudaGetSymbolAddress((void**)&QKVhi, g_QKVhi);
    cudaGetSymbolAddress((void**)&QKVlo, g_QKVlo);
    cudaGetSymbolAddress((void**)&KVhi,  g_KVhi);
    cudaGetSymbolAddress((void**)&KVlo,  g_KVlo);
    cudaGetSymbolAddress((void**)&CQhi,  g_CQhi);
    cudaGetSymbolAddress((void**)&CQlo,  g_CQlo);

    cudaFuncSetAttribute(gemm_mma, cudaFuncAttributeMaxDynamicSharedMemorySize, G_SMEM);
    cudaFuncSetAttribute(attn_mma, cudaFuncAttributeMaxDynamicSharedMemorySize, AT_SMEM);

    const int CVT_B = 256 * 4;
    #define CVT(srcp, hip, lop, n) cvt_kernel<<<(n) / CVT_B, 256>>>(srcp, hip, lop, n)
    #define GEMM(ahi, alo, bhi, blo, bp, cf, ohi, olo, Nn, Kk, act) \
        gemm_mma<<<dim3((Nn) / 128, NTOK / 128), 256, G_SMEM>>>(ahi, alo, bhi, blo, bp, cf, ohi, olo, Nn, Kk, act)
    #define BF16_NULL (__nv_bfloat16*)nullptr

    bias_kernel<<<TM, TA>>>(beats, bias);
    wcvt_kernel<<<W_TOTAL / CVT_B, 256>>>(sa_in_w, sa_out_w, ca_in_w, ca_out_w,
                                          lin1_w, lin2_w, Whi, Wlo);
    CVT(src, Xhi, Xlo, NTOK * D_MODEL);

    // 3) SA packed QKV (split-bf16 output)
    GEMM(Xhi, Xlo, Whi + W_SAIN, Wlo + W_SAIN, sa_in_b, (float*)nullptr,
         QKVhi, QKVlo, 3 * D_MODEL, D_MODEL, 0);

    // 4) SA attention
    attn_mma<<<dim3(TM / 64, BATCH * NHEAD), 128, AT_SMEM>>>(
        QKVhi, QKVlo, 3 * D_MODEL, 0,
        QKVhi, QKVlo, 3 * D_MODEL, D_MODEL,
        QKVhi, QKVlo, 3 * D_MODEL, 2 * D_MODEL,
        Xhi, Xlo, nullptr, 0.125f);

    // 5) SA out-proj  (ncu -s 5 lands here)
    GEMM(Xhi, Xlo, Whi + W_SAOUT, Wlo + W_SAOUT, sa_out_b, tmp,
         BF16_NULL, BF16_NULL, D_MODEL, D_MODEL, 0);

    // 6) x1 = LN1(src + sa), fused split
    add_ln_kernel<<<NTOK, 256>>>(src, tmp, nullptr, n1_g, n1_b, x1, Xhi, Xlo);

    // 7) CA Q-proj
    GEMM(Xhi, Xlo, Whi + W_CAIN, Wlo + W_CAIN, ca_in_b, (float*)nullptr,
         CQhi, CQlo, D_MODEL, D_MODEL, 0);

    // 8-9) audio convert + CA KV-proj
    CVT(audio, Xhi, Xlo, NTOK * D_MODEL);
    GEMM(Xhi, Xlo, Whi + W_CAIN + (size_t)D_MODEL * D_MODEL, Wlo + W_CAIN + (size_t)D_MODEL * D_MODEL,
         ca_in_b + D_MODEL, (float*)nullptr, KVhi, KVlo, 2 * D_MODEL, D_MODEL, 0);

    // 10) CA attention (biased)
    attn_mma<<<dim3(TM / 64, BATCH * NHEAD), 128, AT_SMEM>>>(
        CQhi, CQlo, D_MODEL, 0,
        KVhi, KVlo, 2 * D_MODEL, 0,
        KVhi, KVlo, 2 * D_MODEL, D_MODEL,
        Xhi, Xlo, bias, 0.125f);

    // 11) CA out-proj
    GEMM(Xhi, Xlo, Whi + W_CAOUT, Wlo + W_CAOUT, ca_out_b, tmp,
         BF16_NULL, BF16_NULL, D_MODEL, D_MODEL, 0);

    // 12) x2 = LNc(x1 + tanh(gate)*cross), fused split
    add_ln_kernel<<<NTOK, 256>>>(x1, tmp, gate, nc_g, nc_b, x2, Xhi, Xlo);

    // 13-14) FFN
    GEMM(Xhi, Xlo, Whi + W_LIN1, Wlo + W_LIN1, lin1_b, (float*)nullptr, Hhi, Hlo,
         DFF, D_MODEL, 1);
    GEMM(Hhi, Hlo, Whi + W_LIN2, Wlo + W_LIN2, lin2_b, ff2,
         BF16_NULL, BF16_NULL, D_MODEL, DFF, 0);

    // 15) out = LN2(x2 + ff)
    add_ln_kernel<<<NTOK, 256>>>(x2, ff2, nullptr, n2_g, n2_b, out,
                                 BF16_NULL, BF16_NULL);
}

// round 8
// speedup vs baseline: 1.2257x; 1.1304x over previous
#include <cuda_runtime.h>
#include <cuda_bf16.h>
#include <math.h>
#include <stdint.h>

// ---------------- Problem constants ----------------
#define D_MODEL 1024
#define NHEAD   16
#define HDIM    64
#define DFF     4096
#define TM      512
#define TA      512
#define BATCH   32
#define NTOK    (TM * BATCH)   // 16384
#define NBEATS  64
#define LN_EPS  1e-5f

// ---------------- fp32 scratch ----------------
__device__ float g_tmp [NTOK * D_MODEL];
__device__ float g_x1  [NTOK * D_MODEL];
__device__ float g_x2  [NTOK * D_MODEL];
__device__ float g_ff2 [NTOK * D_MODEL];
__device__ float g_bias[TM * TA];

// ---------------- bf16 split scratch ----------------
__device__ __nv_bfloat16 g_Xhi [NTOK * D_MODEL];
__device__ __nv_bfloat16 g_Xlo [NTOK * D_MODEL];
__device__ __nv_bfloat16 g_Hhi [NTOK * DFF];
__device__ __nv_bfloat16 g_Hlo [NTOK * DFF];
__device__ __nv_bfloat16 g_QKVhi[NTOK * 3 * D_MODEL];
__device__ __nv_bfloat16 g_QKVlo[NTOK * 3 * D_MODEL];
__device__ __nv_bfloat16 g_KVhi[NTOK * 2 * D_MODEL];
__device__ __nv_bfloat16 g_KVlo[NTOK * 2 * D_MODEL];
__device__ __nv_bfloat16 g_CQhi[NTOK * D_MODEL];
__device__ __nv_bfloat16 g_CQlo[NTOK * D_MODEL];
__device__ __nv_bfloat16 g_Whi[16777216];
__device__ __nv_bfloat16 g_Wlo[16777216];

#define W_SAIN   0
#define W_SAOUT  3145728
#define W_CAIN   4194304
#define W_CAOUT  7340032
#define W_LIN1   8388608
#define W_LIN2  12582912
#define W_TOTAL 16777216

// ================= helpers (non-'a' PTX only) =================
__device__ __forceinline__ uint32_t smem_u32(const void* p) {
    uint32_t a;
    asm("{ .reg .u64 t; cvta.to.shared.u64 t, %1; cvt.u32.u64 %0, t; }" : "=r"(a) : "l"(p));
    return a;
}
__device__ __forceinline__ void cp_async16(uint32_t saddr, const void* g) {
    asm volatile("cp.async.cg.shared.global [%0], [%1], 16;" :: "r"(saddr), "l"(g));
}
__device__ __forceinline__ void cp_commit() {
    asm volatile("cp.async.commit_group;" ::: "memory");
}
__device__ __forceinline__ void ldsm_x4(uint32_t (&r)[4], uint32_t addr) {
    asm volatile("ldmatrix.sync.aligned.m8n8.x4.shared.b16 {%0,%1,%2,%3}, [%4];"
                 : "=r"(r[0]), "=r"(r[1]), "=r"(r[2]), "=r"(r[3]) : "r"(addr));
}
__device__ __forceinline__ void ldsm_x4_t(uint32_t (&r)[4], uint32_t addr) {
    asm volatile("ldmatrix.sync.aligned.m8n8.x4.trans.shared.b16 {%0,%1,%2,%3}, [%4];"
                 : "=r"(r[0]), "=r"(r[1]), "=r"(r[2]), "=r"(r[3]) : "r"(addr));
}
__device__ __forceinline__ void mma16816(float (&d)[4], const uint32_t (&a)[4],
                                         uint32_t b0, uint32_t b1) {
    asm volatile(
        "mma.sync.aligned.m16n8k16.row.col.f32.bf16.bf16.f32 "
        "{%0,%1,%2,%3}, {%4,%5,%6,%7}, {%8,%9}, {%0,%1,%2,%3};"
        : "+f"(d[0]), "+f"(d[1]), "+f"(d[2]), "+f"(d[3])
        : "r"(a[0]), "r"(a[1]), "r"(a[2]), "r"(a[3]), "r"(b0), "r"(b1));
}
__device__ __forceinline__ uint32_t pack_bf16x2(float x, float y) {
    return (uint32_t)__bfloat16_as_ushort(__float2bfloat16(x)) |
           ((uint32_t)__bfloat16_as_ushort(__float2bfloat16(y)) << 16);
}
__device__ __forceinline__ void split4(float4 v, uint2& uh, uint2& ul) {
    __nv_bfloat16 h0 = __float2bfloat16(v.x), h1 = __float2bfloat16(v.y);
    __nv_bfloat16 h2 = __float2bfloat16(v.z), h3 = __float2bfloat16(v.w);
    uh.x = (uint32_t)__bfloat16_as_ushort(h0) | ((uint32_t)__bfloat16_as_ushort(h1) << 16);
    uh.y = (uint32_t)__bfloat16_as_ushort(h2) | ((uint32_t)__bfloat16_as_ushort(h3) << 16);
    ul.x = pack_bf16x2(v.x - __bfloat162float(h0), v.y - __bfloat162float(h1));
    ul.y = pack_bf16x2(v.z - __bfloat162float(h2), v.w - __bfloat162float(h3));
}

// ================= converts =================
__global__ __launch_bounds__(256) void cvt_kernel(
    const float* __restrict__ src, __nv_bfloat16* __restrict__ hi,
    __nv_bfloat16* __restrict__ lo, int n)
{
    int i = (blockIdx.x * 256 + threadIdx.x) * 4;
    if (i >= n) return;
    uint2 uh, ul;
    split4(*(const float4*)(src + i), uh, ul);
    *(uint2*)(hi + i) = uh;
    *(uint2*)(lo + i) = ul;
}

__global__ __launch_bounds__(256) void wcvt_kernel(
    const float* __restrict__ w0, const float* __restrict__ w1,
    const float* __restrict__ w2, const float* __restrict__ w3,
    const float* __restrict__ w4, const float* __restrict__ w5,
    __nv_bfloat16* __restrict__ hi, __nv_bfloat16* __restrict__ lo)
{
    int i = (blockIdx.x * 256 + threadIdx.x) * 4;
    const float* src; int off;
    if      (i < W_SAOUT) { src = w0; off = W_SAIN; }
    else if (i < W_CAIN)  { src = w1; off = W_SAOUT; }
    else if (i < W_CAOUT) { src = w2; off = W_CAIN; }
    else if (i < W_LIN1)  { src = w3; off = W_CAOUT; }
    else if (i < W_LIN2)  { src = w4; off = W_LIN1; }
    else                  { src = w5; off = W_LIN2; }
    uint2 uh, ul;
    split4(*(const float4*)(src + (i - off)), uh, ul);
    *(uint2*)(hi + i) = uh;
    *(uint2*)(lo + i) = ul;
}

// ================= mma.sync GEMM =================
// C[M,N] = A[M,K]*B[N,K]^T + bias, 3-term split-bf16. CTA 128x128 (warp 32x64),
// BK=32, 3 stages (96KB) + __launch_bounds__(256,2) -> 2 CTAs/SM for bubble fill.
// Inner loop holds B frags for 2 of 4 u-tiles at a time to fit 128 regs.
#define G_STAGE 32768
#define G_SMEM  (3 * G_STAGE)

__global__ __launch_bounds__(256, 2) void gemm_mma(
    const __nv_bfloat16* __restrict__ Ahi, const __nv_bfloat16* __restrict__ Alo,
    const __nv_bfloat16* __restrict__ Bhi, const __nv_bfloat16* __restrict__ Blo,
    const float* __restrict__ bias, float* __restrict__ Cf,
    __nv_bfloat16* __restrict__ Ohi, __nv_bfloat16* __restrict__ Olo,
    int N, int K, int act)
{
    extern __shared__ __align__(128) char smem[];
    const uint32_t sbase = smem_u32(smem);
    const int tid = threadIdx.x;
    const int lane = tid & 31, wid = tid >> 5;
    const int warp_m = wid & 3, warp_n = wid >> 2;
    const int m0 = blockIdx.y * 128, n0 = blockIdx.x * 128;

    float acc[2][8][4];
    #pragma unroll
    for (int t = 0; t < 2; t++)
        #pragma unroll
        for (int j = 0; j < 8; j++)
            #pragma unroll
            for (int e = 0; e < 4; e++) acc[t][j][e] = 0.0f;

    int lr0 = tid >> 2,         lc0 = tid & 3;
    int lr1 = (tid + 256) >> 2, lc1 = tid & 3;
    uint32_t lsw0 = lr0 * 64 + ((lc0 ^ ((lr0 >> 1) & 3)) << 4);
    uint32_t lsw1 = lr1 * 64 + ((lc1 ^ ((lr1 >> 1) & 3)) << 4);

    auto stage_load = [&](int ci, int st) {
        const uint32_t sb = sbase + st * G_STAGE;
        const int kk = ci * 32;
        {
            size_t goA = (size_t)(m0 + lr0) * K + kk + lc0 * 8;
            size_t goB = (size_t)(n0 + lr0) * K + kk + lc0 * 8;
            cp_async16(sb + lsw0,         Ahi + goA);
            cp_async16(sb + 8192 + lsw0,  Alo + goA);
            cp_async16(sb + 16384 + lsw0, Bhi + goB);
            cp_async16(sb + 24576 + lsw0, Blo + goB);
        }
        {
            size_t goA = (size_t)(m0 + lr1) * K + kk + lc1 * 8;
            size_t goB = (size_t)(n0 + lr1) * K + kk + lc1 * 8;
            cp_async16(sb + lsw1,         Ahi + goA);
            cp_async16(sb + 8192 + lsw1,  Alo + goA);
            cp_async16(sb + 16384 + lsw1, Bhi + goB);
            cp_async16(sb + 24576 + lsw1, Blo + goB);
        }
        cp_commit();
    };

    const int lr = lane & 15;
    const int lseg = lane >> 4;
    int arow[2], brow[4];
    #pragma unroll
    for (int t = 0; t < 2; t++) arow[t] = warp_m * 32 + t * 16 + lr;
    #pragma unroll
    for (int u = 0; u < 4; u++) brow[u] = warp_n * 64 + u * 16 + lr;

    const int nch = K >> 5;
    stage_load(0, 0);
    stage_load(1, 1);

    for (int i = 0; i < nch; i++) {
        if (i < nch - 1) asm volatile("cp.async.wait_group 1;" ::: "memory");
        else             asm volatile("cp.async.wait_group 0;" ::: "memory");
        __syncthreads();
        if (i + 2 < nch) stage_load(i + 2, (i + 2) % 3);  // stage consumed at i-1

        const uint32_t sb = sbase + (i % 3) * G_STAGE;
        #pragma unroll
        for (int s = 0; s < 2; s++) {
            const int chunk = 2 * s + lseg;
            uint32_t ah[2][4], al[2][4];
            #pragma unroll
            for (int t = 0; t < 2; t++) {
                uint32_t a = sb + arow[t] * 64 + ((chunk ^ ((arow[t] >> 1) & 3)) << 4);
                ldsm_x4(ah[t], a);
                ldsm_x4(al[t], a + 8192);
            }
            // process u-tiles two at a time to bound live registers (~116)
            #pragma unroll
            for (int half = 0; half < 2; half++) {
                uint32_t bh[2][4], bl[2][4];
                #pragma unroll
                for (int uu = 0; uu < 2; uu++) {
                    int u = 2 * half + uu;
                    uint32_t a = sb + 16384 + brow[u] * 64 + ((chunk ^ ((brow[u] >> 1) & 3)) << 4);
                    ldsm_x4(bh[uu], a);
                    ldsm_x4(bl[uu], a + 8192);
                }
                #pragma unroll
                for (int t = 0; t < 2; t++)
                    #pragma unroll
                    for (int uu = 0; uu < 2; uu++) {
                        int j = 2 * (2 * half + uu);
                        mma16816(acc[t][j],     ah[t], bh[uu][0], bh[uu][2]);
                        mma16816(acc[t][j + 1], ah[t], bh[uu][1], bh[uu][3]);
                    }
                #pragma unroll
                for (int t = 0; t < 2; t++)
                    #pragma unroll
                    for (int uu = 0; uu < 2; uu++) {
                        int j = 2 * (2 * half + uu);
                        mma16816(acc[t][j],     ah[t], bl[uu][0], bl[uu][2]);
                        mma16816(acc[t][j + 1], ah[t], bl[uu][1], bl[uu][3]);
                    }
                #pragma unroll
                for (int t = 0; t < 2; t++)
                    #pragma unroll
                    for (int uu = 0; uu < 2; uu++) {
                        int j = 2 * (2 * half + uu);
                        mma16816(acc[t][j],     al[t], bh[uu][0], bh[uu][2]);
                        mma16816(acc[t][j + 1], al[t], bh[uu][1], bh[uu][3]);
                    }
            }
        }
    }

    #pragma unroll
    for (int t = 0; t < 2; t++) {
        const int rbase = m0 + warp_m * 32 + t * 16 + (lane >> 2);
        #pragma unroll
        for (int j = 0; j < 8; j++) {
            const int col = n0 + warp_n * 64 + j * 8 + 2 * (lane & 3);
            const float b0 = __ldg(bias + col), b1 = __ldg(bias + col + 1);
            #pragma unroll
            for (int half = 0; half < 2; half++) {
                const int row = rbase + 8 * half;
                float v0 = acc[t][j][2 * half]     + b0;
                float v1 = acc[t][j][2 * half + 1] + b1;
                if (act) {
                    v0 = 0.5f * v0 * (1.0f + erff(v0 * 0.70710678118654752f));
                    v1 = 0.5f * v1 * (1.0f + erff(v1 * 0.70710678118654752f));
                }
                const size_t off = (size_t)row * N + col;
                if (Cf) {
                    *(float2*)(Cf + off) = make_float2(v0, v1);
                } else {
                    __nv_bfloat16 h0 = __float2bfloat16(v0);
                    __nv_bfloat16 h1 = __float2bfloat16(v1);
                    *(uint32_t*)(Ohi + off) =
                        (uint32_t)__bfloat16_as_ushort(h0) | ((uint32_t)__bfloat16_as_ushort(h1) << 16);
                    *(uint32_t*)(Olo + off) =
                        pack_bf16x2(v0 - __bfloat162float(h0), v1 - __bfloat162float(h1));
                }
            }
        }
    }
}

// ================= FA2-style attention on mma.sync =================
#define AT_BUF  32768
#define AT_SMEM (3 * AT_BUF)

__global__ __launch_bounds__(128) void attn_mma(
    const __nv_bfloat16* __restrict__ Qhi, const __nv_bfloat16* __restrict__ Qlo, int ldq, int qoff,
    const __nv_bfloat16* __restrict__ Khi, const __nv_bfloat16* __restrict__ Klo, int ldk, int koff,
    const __nv_bfloat16* __restrict__ Vhi, const __nv_bfloat16* __restrict__ Vlo, int ldv, int voff,
    __nv_bfloat16* __restrict__ Ohi, __nv_bfloat16* __restrict__ Olo,
    const float* __restrict__ bias, float scale)
{
    extern __shared__ __align__(128) char smem[];
    const uint32_t sbase = smem_u32(smem);
    const int tid = threadIdx.x, lane = tid & 31, w = tid >> 5;
    const int qt = blockIdx.x, bh = blockIdx.y;
    const int b = bh & (BATCH - 1), h = bh >> 5;

    #pragma unroll
    for (int it = 0; it < 4; it++) {
        int idx = tid + it * 128, r = idx >> 3, c = idx & 7;
        uint32_t sw = r * 128 + ((c ^ (r & 7)) << 4);
        size_t g = (size_t)((qt * 64 + r) * BATCH + b) * ldq + qoff + h * HDIM + c * 8;
        cp_async16(sbase + sw,        Qhi + g);
        cp_async16(sbase + 8192 + sw, Qlo + g);
    }
    cp_commit();
    asm volatile("cp.async.wait_group 0;" ::: "memory");
    __syncthreads();

    const int lr = lane & 15, ls = lane >> 4;
    uint32_t qh[4][4], ql[4][4];
    {
        int qrow = w * 16 + lr;
        #pragma unroll
        for (int kc = 0; kc < 4; kc++) {
            int chunk = 2 * kc + ls;
            uint32_t a = sbase + qrow * 128 + ((chunk ^ (qrow & 7)) << 4);
            ldsm_x4(qh[kc], a);
            ldsm_x4(ql[kc], a + 8192);
        }
    }
    __syncthreads();

    auto load_kt = [&](int kt, int st) {
        uint32_t sb = sbase + st * AT_BUF;
        #pragma unroll
        for (int it = 0; it < 4; it++) {
            int idx = tid + it * 128, r = idx >> 3, c = idx & 7;
            uint32_t sw = r * 128 + ((c ^ (r & 7)) << 4);
            size_t rowi = (size_t)((kt * 64 + r) * BATCH + b);
            size_t gk = rowi * ldk + koff + h * HDIM + c * 8;
            size_t gv = rowi * ldv + voff + h * HDIM + c * 8;
            cp_async16(sb + sw,         Khi + gk);
            cp_async16(sb + 8192 + sw,  Klo + gk);
            cp_async16(sb + 16384 + sw, Vhi + gv);
            cp_async16(sb + 24576 + sw, Vlo + gv);
        }
        cp_commit();
    };
    load_kt(0, 0);
    load_kt(1, 1);

    float o[8][4];
    #pragma unroll
    for (int t = 0; t < 8; t++)
        #pragma unroll
        for (int e = 0; e < 4; e++) o[t][e] = 0.0f;
    float mrow0 = -1e30f, mrow1 = -1e30f, lsum0 = 0.0f, lsum1 = 0.0f;

    const int vkbase = ((lane & 16) ? 8 : 0) + (lane & 7);
    const int vcsel  = (lane >> 3) & 1;

    for (int kt = 0; kt < 8; kt++) {
        if (kt < 7) asm volatile("cp.async.wait_group 1;" ::: "memory");
        else        asm volatile("cp.async.wait_group 0;" ::: "memory");
        __syncthreads();
        if (kt + 2 < 8) load_kt(kt + 2, (kt + 2) % 3);
        const uint32_t sb = sbase + (kt % 3) * AT_BUF;

        float s[8][4];
        #pragma unroll
        for (int t = 0; t < 8; t++)
            #pragma unroll
            for (int e = 0; e < 4; e++) s[t][e] = 0.0f;
        #pragma unroll
        for (int kc = 0; kc < 4; kc++) {
            uint32_t kh[4][4], kl[4][4];
            #pragma unroll
            for (int u = 0; u < 4; u++) {
                int krow = u * 16 + lr, chunk = 2 * kc + ls;
                uint32_t a = sb + krow * 128 + ((chunk ^ (krow & 7)) << 4);
                ldsm_x4(kh[u], a);
                ldsm_x4(kl[u], a + 8192);
            }
            #pragma unroll
            for (int u = 0; u < 4; u++) {
                mma16816(s[2 * u],     qh[kc], kh[u][0], kh[u][2]);
                mma16816(s[2 * u + 1], qh[kc], kh[u][1], kh[u][3]);
            }
            #pragma unroll
            for (int u = 0; u < 4; u++) {
                mma16816(s[2 * u],     qh[kc], kl[u][0], kl[u][2]);
                mma16816(s[2 * u + 1], qh[kc], kl[u][1], kl[u][3]);
            }
            #pragma unroll
            for (int u = 0; u < 4; u++) {
                mma16816(s[2 * u],     ql[kc], kh[u][0], kh[u][2]);
                mma16816(s[2 * u + 1], ql[kc], kh[u][1], kh[u][3]);
            }
        }

        const int row0 = qt * 64 + w * 16 + (lane >> 2);
        if (bias) {
            #pragma unroll
            for (int t = 0; t < 8; t++) {
                int col = kt * 64 + t * 8 + 2 * (lane & 3);
                float2 b0 = *(const float2*)(bias + (size_t)row0 * TA + col);
                float2 b1 = *(const float2*)(bias + (size_t)(row0 + 8) * TA + col);
                s[t][0] = s[t][0] * scale + b0.x; s[t][1] = s[t][1] * scale + b0.y;
                s[t][2] = s[t][2] * scale + b1.x; s[t][3] = s[t][3] * scale + b1.y;
            }
        } else {
            #pragma unroll
            for (int t = 0; t < 8; t++)
                #pragma unroll
                for (int e = 0; e < 4; e++) s[t][e] *= scale;
        }

        float mx0 = -1e30f, mx1 = -1e30f;
        #pragma unroll
        for (int t = 0; t < 8; t++) {
            mx0 = fmaxf(mx0, fmaxf(s[t][0], s[t][1]));
            mx1 = fmaxf(mx1, fmaxf(s[t][2], s[t][3]));
        }
        mx0 = fmaxf(mx0, __shfl_xor_sync(0xffffffffu, mx0, 1));
        mx0 = fmaxf(mx0, __shfl_xor_sync(0xffffffffu, mx0, 2));
        mx1 = fmaxf(mx1, __shfl_xor_sync(0xffffffffu, mx1, 1));
        mx1 = fmaxf(mx1, __shfl_xor_sync(0xffffffffu, mx1, 2));
        float mn0 = fmaxf(mrow0, mx0), mn1 = fmaxf(mrow1, mx1);
        float a0 = __expf(mrow0 - mn0), a1 = __expf(mrow1 - mn1);
        mrow0 = mn0; mrow1 = mn1;

        float sum0 = 0.0f, sum1 = 0.0f;
        uint32_t phi[4][4], plo[4][4];
        #pragma unroll
        for (int t = 0; t < 8; t++) {
            float p0 = __expf(s[t][0] - mn0), p1 = __expf(s[t][1] - mn0);
            float p2 = __expf(s[t][2] - mn1), p3 = __expf(s[t][3] - mn1);
            sum0 += p0 + p1; sum1 += p2 + p3;
            __nv_bfloat16 h0 = __float2bfloat16(p0), h1 = __float2bfloat16(p1);
            __nv_bfloat16 h2 = __float2bfloat16(p2), h3 = __float2bfloat16(p3);
            const int kc = t >> 1, j = (t & 1) * 2;
            phi[kc][j]     = (uint32_t)__bfloat16_as_ushort(h0) | ((uint32_t)__bfloat16_as_ushort(h1) << 16);
            phi[kc][j + 1] = (uint32_t)__bfloat16_as_ushort(h2) | ((uint32_t)__bfloat16_as_ushort(h3) << 16);
            plo[kc][j]     = pack_bf16x2(p0 - __bfloat162float(h0), p1 - __bfloat162float(h1));
            plo[kc][j + 1] = pack_bf16x2(p2 - __bfloat162float(h2), p3 - __bfloat162float(h3));
        }
        sum0 += __shfl_xor_sync(0xffffffffu, sum0, 1);
        sum0 += __shfl_xor_sync(0xffffffffu, sum0, 2);
        sum1 += __shfl_xor_sync(0xffffffffu, sum1, 1);
        sum1 += __shfl_xor_sync(0xffffffffu, sum1, 2);
        lsum0 = lsum0 * a0 + sum0;
        lsum1 = lsum1 * a1 + sum1;
        #pragma unroll
        for (int t = 0; t < 8; t++) {
            o[t][0] *= a0; o[t][1] *= a0;
            o[t][2] *= a1; o[t][3] *= a1;
        }

        #pragma unroll
        for (int kc = 0; kc < 4; kc++) {
            int vkey = kc * 16 + vkbase;
            uint32_t vh[4][4], vl[4][4];
            #pragma unroll
            for (int du = 0; du < 4; du++) {
                int chunk = 2 * du + vcsel;
                uint32_t a = sb + 16384 + vkey * 128 + ((chunk ^ (vkey & 7)) << 4);
                ldsm_x4_t(vh[du], a);
                ldsm_x4_t(vl[du], a + 8192);
            }
            #pragma unroll
            for (int du = 0; du < 4; du++) {
                mma16816(o[2 * du],     phi[kc], vh[du][0], vh[du][2]);
                mma16816(o[2 * du + 1], phi[kc], vh[du][1], vh[du][3]);
            }
            #pragma unroll
            for (int du = 0; du < 4; du++) {
                mma16816(o[2 * du],     phi[kc], vl[du][0], vl[du][2]);
                mma16816(o[2 * du + 1], phi[kc], vl[du][1], vl[du][3]);
            }
            #pragma unroll
            for (int du = 0; du < 4; du++) {
                mma16816(o[2 * du],     plo[kc], vh[du][0], vh[du][2]);
                mma16816(o[2 * du + 1], plo[kc], vh[du][1], vh[du][3]);
            }
        }
    }

    float inv0 = 1.0f / lsum0, inv1 = 1.0f / lsum1;
    const int row0 = qt * 64 + w * 16 + (lane >> 2);
    #pragma unroll
    for (int t = 0; t < 8; t++) {
        int col = t * 8 + 2 * (lane & 3);
        float v0 = o[t][0] * inv0, v1 = o[t][1] * inv0;
        float v2 = o[t][2] * inv1, v3 = o[t][3] * inv1;
        size_t off0 = (size_t)(row0 * BATCH + b) * D_MODEL + h * HDIM + col;
        size_t off1 = (size_t)((row0 + 8) * BATCH + b) * D_MODEL + h * HDIM + col;
        __nv_bfloat16 h0 = __float2bfloat16(v0), h1 = __float2bfloat16(v1);
        __nv_bfloat16 h2 = __float2bfloat16(v2), h3 = __float2bfloat16(v3);
        *(uint32_t*)(Ohi + off0) = (uint32_t)__bfloat16_as_ushort(h0) | ((uint32_t)__bfloat16_as_ushort(h1) << 16);
        *(uint32_t*)(Olo + off0) = pack_bf16x2(v0 - __bfloat162float(h0), v1 - __bfloat162float(h1));
        *(uint32_t*)(Ohi + off1) = (uint32_t)__bfloat16_as_ushort(h2) | ((uint32_t)__bfloat16_as_ushort(h3) << 16);
        *(uint32_t*)(Olo + off1) = pack_bf16x2(v2 - __bfloat162float(h2), v3 - __bfloat162float(h3));
    }
}

// ---------------- Bias precompute ----------------
__global__ void bias_kernel(const int* __restrict__ beats, float* __restrict__ out) {
    __shared__ int sb[NBEATS];
    int i = blockIdx.x;
    int j = threadIdx.x;
    if (threadIdx.x < NBEATS) sb[threadIdx.x] = beats[threadIdx.x];
    __syncthreads();
    float bb = 0.0f;
    #pragma unroll 8
    for (int n = 0; n < NBEATS; n++) {
        int bf = sb[n];
        if (j == bf) bb = fmaxf(bb, 2.0f);
        if (bf > 0      && j == bf - 1) bb = fmaxf(bb, 1.0f);
        if (bf < TA - 1 && j == bf + 1) bb = fmaxf(bb, 1.0f);
    }
    float scale = (float)(TA - 1) / (float)(TM - 1);
    float d = (float)i * scale - (float)j;
    out[i * TA + j] = -(d * d) * (1.0f / 32.0f) + bb;
}

// ---------------- Fused residual + LayerNorm (+ optional bf16 split out) ----------------
__global__ __launch_bounds__(256) void add_ln_kernel(
    const float* __restrict__ A, const float* __restrict__ Bv,
    const float* __restrict__ gatePtr,
    const float* __restrict__ gamma, const float* __restrict__ beta,
    float* __restrict__ out,
    __nv_bfloat16* __restrict__ ohi, __nv_bfloat16* __restrict__ olo)
{
    int t = blockIdx.x;
    int tid = threadIdx.x;
    float gscale = gatePtr ? tanhf(*gatePtr) : 1.0f;
    const float4* a4 = (const float4*)(A  + (size_t)t * D_MODEL);
    const float4* b4 = (const float4*)(Bv + (size_t)t * D_MODEL);
    float4 av = a4[tid], bv = b4[tid];
    float x0 = av.x + gscale * bv.x;
    float x1 = av.y + gscale * bv.y;
    float x2 = av.z + gscale * bv.z;
    float x3 = av.w + gscale * bv.w;
    float s  = x0 + x1 + x2 + x3;
    float ss = x0 * x0 + x1 * x1 + x2 * x2 + x3 * x3;

    __shared__ float rs[8], rss[8];
    #pragma unroll
    for (int o = 16; o > 0; o >>= 1) {
        s  += __shfl_xor_sync(0xffffffffu, s,  o);
        ss += __shfl_xor_sync(0xffffffffu, ss, o);
    }
    if ((tid & 31) == 0) { rs[tid >> 5] = s; rss[tid >> 5] = ss; }
    __syncthreads();
    float stot = 0.0f, sstot = 0.0f;
    #pragma unroll
    for (int i = 0; i < 8; i++) { stot += rs[i]; sstot += rss[i]; }
    float mean = stot * (1.0f / D_MODEL);
    float var  = sstot * (1.0f / D_MODEL) - mean * mean;
    float rstd = rsqrtf(var + LN_EPS);

    const float4* g4 = (const float4*)gamma;
    const float4* be4 = (const float4*)beta;
    float4 g = g4[tid], be = be4[tid];
    float4 o;
    o.x = (x0 - mean) * rstd * g.x + be.x;
    o.y = (x1 - mean) * rstd * g.y + be.y;
    o.z = (x2 - mean) * rstd * g.z + be.z;
    o.w = (x3 - mean) * rstd * g.w + be.w;
    ((float4*)(out + (size_t)t * D_MODEL))[tid] = o;
    if (ohi) {
        uint2 uh, ul;
        split4(o, uh, ul);
        ((uint2*)(ohi + (size_t)t * D_MODEL))[tid] = uh;
        ((uint2*)(olo + (size_t)t * D_MODEL))[tid] = ul;
    }
}

// ---------------- Launch ----------------
extern "C" void kernel_launch(void* const* d_in, const int* in_sizes, int n_in,
                              void* d_out, int out_size) {
    const float* src      = (const float*)d_in[0];
    const float* audio    = (const float*)d_in[1];
    const int*   beats    = (const int*)  d_in[2];
    const float* sa_in_w  = (const float*)d_in[3];
    const float* sa_in_b  = (const float*)d_in[4];
    const float* sa_out_w = (const float*)d_in[5];
    const float* sa_out_b = (const float*)d_in[6];
    const float* ca_in_w  = (const float*)d_in[7];
    const float* ca_in_b  = (const float*)d_in[8];
    const float* ca_out_w = (const float*)d_in[9];
    const float* ca_out_b = (const float*)d_in[10];
    const float* gate     = (const float*)d_in[11];
    const float* n1_g     = (const float*)d_in[12];
    const float* n1_b     = (const float*)d_in[13];
    const float* nc_g     = (const float*)d_in[14];
    const float* nc_b     = (const float*)d_in[15];
    const float* n2_g     = (const float*)d_in[16];
    const float* n2_b     = (const float*)d_in[17];
    const float* lin1_w   = (const float*)d_in[18];
    const float* lin1_b   = (const float*)d_in[19];
    const float* lin2_w   = (const float*)d_in[20];
    const float* lin2_b   = (const float*)d_in[21];
    float* out = (float*)d_out;

    float *tmp, *x1, *x2, *ff2, *bias;
    __nv_bfloat16 *Xhi, *Xlo, *Hhi, *Hlo, *Whi, *Wlo;
    __nv_bfloat16 *QKVhi, *QKVlo, *KVhi, *KVlo, *CQhi, *CQlo;
    cudaGetSymbolAddress((void**)&tmp,  g_tmp);
    cudaGetSymbolAddress((void**)&x1,   g_x1);
    cudaGetSymbolAddress((void**)&x2,   g_x2);
    cudaGetSymbolAddress((void**)&ff2,  g_ff2);
    cudaGetSymbolAddress((void**)&bias, g_bias);
    cudaGetSymbolAddress((void**)&Xhi,  g_Xhi);
    cudaGetSymbolAddress((void**)&Xlo,  g_Xlo);
    cudaGetSymbolAddress((void**)&Hhi,  g_Hhi);
    cudaGetSymbolAddress((void**)&Hlo,  g_Hlo);
    cudaGetSymbolAddress((void**)&Whi,  g_Whi);
    cudaGetSymbolAddress((void**)&Wlo,  g_Wlo);
    cudaGetSymbolAddress((void**)&QKVhi, g_QKVhi);
    cudaGetSymbolAddress((void**)&QKVlo, g_QKVlo);
    cudaGetSymbolAddress((void**)&KVhi,  g_KVhi);
    cudaGetSymbolAddress((void**)&KVlo,  g_KVlo);
    cudaGetSymbolAddress((void**)&CQhi,  g_CQhi);
    cudaGetSymbolAddress((void**)&CQlo,  g_CQlo);

    cudaFuncSetAttribute(gemm_mma, cudaFuncAttributeMaxDynamicSharedMemorySize, G_SMEM);
    cudaFuncSetAttribute(attn_mma, cudaFuncAttributeMaxDynamicSharedMemorySize, AT_SMEM);

    const int CVT_B = 256 * 4;
    #define CVT(srcp, hip, lop, n) cvt_kernel<<<(n) / CVT_B, 256>>>(srcp, hip, lop, n)
    #define GEMM(ahi, alo, bhi, blo, bp, cf, ohi, olo, Nn, Kk, act) \
        gemm_mma<<<dim3((Nn) / 128, NTOK / 128), 256, G_SMEM>>>(ahi, alo, bhi, blo, bp, cf, ohi, olo, Nn, Kk, act)
    #define BF16_NULL (__nv_bfloat16*)nullptr

    bias_kernel<<<TM, TA>>>(beats, bias);
    wcvt_kernel<<<W_TOTAL / CVT_B, 256>>>(sa_in_w, sa_out_w, ca_in_w, ca_out_w,
                                          lin1_w, lin2_w, Whi, Wlo);
    CVT(src, Xhi, Xlo, NTOK * D_MODEL);

    // 3) SA packed QKV (split-bf16 output)
    GEMM(Xhi, Xlo, Whi + W_SAIN, Wlo + W_SAIN, sa_in_b, (float*)nullptr,
         QKVhi, QKVlo, 3 * D_MODEL, D_MODEL, 0);

    // 4) SA attention
    attn_mma<<<dim3(TM / 64, BATCH * NHEAD), 128, AT_SMEM>>>(
        QKVhi, QKVlo, 3 * D_MODEL, 0,
        QKVhi, QKVlo, 3 * D_MODEL, D_MODEL,
        QKVhi, QKVlo, 3 * D_MODEL, 2 * D_MODEL,
        Xhi, Xlo, nullptr, 0.125f);

    // 5) SA out-proj  (ncu -s 5 lands here)
    GEMM(Xhi, Xlo, Whi + W_SAOUT, Wlo + W_SAOUT, sa_out_b, tmp,
         BF16_NULL, BF16_NULL, D_MODEL, D_MODEL, 0);

    // 6) x1 = LN1(src + sa), fused split
    add_ln_kernel<<<NTOK, 256>>>(src, tmp, nullptr, n1_g, n1_b, x1, Xhi, Xlo);

    // 7) CA Q-proj
    GEMM(Xhi, Xlo, Whi + W_CAIN, Wlo + W_CAIN, ca_in_b, (float*)nullptr,
         CQhi, CQlo, D_MODEL, D_MODEL, 0);

    // 8-9) audio convert + CA KV-proj
    CVT(audio, Xhi, Xlo, NTOK * D_MODEL);
    GEMM(Xhi, Xlo, Whi + W_CAIN + (size_t)D_MODEL * D_MODEL, Wlo + W_CAIN + (size_t)D_MODEL * D_MODEL,
         ca_in_b + D_MODEL, (float*)nullptr, KVhi, KVlo, 2 * D_MODEL, D_MODEL, 0);

    // 10) CA attention (biased)
    attn_mma<<<dim3(TM / 64, BATCH * NHEAD), 128, AT_SMEM>>>(
        CQhi, CQlo, D_MODEL, 0,
        KVhi, KVlo, 2 * D_MODEL, 0,
        KVhi, KVlo, 2 * D_MODEL, D_MODEL,
        Xhi, Xlo, bias, 0.125f);

    // 11) CA out-proj
    GEMM(Xhi, Xlo, Whi + W_CAOUT, Wlo + W_CAOUT, ca_out_b, tmp,
         BF16_NULL, BF16_NULL, D_MODEL, D_MODEL, 0);

    // 12) x2 = LNc(x1 + tanh(gate)*cross), fused split
    add_ln_kernel<<<NTOK, 256>>>(x1, tmp, gate, nc_g, nc_b, x2, Xhi, Xlo);

    // 13-14) FFN
    GEMM(Xhi, Xlo, Whi + W_LIN1, Wlo + W_LIN1, lin1_b, (float*)nullptr, Hhi, Hlo,
         DFF, D_MODEL, 1);
    GEMM(Hhi, Hlo, Whi + W_LIN2, Wlo + W_LIN2, lin2_b, ff2,
         BF16_NULL, BF16_NULL, D_MODEL, DFF, 0);

    // 15) out = LN2(x2 + ff)
    add_ln_kernel<<<NTOK, 256>>>(x2, ff2, nullptr, n2_g, n2_b, out,
                                 BF16_NULL, BF16_NULL);
}

// round 9
// speedup vs baseline: 1.2294x; 1.0031x over previous
#include <cuda_runtime.h>
#include <cuda_bf16.h>
#include <math.h>
#include <stdint.h>

// ---------------- Problem constants ----------------
#define D_MODEL 1024
#define NHEAD   16
#define HDIM    64
#define DFF     4096
#define TM      512
#define TA      512
#define BATCH   32
#define NTOK    (TM * BATCH)   // 16384
#define NBEATS  64
#define LN_EPS  1e-5f

// ---------------- fp32 scratch ----------------
__device__ float g_tmp [NTOK * D_MODEL];
__device__ float g_x1  [NTOK * D_MODEL];
__device__ float g_x2  [NTOK * D_MODEL];
__device__ float g_ff2 [NTOK * D_MODEL];
__device__ float g_bias[TM * TA];

// ---------------- bf16 split scratch ----------------
__device__ __nv_bfloat16 g_Xhi [NTOK * D_MODEL];
__device__ __nv_bfloat16 g_Xlo [NTOK * D_MODEL];
__device__ __nv_bfloat16 g_AUhi[NTOK * D_MODEL];
__device__ __nv_bfloat16 g_AUlo[NTOK * D_MODEL];
__device__ __nv_bfloat16 g_Hhi [NTOK * DFF];
__device__ __nv_bfloat16 g_Hlo [NTOK * DFF];
__device__ __nv_bfloat16 g_QKVhi[NTOK * 3 * D_MODEL];
__device__ __nv_bfloat16 g_QKVlo[NTOK * 3 * D_MODEL];
__device__ __nv_bfloat16 g_KVhi[NTOK * 2 * D_MODEL];
__device__ __nv_bfloat16 g_KVlo[NTOK * 2 * D_MODEL];
__device__ __nv_bfloat16 g_CQhi[NTOK * D_MODEL];
__device__ __nv_bfloat16 g_CQlo[NTOK * D_MODEL];
__device__ __nv_bfloat16 g_Whi[16777216];
__device__ __nv_bfloat16 g_Wlo[16777216];

#define W_SAIN   0
#define W_SAOUT  3145728
#define W_CAIN   4194304
#define W_CAOUT  7340032
#define W_LIN1   8388608
#define W_LIN2  12582912
#define W_TOTAL 16777216

// ================= helpers (non-'a' PTX only) =================
__device__ __forceinline__ uint32_t smem_u32(const void* p) {
    uint32_t a;
    asm("{ .reg .u64 t; cvta.to.shared.u64 t, %1; cvt.u32.u64 %0, t; }" : "=r"(a) : "l"(p));
    return a;
}
__device__ __forceinline__ void cp_async16(uint32_t saddr, const void* g) {
    asm volatile("cp.async.cg.shared.global [%0], [%1], 16;" :: "r"(saddr), "l"(g));
}
__device__ __forceinline__ void cp_commit() {
    asm volatile("cp.async.commit_group;" ::: "memory");
}
__device__ __forceinline__ void ldsm_x4(uint32_t (&r)[4], uint32_t addr) {
    asm volatile("ldmatrix.sync.aligned.m8n8.x4.shared.b16 {%0,%1,%2,%3}, [%4];"
                 : "=r"(r[0]), "=r"(r[1]), "=r"(r[2]), "=r"(r[3]) : "r"(addr));
}
__device__ __forceinline__ void ldsm_x4_t(uint32_t (&r)[4], uint32_t addr) {
    asm volatile("ldmatrix.sync.aligned.m8n8.x4.trans.shared.b16 {%0,%1,%2,%3}, [%4];"
                 : "=r"(r[0]), "=r"(r[1]), "=r"(r[2]), "=r"(r[3]) : "r"(addr));
}
__device__ __forceinline__ void mma16816(float (&d)[4], const uint32_t (&a)[4],
                                         uint32_t b0, uint32_t b1) {
    asm volatile(
        "mma.sync.aligned.m16n8k16.row.col.f32.bf16.bf16.f32 "
        "{%0,%1,%2,%3}, {%4,%5,%6,%7}, {%8,%9}, {%0,%1,%2,%3};"
        : "+f"(d[0]), "+f"(d[1]), "+f"(d[2]), "+f"(d[3])
        : "r"(a[0]), "r"(a[1]), "r"(a[2]), "r"(a[3]), "r"(b0), "r"(b1));
}
__device__ __forceinline__ uint32_t pack_bf16x2(float x, float y) {
    return (uint32_t)__bfloat16_as_ushort(__float2bfloat16(x)) |
           ((uint32_t)__bfloat16_as_ushort(__float2bfloat16(y)) << 16);
}
__device__ __forceinline__ void split4(float4 v, uint2& uh, uint2& ul) {
    __nv_bfloat16 h0 = __float2bfloat16(v.x), h1 = __float2bfloat16(v.y);
    __nv_bfloat16 h2 = __float2bfloat16(v.z), h3 = __float2bfloat16(v.w);
    uh.x = (uint32_t)__bfloat16_as_ushort(h0) | ((uint32_t)__bfloat16_as_ushort(h1) << 16);
    uh.y = (uint32_t)__bfloat16_as_ushort(h2) | ((uint32_t)__bfloat16_as_ushort(h3) << 16);
    ul.x = pack_bf16x2(v.x - __bfloat162float(h0), v.y - __bfloat162float(h1));
    ul.y = pack_bf16x2(v.z - __bfloat162float(h2), v.w - __bfloat162float(h3));
}

// ================= converts =================
__global__ __launch_bounds__(256) void cvt_kernel(
    const float* __restrict__ src, __nv_bfloat16* __restrict__ hi,
    __nv_bfloat16* __restrict__ lo, int n)
{
    int i = (blockIdx.x * 256 + threadIdx.x) * 4;
    if (i >= n) return;
    uint2 uh, ul;
    split4(*(const float4*)(src + i), uh, ul);
    *(uint2*)(hi + i) = uh;
    *(uint2*)(lo + i) = ul;
}

__global__ __launch_bounds__(256) void wcvt_kernel(
    const float* __restrict__ w0, const float* __restrict__ w1,
    const float* __restrict__ w2, const float* __restrict__ w3,
    const float* __restrict__ w4, const float* __restrict__ w5,
    __nv_bfloat16* __restrict__ hi, __nv_bfloat16* __restrict__ lo)
{
    int i = (blockIdx.x * 256 + threadIdx.x) * 4;
    const float* src; int off;
    if      (i < W_SAOUT) { src = w0; off = W_SAIN; }
    else if (i < W_CAIN)  { src = w1; off = W_SAOUT; }
    else if (i < W_CAOUT) { src = w2; off = W_CAIN; }
    else if (i < W_LIN1)  { src = w3; off = W_CAOUT; }
    else if (i < W_LIN2)  { src = w4; off = W_LIN1; }
    else                  { src = w5; off = W_LIN2; }
    uint2 uh, ul;
    split4(*(const float4*)(src + (i - off)), uh, ul);
    *(uint2*)(hi + i) = uh;
    *(uint2*)(lo + i) = ul;
}

// ================= mma.sync GEMM =================
// C[M,N] = A[M,K]*B[N,K]^T + bias, 3-term split-bf16. CTA 128x128 (warp 32x64),
// BK=32, 3 stages, 2 CTAs/SM. Prefetch split into A-half / B-half interleaved
// with compute to spread LSU issue.
#define G_STAGE 32768
#define G_SMEM  (3 * G_STAGE)

__global__ __launch_bounds__(256, 2) void gemm_mma(
    const __nv_bfloat16* __restrict__ Ahi, const __nv_bfloat16* __restrict__ Alo,
    const __nv_bfloat16* __restrict__ Bhi, const __nv_bfloat16* __restrict__ Blo,
    const float* __restrict__ bias, float* __restrict__ Cf,
    __nv_bfloat16* __restrict__ Ohi, __nv_bfloat16* __restrict__ Olo,
    int N, int K, int act)
{
    extern __shared__ __align__(128) char smem[];
    const uint32_t sbase = smem_u32(smem);
    const int tid = threadIdx.x;
    const int lane = tid & 31, wid = tid >> 5;
    const int warp_m = wid & 3, warp_n = wid >> 2;
    const int m0 = blockIdx.y * 128, n0 = blockIdx.x * 128;

    float acc[2][8][4];
    #pragma unroll
    for (int t = 0; t < 2; t++)
        #pragma unroll
        for (int j = 0; j < 8; j++)
            #pragma unroll
            for (int e = 0; e < 4; e++) acc[t][j][e] = 0.0f;

    int lr0 = tid >> 2,         lc0 = tid & 3;
    int lr1 = (tid + 256) >> 2, lc1 = tid & 3;
    uint32_t lsw0 = lr0 * 64 + ((lc0 ^ ((lr0 >> 1) & 3)) << 4);
    uint32_t lsw1 = lr1 * 64 + ((lc1 ^ ((lr1 >> 1) & 3)) << 4);

    auto load_A = [&](int ci, uint32_t sb) {
        const int kk = ci * 32;
        size_t goA0 = (size_t)(m0 + lr0) * K + kk + lc0 * 8;
        size_t goA1 = (size_t)(m0 + lr1) * K + kk + lc1 * 8;
        cp_async16(sb + lsw0,        Ahi + goA0);
        cp_async16(sb + 8192 + lsw0, Alo + goA0);
        cp_async16(sb + lsw1,        Ahi + goA1);
        cp_async16(sb + 8192 + lsw1, Alo + goA1);
    };
    auto load_B = [&](int ci, uint32_t sb) {
        const int kk = ci * 32;
        size_t goB0 = (size_t)(n0 + lr0) * K + kk + lc0 * 8;
        size_t goB1 = (size_t)(n0 + lr1) * K + kk + lc1 * 8;
        cp_async16(sb + 16384 + lsw0, Bhi + goB0);
        cp_async16(sb + 24576 + lsw0, Blo + goB0);
        cp_async16(sb + 16384 + lsw1, Bhi + goB1);
        cp_async16(sb + 24576 + lsw1, Blo + goB1);
    };

    const int lr = lane & 15;
    const int lseg = lane >> 4;
    int arow[2], brow[4];
    #pragma unroll
    for (int t = 0; t < 2; t++) arow[t] = warp_m * 32 + t * 16 + lr;
    #pragma unroll
    for (int u = 0; u < 4; u++) brow[u] = warp_n * 64 + u * 16 + lr;

    const int nch = K >> 5;
    load_A(0, sbase);             load_B(0, sbase);             cp_commit();
    load_A(1, sbase + G_STAGE);   load_B(1, sbase + G_STAGE);   cp_commit();

    for (int i = 0; i < nch; i++) {
        if (i < nch - 1) asm volatile("cp.async.wait_group 1;" ::: "memory");
        else             asm volatile("cp.async.wait_group 0;" ::: "memory");
        __syncthreads();

        const uint32_t sb = sbase + (i % 3) * G_STAGE;
        const bool pf = (i + 2 < nch);
        const uint32_t psb = sbase + ((i + 2) % 3) * G_STAGE;

        #pragma unroll
        for (int s = 0; s < 2; s++) {
            const int chunk = 2 * s + lseg;
            uint32_t ah[2][4], al[2][4];
            #pragma unroll
            for (int t = 0; t < 2; t++) {
                uint32_t a = sb + arow[t] * 64 + ((chunk ^ ((arow[t] >> 1) & 3)) << 4);
                ldsm_x4(ah[t], a);
                ldsm_x4(al[t], a + 8192);
            }
            // spread the prefetch: A-half after s=0 frag loads, B-half after s=1
            if (s == 0) { if (pf) load_A(i + 2, psb); }
            else        { if (pf) { load_B(i + 2, psb); cp_commit(); } }

            #pragma unroll
            for (int half = 0; half < 2; half++) {
                uint32_t bh[2][4], bl[2][4];
                #pragma unroll
                for (int uu = 0; uu < 2; uu++) {
                    int u = 2 * half + uu;
                    uint32_t a = sb + 16384 + brow[u] * 64 + ((chunk ^ ((brow[u] >> 1) & 3)) << 4);
                    ldsm_x4(bh[uu], a);
                    ldsm_x4(bl[uu], a + 8192);
                }
                #pragma unroll
                for (int t = 0; t < 2; t++)
                    #pragma unroll
                    for (int uu = 0; uu < 2; uu++) {
                        int j = 2 * (2 * half + uu);
                        mma16816(acc[t][j],     ah[t], bh[uu][0], bh[uu][2]);
                        mma16816(acc[t][j + 1], ah[t], bh[uu][1], bh[uu][3]);
                    }
                #pragma unroll
                for (int t = 0; t < 2; t++)
                    #pragma unroll
                    for (int uu = 0; uu < 2; uu++) {
                        int j = 2 * (2 * half + uu);
                        mma16816(acc[t][j],     ah[t], bl[uu][0], bl[uu][2]);
                        mma16816(acc[t][j + 1], ah[t], bl[uu][1], bl[uu][3]);
                    }
                #pragma unroll
                for (int t = 0; t < 2; t++)
                    #pragma unroll
                    for (int uu = 0; uu < 2; uu++) {
                        int j = 2 * (2 * half + uu);
                        mma16816(acc[t][j],     al[t], bh[uu][0], bh[uu][2]);
                        mma16816(acc[t][j + 1], al[t], bh[uu][1], bh[uu][3]);
                    }
            }
        }
    }

    #pragma unroll
    for (int t = 0; t < 2; t++) {
        const int rbase = m0 + warp_m * 32 + t * 16 + (lane >> 2);
        #pragma unroll
        for (int j = 0; j < 8; j++) {
            const int col = n0 + warp_n * 64 + j * 8 + 2 * (lane & 3);
            const float b0 = __ldg(bias + col), b1 = __ldg(bias + col + 1);
            #pragma unroll
            for (int half = 0; half < 2; half++) {
                const int row = rbase + 8 * half;
                float v0 = acc[t][j][2 * half]     + b0;
                float v1 = acc[t][j][2 * half + 1] + b1;
                if (act) {
                    v0 = 0.5f * v0 * (1.0f + erff(v0 * 0.70710678118654752f));
                    v1 = 0.5f * v1 * (1.0f + erff(v1 * 0.70710678118654752f));
                }
                const size_t off = (size_t)row * N + col;
                if (Cf) {
                    *(float2*)(Cf + off) = make_float2(v0, v1);
                } else {
                    __nv_bfloat16 h0 = __float2bfloat16(v0);
                    __nv_bfloat16 h1 = __float2bfloat16(v1);
                    *(uint32_t*)(Ohi + off) =
                        (uint32_t)__bfloat16_as_ushort(h0) | ((uint32_t)__bfloat16_as_ushort(h1) << 16);
                    *(uint32_t*)(Olo + off) =
                        pack_bf16x2(v0 - __bfloat162float(h0), v1 - __bfloat162float(h1));
                }
            }
        }
    }
}

// ================= FA2-style attention on mma.sync =================
#define AT_BUF  32768
#define AT_SMEM (3 * AT_BUF)

__global__ __launch_bounds__(128) void attn_mma(
    const __nv_bfloat16* __restrict__ Qhi, const __nv_bfloat16* __restrict__ Qlo, int ldq, int qoff,
    const __nv_bfloat16* __restrict__ Khi, const __nv_bfloat16* __restrict__ Klo, int ldk, int koff,
    const __nv_bfloat16* __restrict__ Vhi, const __nv_bfloat16* __restrict__ Vlo, int ldv, int voff,
    __nv_bfloat16* __restrict__ Ohi, __nv_bfloat16* __restrict__ Olo,
    const float* __restrict__ bias, float scale)
{
    extern __shared__ __align__(128) char smem[];
    const uint32_t sbase = smem_u32(smem);
    const int tid = threadIdx.x, lane = tid & 31, w = tid >> 5;
    const int qt = blockIdx.x, bh = blockIdx.y;
    const int b = bh & (BATCH - 1), h = bh >> 5;

    #pragma unroll
    for (int it = 0; it < 4; it++) {
        int idx = tid + it * 128, r = idx >> 3, c = idx & 7;
        uint32_t sw = r * 128 + ((c ^ (r & 7)) << 4);
        size_t g = (size_t)((qt * 64 + r) * BATCH + b) * ldq + qoff + h * HDIM + c * 8;
        cp_async16(sbase + sw,        Qhi + g);
        cp_async16(sbase + 8192 + sw, Qlo + g);
    }
    cp_commit();
    asm volatile("cp.async.wait_group 0;" ::: "memory");
    __syncthreads();

    const int lr = lane & 15, ls = lane >> 4;
    uint32_t qh[4][4], ql[4][4];
    {
        int qrow = w * 16 + lr;
        #pragma unroll
        for (int kc = 0; kc < 4; kc++) {
            int chunk = 2 * kc + ls;
            uint32_t a = sbase + qrow * 128 + ((chunk ^ (qrow & 7)) << 4);
            ldsm_x4(qh[kc], a);
            ldsm_x4(ql[kc], a + 8192);
        }
    }
    __syncthreads();

    auto load_kt = [&](int kt, int st) {
        uint32_t sb = sbase + st * AT_BUF;
        #pragma unroll
        for (int it = 0; it < 4; it++) {
            int idx = tid + it * 128, r = idx >> 3, c = idx & 7;
            uint32_t sw = r * 128 + ((c ^ (r & 7)) << 4);
            size_t rowi = (size_t)((kt * 64 + r) * BATCH + b);
            size_t gk = rowi * ldk + koff + h * HDIM + c * 8;
            size_t gv = rowi * ldv + voff + h * HDIM + c * 8;
            cp_async16(sb + sw,         Khi + gk);
            cp_async16(sb + 8192 + sw,  Klo + gk);
            cp_async16(sb + 16384 + sw, Vhi + gv);
            cp_async16(sb + 24576 + sw, Vlo + gv);
        }
        cp_commit();
    };
    load_kt(0, 0);
    load_kt(1, 1);

    float o[8][4];
    #pragma unroll
    for (int t = 0; t < 8; t++)
        #pragma unroll
        for (int e = 0; e < 4; e++) o[t][e] = 0.0f;
    float mrow0 = -1e30f, mrow1 = -1e30f, lsum0 = 0.0f, lsum1 = 0.0f;

    const int vkbase = ((lane & 16) ? 8 : 0) + (lane & 7);
    const int vcsel  = (lane >> 3) & 1;

    for (int kt = 0; kt < 8; kt++) {
        if (kt < 7) asm volatile("cp.async.wait_group 1;" ::: "memory");
        else        asm volatile("cp.async.wait_group 0;" ::: "memory");
        __syncthreads();
        if (kt + 2 < 8) load_kt(kt + 2, (kt + 2) % 3);
        const uint32_t sb = sbase + (kt % 3) * AT_BUF;

        float s[8][4];
        #pragma unroll
        for (int t = 0; t < 8; t++)
            #pragma unroll
            for (int e = 0; e < 4; e++) s[t][e] = 0.0f;
        #pragma unroll
        for (int kc = 0; kc < 4; kc++) {
            uint32_t kh[4][4], kl[4][4];
            #pragma unroll
            for (int u = 0; u < 4; u++) {
                int krow = u * 16 + lr, chunk = 2 * kc + ls;
                uint32_t a = sb + krow * 128 + ((chunk ^ (krow & 7)) << 4);
                ldsm_x4(kh[u], a);
                ldsm_x4(kl[u], a + 8192);
            }
            #pragma unroll
            for (int u = 0; u < 4; u++) {
                mma16816(s[2 * u],     qh[kc], kh[u][0], kh[u][2]);
                mma16816(s[2 * u + 1], qh[kc], kh[u][1], kh[u][3]);
            }
            #pragma unroll
            for (int u = 0; u < 4; u++) {
                mma16816(s[2 * u],     qh[kc], kl[u][0], kl[u][2]);
                mma16816(s[2 * u + 1], qh[kc], kl[u][1], kl[u][3]);
            }
            #pragma unroll
            for (int u = 0; u < 4; u++) {
                mma16816(s[2 * u],     ql[kc], kh[u][0], kh[u][2]);
                mma16816(s[2 * u + 1], ql[kc], kh[u][1], kh[u][3]);
            }
        }

        const int row0 = qt * 64 + w * 16 + (lane >> 2);
        if (bias) {
            #pragma unroll
            for (int t = 0; t < 8; t++) {
                int col = kt * 64 + t * 8 + 2 * (lane & 3);
                float2 b0 = *(const float2*)(bias + (size_t)row0 * TA + col);
                float2 b1 = *(const float2*)(bias + (size_t)(row0 + 8) * TA + col);
                s[t][0] = s[t][0] * scale + b0.x; s[t][1] = s[t][1] * scale + b0.y;
                s[t][2] = s[t][2] * scale + b1.x; s[t][3] = s[t][3] * scale + b1.y;
            }
        } else {
            #pragma unroll
            for (int t = 0; t < 8; t++)
                #pragma unroll
                for (int e = 0; e < 4; e++) s[t][e] *= scale;
        }

        float mx0 = -1e30f, mx1 = -1e30f;
        #pragma unroll
        for (int t = 0; t < 8; t++) {
            mx0 = fmaxf(mx0, fmaxf(s[t][0], s[t][1]));
            mx1 = fmaxf(mx1, fmaxf(s[t][2], s[t][3]));
        }
        mx0 = fmaxf(mx0, __shfl_xor_sync(0xffffffffu, mx0, 1));
        mx0 = fmaxf(mx0, __shfl_xor_sync(0xffffffffu, mx0, 2));
        mx1 = fmaxf(mx1, __shfl_xor_sync(0xffffffffu, mx1, 1));
        mx1 = fmaxf(mx1, __shfl_xor_sync(0xffffffffu, mx1, 2));
        float mn0 = fmaxf(mrow0, mx0), mn1 = fmaxf(mrow1, mx1);
        float a0 = __expf(mrow0 - mn0), a1 = __expf(mrow1 - mn1);
        mrow0 = mn0; mrow1 = mn1;

        float sum0 = 0.0f, sum1 = 0.0f;
        uint32_t phi[4][4], plo[4][4];
        #pragma unroll
        for (int t = 0; t < 8; t++) {
            float p0 = __expf(s[t][0] - mn0), p1 = __expf(s[t][1] - mn0);
            float p2 = __expf(s[t][2] - mn1), p3 = __expf(s[t][3] - mn1);
            sum0 += p0 + p1; sum1 += p2 + p3;
            __nv_bfloat16 h0 = __float2bfloat16(p0), h1 = __float2bfloat16(p1);
            __nv_bfloat16 h2 = __float2bfloat16(p2), h3 = __float2bfloat16(p3);
            const int kc = t >> 1, j = (t & 1) * 2;
            phi[kc][j]     = (uint32_t)__bfloat16_as_ushort(h0) | ((uint32_t)__bfloat16_as_ushort(h1) << 16);
            phi[kc][j + 1] = (uint32_t)__bfloat16_as_ushort(h2) | ((uint32_t)__bfloat16_as_ushort(h3) << 16);
            plo[kc][j]     = pack_bf16x2(p0 - __bfloat162float(h0), p1 - __bfloat162float(h1));
            plo[kc][j + 1] = pack_bf16x2(p2 - __bfloat162float(h2), p3 - __bfloat162float(h3));
        }
        sum0 += __shfl_xor_sync(0xffffffffu, sum0, 1);
        sum0 += __shfl_xor_sync(0xffffffffu, sum0, 2);
        sum1 += __shfl_xor_sync(0xffffffffu, sum1, 1);
        sum1 += __shfl_xor_sync(0xffffffffu, sum1, 2);
        lsum0 = lsum0 * a0 + sum0;
        lsum1 = lsum1 * a1 + sum1;
        #pragma unroll
        for (int t = 0; t < 8; t++) {
            o[t][0] *= a0; o[t][1] *= a0;
            o[t][2] *= a1; o[t][3] *= a1;
        }

        #pragma unroll
        for (int kc = 0; kc < 4; kc++) {
            int vkey = kc * 16 + vkbase;
            uint32_t vh[4][4], vl[4][4];
            #pragma unroll
            for (int du = 0; du < 4; du++) {
                int chunk = 2 * du + vcsel;
                uint32_t a = sb + 16384 + vkey * 128 + ((chunk ^ (vkey & 7)) << 4);
                ldsm_x4_t(vh[du], a);
                ldsm_x4_t(vl[du], a + 8192);
            }
            #pragma unroll
            for (int du = 0; du < 4; du++) {
                mma16816(o[2 * du],     phi[kc], vh[du][0], vh[du][2]);
                mma16816(o[2 * du + 1], phi[kc], vh[du][1], vh[du][3]);
            }
            #pragma unroll
            for (int du = 0; du < 4; du++) {
                mma16816(o[2 * du],     phi[kc], vl[du][0], vl[du][2]);
                mma16816(o[2 * du + 1], phi[kc], vl[du][1], vl[du][3]);
            }
            #pragma unroll
            for (int du = 0; du < 4; du++) {
                mma16816(o[2 * du],     plo[kc], vh[du][0], vh[du][2]);
                mma16816(o[2 * du + 1], plo[kc], vh[du][1], vh[du][3]);
            }
        }
    }

    float inv0 = 1.0f / lsum0, inv1 = 1.0f / lsum1;
    const int row0 = qt * 64 + w * 16 + (lane >> 2);
    #pragma unroll
    for (int t = 0; t < 8; t++) {
        int col = t * 8 + 2 * (lane & 3);
        float v0 = o[t][0] * inv0, v1 = o[t][1] * inv0;
        float v2 = o[t][2] * inv1, v3 = o[t][3] * inv1;
        size_t off0 = (size_t)(row0 * BATCH + b) * D_MODEL + h * HDIM + col;
        size_t off1 = (size_t)((row0 + 8) * BATCH + b) * D_MODEL + h * HDIM + col;
        __nv_bfloat16 h0 = __float2bfloat16(v0), h1 = __float2bfloat16(v1);
        __nv_bfloat16 h2 = __float2bfloat16(v2), h3 = __float2bfloat16(v3);
        *(uint32_t*)(Ohi + off0) = (uint32_t)__bfloat16_as_ushort(h0) | ((uint32_t)__bfloat16_as_ushort(h1) << 16);
        *(uint32_t*)(Olo + off0) = pack_bf16x2(v0 - __bfloat162float(h0), v1 - __bfloat162float(h1));
        *(uint32_t*)(Ohi + off1) = (uint32_t)__bfloat16_as_ushort(h2) | ((uint32_t)__bfloat16_as_ushort(h3) << 16);
        *(uint32_t*)(Olo + off1) = pack_bf16x2(v2 - __bfloat162float(h2), v3 - __bfloat162float(h3));
    }
}

// ---------------- Bias precompute ----------------
__global__ void bias_kernel(const int* __restrict__ beats, float* __restrict__ out) {
    __shared__ int sb[NBEATS];
    int i = blockIdx.x;
    int j = threadIdx.x;
    if (threadIdx.x < NBEATS) sb[threadIdx.x] = beats[threadIdx.x];
    __syncthreads();
    float bb = 0.0f;
    #pragma unroll 8
    for (int n = 0; n < NBEATS; n++) {
        int bf = sb[n];
        if (j == bf) bb = fmaxf(bb, 2.0f);
        if (bf > 0      && j == bf - 1) bb = fmaxf(bb, 1.0f);
        if (bf < TA - 1 && j == bf + 1) bb = fmaxf(bb, 1.0f);
    }
    float scale = (float)(TA - 1) / (float)(TM - 1);
    float d = (float)i * scale - (float)j;
    out[i * TA + j] = -(d * d) * (1.0f / 32.0f) + bb;
}

// ---------------- Fused residual + LayerNorm (+ optional bf16 split out) ----------------
__global__ __launch_bounds__(256) void add_ln_kernel(
    const float* __restrict__ A, const float* __restrict__ Bv,
    const float* __restrict__ gatePtr,
    const float* __restrict__ gamma, const float* __restrict__ beta,
    float* __restrict__ out,
    __nv_bfloat16* __restrict__ ohi, __nv_bfloat16* __restrict__ olo)
{
    int t = blockIdx.x;
    int tid = threadIdx.x;
    float gscale = gatePtr ? tanhf(*gatePtr) : 1.0f;
    const float4* a4 = (const float4*)(A  + (size_t)t * D_MODEL);
    const float4* b4 = (const float4*)(Bv + (size_t)t * D_MODEL);
    float4 av = a4[tid], bv = b4[tid];
    float x0 = av.x + gscale * bv.x;
    float x1 = av.y + gscale * bv.y;
    float x2 = av.z + gscale * bv.z;
    float x3 = av.w + gscale * bv.w;
    float s  = x0 + x1 + x2 + x3;
    float ss = x0 * x0 + x1 * x1 + x2 * x2 + x3 * x3;

    __shared__ float rs[8], rss[8];
    #pragma unroll
    for (int o = 16; o > 0; o >>= 1) {
        s  += __shfl_xor_sync(0xffffffffu, s,  o);
        ss += __shfl_xor_sync(0xffffffffu, ss, o);
    }
    if ((tid & 31) == 0) { rs[tid >> 5] = s; rss[tid >> 5] = ss; }
    __syncthreads();
    float stot = 0.0f, sstot = 0.0f;
    #pragma unroll
    for (int i = 0; i < 8; i++) { stot += rs[i]; sstot += rss[i]; }
    float mean = stot * (1.0f / D_MODEL);
    float var  = sstot * (1.0f / D_MODEL) - mean * mean;
    float rstd = rsqrtf(var + LN_EPS);

    const float4* g4 = (const float4*)gamma;
    const float4* be4 = (const float4*)beta;
    float4 g = g4[tid], be = be4[tid];
    float4 o;
    o.x = (x0 - mean) * rstd * g.x + be.x;
    o.y = (x1 - mean) * rstd * g.y + be.y;
    o.z = (x2 - mean) * rstd * g.z + be.z;
    o.w = (x3 - mean) * rstd * g.w + be.w;
    ((float4*)(out + (size_t)t * D_MODEL))[tid] = o;
    if (ohi) {
        uint2 uh, ul;
        split4(o, uh, ul);
        ((uint2*)(ohi + (size_t)t * D_MODEL))[tid] = uh;
        ((uint2*)(olo + (size_t)t * D_MODEL))[tid] = ul;
    }
}

// ---------------- Launch ----------------
extern "C" void kernel_launch(void* const* d_in, const int* in_sizes, int n_in,
                              void* d_out, int out_size) {
    const float* src      = (const float*)d_in[0];
    const float* audio    = (const float*)d_in[1];
    const int*   beats    = (const int*)  d_in[2];
    const float* sa_in_w  = (const float*)d_in[3];
    const float* sa_in_b  = (const float*)d_in[4];
    const float* sa_out_w = (const float*)d_in[5];
    const float* sa_out_b = (const float*)d_in[6];
    const float* ca_in_w  = (const float*)d_in[7];
    const float* ca_in_b  = (const float*)d_in[8];
    const float* ca_out_w = (const float*)d_in[9];
    const float* ca_out_b = (const float*)d_in[10];
    const float* gate     = (const float*)d_in[11];
    const float* n1_g     = (const float*)d_in[12];
    const float* n1_b     = (const float*)d_in[13];
    const float* nc_g     = (const float*)d_in[14];
    const float* nc_b     = (const float*)d_in[15];
    const float* n2_g     = (const float*)d_in[16];
    const float* n2_b     = (const float*)d_in[17];
    const float* lin1_w   = (const float*)d_in[18];
    const float* lin1_b   = (const float*)d_in[19];
    const float* lin2_w   = (const float*)d_in[20];
    const float* lin2_b   = (const float*)d_in[21];
    float* out = (float*)d_out;

    float *tmp, *x1, *x2, *ff2, *bias;
    __nv_bfloat16 *Xhi, *Xlo, *AUhi, *AUlo, *Hhi, *Hlo, *Whi, *Wlo;
    __nv_bfloat16 *QKVhi, *QKVlo, *KVhi, *KVlo, *CQhi, *CQlo;
    cudaGetSymbolAddress((void**)&tmp,  g_tmp);
    cudaGetSymbolAddress((void**)&x1,   g_x1);
    cudaGetSymbolAddress((void**)&x2,   g_x2);
    cudaGetSymbolAddress((void**)&ff2,  g_ff2);
    cudaGetSymbolAddress((void**)&bias, g_bias);
    cudaGetSymbolAddress((void**)&Xhi,  g_Xhi);
    cudaGetSymbolAddress((void**)&Xlo,  g_Xlo);
    cudaGetSymbolAddress((void**)&AUhi, g_AUhi);
    cudaGetSymbolAddress((void**)&AUlo, g_AUlo);
    cudaGetSymbolAddress((void**)&Hhi,  g_Hhi);
    cudaGetSymbolAddress((void**)&Hlo,  g_Hlo);
    cudaGetSymbolAddress((void**)&Whi,  g_Whi);
    cudaGetSymbolAddress((void**)&Wlo,  g_Wlo);
    cudaGetSymbolAddress((void**)&QKVhi, g_QKVhi);
    cudaGetSymbolAddress((void**)&QKVlo, g_QKVlo);
    cudaGetSymbolAddress((void**)&KVhi,  g_KVhi);
    cudaGetSymbolAddress((void**)&KVlo,  g_KVlo);
    cudaGetSymbolAddress((void**)&CQhi,  g_CQhi);
    cudaGetSymbolAddress((void**)&CQlo,  g_CQlo);

    cudaFuncSetAttribute(gemm_mma, cudaFuncAttributeMaxDynamicSharedMemorySize, G_SMEM);
    cudaFuncSetAttribute(attn_mma, cudaFuncAttributeMaxDynamicSharedMemorySize, AT_SMEM);

    const int CVT_B = 256 * 4;
    #define CVT(srcp, hip, lop, n) cvt_kernel<<<(n) / CVT_B, 256>>>(srcp, hip, lop, n)
    #define GEMM(ahi, alo, bhi, blo, bp, cf, ohi, olo, Nn, Kk, act) \
        gemm_mma<<<dim3((Nn) / 128, NTOK / 128), 256, G_SMEM>>>(ahi, alo, bhi, blo, bp, cf, ohi, olo, Nn, Kk, act)
    #define BF16_NULL (__nv_bfloat16*)nullptr

    // 0-3) bias, weights, src + audio converts
    bias_kernel<<<TM, TA>>>(beats, bias);
    wcvt_kernel<<<W_TOTAL / CVT_B, 256>>>(sa_in_w, sa_out_w, ca_in_w, ca_out_w,
                                          lin1_w, lin2_w, Whi, Wlo);
    CVT(src, Xhi, Xlo, NTOK * D_MODEL);
    CVT(audio, AUhi, AUlo, NTOK * D_MODEL);

    // 4) SA packed QKV (split-bf16 output)
    GEMM(Xhi, Xlo, Whi + W_SAIN, Wlo + W_SAIN, sa_in_b, (float*)nullptr,
         QKVhi, QKVlo, 3 * D_MODEL, D_MODEL, 0);

    // 5) CA KV-proj (independent; fills QKV tail)  (ncu -s 5 lands here)
    GEMM(AUhi, AUlo, Whi + W_CAIN + (size_t)D_MODEL * D_MODEL, Wlo + W_CAIN + (size_t)D_MODEL * D_MODEL,
         ca_in_b + D_MODEL, (float*)nullptr, KVhi, KVlo, 2 * D_MODEL, D_MODEL, 0);

    // 6) SA attention
    attn_mma<<<dim3(TM / 64, BATCH * NHEAD), 128, AT_SMEM>>>(
        QKVhi, QKVlo, 3 * D_MODEL, 0,
        QKVhi, QKVlo, 3 * D_MODEL, D_MODEL,
        QKVhi, QKVlo, 3 * D_MODEL, 2 * D_MODEL,
        Xhi, Xlo, nullptr, 0.125f);

    // 7) SA out-proj
    GEMM(Xhi, Xlo, Whi + W_SAOUT, Wlo + W_SAOUT, sa_out_b, tmp,
         BF16_NULL, BF16_NULL, D_MODEL, D_MODEL, 0);

    // 8) x1 = LN1(src + sa), fused split
    add_ln_kernel<<<NTOK, 256>>>(src, tmp, nullptr, n1_g, n1_b, x1, Xhi, Xlo);

    // 9) CA Q-proj
    GEMM(Xhi, Xlo, Whi + W_CAIN, Wlo + W_CAIN, ca_in_b, (float*)nullptr,
         CQhi, CQlo, D_MODEL, D_MODEL, 0);

    // 10) CA attention (biased)
    attn_mma<<<dim3(TM / 64, BATCH * NHEAD), 128, AT_SMEM>>>(
        CQhi, CQlo, D_MODEL, 0,
        KVhi, KVlo, 2 * D_MODEL, 0,
        KVhi, KVlo, 2 * D_MODEL, D_MODEL,
        Xhi, Xlo, bias, 0.125f);

    // 11) CA out-proj
    GEMM(Xhi, Xlo, Whi + W_CAOUT, Wlo + W_CAOUT, ca_out_b, tmp,
         BF16_NULL, BF16_NULL, D_MODEL, D_MODEL, 0);

    // 12) x2 = LNc(x1 + tanh(gate)*cross), fused split
    add_ln_kernel<<<NTOK, 256>>>(x1, tmp, gate, nc_g, nc_b, x2, Xhi, Xlo);

    // 13-14) FFN
    GEMM(Xhi, Xlo, Whi + W_LIN1, Wlo + W_LIN1, lin1_b, (float*)nullptr, Hhi, Hlo,
         DFF, D_MODEL, 1);
    GEMM(Hhi, Hlo, Whi + W_LIN2, Wlo + W_LIN2, lin2_b, ff2,
         BF16_NULL, BF16_NULL, D_MODEL, DFF, 0);

    // 15) out = LN2(x2 + ff)
    add_ln_kernel<<<NTOK, 256>>>(x2, ff2, nullptr, n2_g, n2_b, out,
                                 BF16_NULL, BF16_NULL);
}

// round 10
// speedup vs baseline: 1.7814x; 1.4489x over previous
#include <cuda_runtime.h>
#include <cuda_fp16.h>
#include <math.h>
#include <stdint.h>

// ---------------- Problem constants ----------------
#define D_MODEL 1024
#define NHEAD   16
#define HDIM    64
#define DFF     4096
#define TM      512
#define TA      512
#define BATCH   32
#define NTOK    (TM * BATCH)   // 16384
#define NBEATS  64
#define LN_EPS  1e-5f

// ---------------- fp32 scratch ----------------
__device__ float g_tmp [NTOK * D_MODEL];
__device__ float g_x1  [NTOK * D_MODEL];
__device__ float g_x2  [NTOK * D_MODEL];
__device__ float g_ff2 [NTOK * D_MODEL];
__device__ float g_bias[TM * TA];

// ---------------- fp16 split scratch ----------------
__device__ __half g_Xhi [NTOK * D_MODEL];
__device__ __half g_Xlo [NTOK * D_MODEL];
__device__ __half g_AUhi[NTOK * D_MODEL];
__device__ __half g_AUlo[NTOK * D_MODEL];
__device__ __half g_Hhi [NTOK * DFF];
__device__ __half g_Hlo [NTOK * DFF];
__device__ __half g_QKVhi[NTOK * 3 * D_MODEL];
__device__ __half g_QKVlo[NTOK * 3 * D_MODEL];
__device__ __half g_KVhi[NTOK * 2 * D_MODEL];
__device__ __half g_CQhi[NTOK * D_MODEL];
__device__ __half g_CQlo[NTOK * D_MODEL];
__device__ __half g_Whi[16777216];   // weights: hi only (2-term scheme)

#define W_SAIN   0
#define W_SAOUT  3145728
#define W_CAIN   4194304
#define W_CAOUT  7340032
#define W_LIN1   8388608
#define W_LIN2  12582912
#define W_TOTAL 16777216

// ================= helpers (non-'a' PTX only) =================
__device__ __forceinline__ uint32_t smem_u32(const void* p) {
    uint32_t a;
    asm("{ .reg .u64 t; cvta.to.shared.u64 t, %1; cvt.u32.u64 %0, t; }" : "=r"(a) : "l"(p));
    return a;
}
__device__ __forceinline__ void cp_async16(uint32_t saddr, const void* g) {
    asm volatile("cp.async.cg.shared.global [%0], [%1], 16;" :: "r"(saddr), "l"(g));
}
__device__ __forceinline__ void cp_commit() {
    asm volatile("cp.async.commit_group;" ::: "memory");
}
__device__ __forceinline__ void ldsm_x4(uint32_t (&r)[4], uint32_t addr) {
    asm volatile("ldmatrix.sync.aligned.m8n8.x4.shared.b16 {%0,%1,%2,%3}, [%4];"
                 : "=r"(r[0]), "=r"(r[1]), "=r"(r[2]), "=r"(r[3]) : "r"(addr));
}
__device__ __forceinline__ void ldsm_x4_t(uint32_t (&r)[4], uint32_t addr) {
    asm volatile("ldmatrix.sync.aligned.m8n8.x4.trans.shared.b16 {%0,%1,%2,%3}, [%4];"
                 : "=r"(r[0]), "=r"(r[1]), "=r"(r[2]), "=r"(r[3]) : "r"(addr));
}
__device__ __forceinline__ void mma16816(float (&d)[4], const uint32_t (&a)[4],
                                         uint32_t b0, uint32_t b1) {
    asm volatile(
        "mma.sync.aligned.m16n8k16.row.col.f32.f16.f16.f32 "
        "{%0,%1,%2,%3}, {%4,%5,%6,%7}, {%8,%9}, {%0,%1,%2,%3};"
        : "+f"(d[0]), "+f"(d[1]), "+f"(d[2]), "+f"(d[3])
        : "r"(a[0]), "r"(a[1]), "r"(a[2]), "r"(a[3]), "r"(b0), "r"(b1));
}
__device__ __forceinline__ uint32_t pack_h2(float x, float y) {
    return (uint32_t)__half_as_ushort(__float2half_rn(x)) |
           ((uint32_t)__half_as_ushort(__float2half_rn(y)) << 16);
}
__device__ __forceinline__ void split4h(float4 v, uint2& uh, uint2& ul) {
    __half h0 = __float2half_rn(v.x), h1 = __float2half_rn(v.y);
    __half h2 = __float2half_rn(v.z), h3 = __float2half_rn(v.w);
    uh.x = (uint32_t)__half_as_ushort(h0) | ((uint32_t)__half_as_ushort(h1) << 16);
    uh.y = (uint32_t)__half_as_ushort(h2) | ((uint32_t)__half_as_ushort(h3) << 16);
    ul.x = pack_h2(v.x - __half2float(h0), v.y - __half2float(h1));
    ul.y = pack_h2(v.z - __half2float(h2), v.w - __half2float(h3));
}

// ================= converts =================
__global__ __launch_bounds__(256) void cvt_kernel(
    const float* __restrict__ src, __half* __restrict__ hi,
    __half* __restrict__ lo, int n)
{
    int i = (blockIdx.x * 256 + threadIdx.x) * 4;
    if (i >= n) return;
    uint2 uh, ul;
    split4h(*(const float4*)(src + i), uh, ul);
    *(uint2*)(hi + i) = uh;
    *(uint2*)(lo + i) = ul;
}

// weights: hi only
__global__ __launch_bounds__(256) void wcvt_kernel(
    const float* __restrict__ w0, const float* __restrict__ w1,
    const float* __restrict__ w2, const float* __restrict__ w3,
    const float* __restrict__ w4, const float* __restrict__ w5,
    __half* __restrict__ hi)
{
    int i = (blockIdx.x * 256 + threadIdx.x) * 4;
    const float* src; int off;
    if      (i < W_SAOUT) { src = w0; off = W_SAIN; }
    else if (i < W_CAIN)  { src = w1; off = W_SAOUT; }
    else if (i < W_CAOUT) { src = w2; off = W_CAIN; }
    else if (i < W_LIN1)  { src = w3; off = W_CAOUT; }
    else if (i < W_LIN2)  { src = w4; off = W_LIN1; }
    else                  { src = w5; off = W_LIN2; }
    float4 v = *(const float4*)(src + (i - off));
    uint2 uh;
    uh.x = pack_h2(v.x, v.y);
    uh.y = pack_h2(v.z, v.w);
    *(uint2*)(hi + i) = uh;
}

// ================= mma.sync GEMM (fp16, 2-term) =================
// C[M,N] = (Ahi+Alo)[M,K]*Bhi[N,K]^T + bias. CTA 128x128 (warp 32x64), BK=32,
// 4 stages x 24KB, 2 CTAs/SM. Term-major MMA issue.
// Stage: Ahi@0 (8K), Alo@8K, Bhi@16K (8K). Rows 64B; chunk c of row r at
// r*64 + ((c^((r>>1)&3))<<4).
#define G_STAGE 24576
#define G_SMEM  (4 * G_STAGE)

__global__ __launch_bounds__(256, 2) void gemm_mma(
    const __half* __restrict__ Ahi, const __half* __restrict__ Alo,
    const __half* __restrict__ Bhi,
    const float* __restrict__ bias, float* __restrict__ Cf,
    __half* __restrict__ Ohi, __half* __restrict__ Olo,
    int N, int K, int act)
{
    extern __shared__ __align__(128) char smem[];
    const uint32_t sbase = smem_u32(smem);
    const int tid = threadIdx.x;
    const int lane = tid & 31, wid = tid >> 5;
    const int warp_m = wid & 3, warp_n = wid >> 2;
    const int m0 = blockIdx.y * 128, n0 = blockIdx.x * 128;

    float acc[2][8][4];
    #pragma unroll
    for (int t = 0; t < 2; t++)
        #pragma unroll
        for (int j = 0; j < 8; j++)
            #pragma unroll
            for (int e = 0; e < 4; e++) acc[t][j][e] = 0.0f;

    int lr0 = tid >> 2,         lc0 = tid & 3;
    int lr1 = (tid + 256) >> 2, lc1 = tid & 3;
    uint32_t lsw0 = lr0 * 64 + ((lc0 ^ ((lr0 >> 1) & 3)) << 4);
    uint32_t lsw1 = lr1 * 64 + ((lc1 ^ ((lr1 >> 1) & 3)) << 4);

    auto stage_load = [&](int ci, int st) {
        const uint32_t sb = sbase + st * G_STAGE;
        const int kk = ci * 32;
        size_t goA0 = (size_t)(m0 + lr0) * K + kk + lc0 * 8;
        size_t goA1 = (size_t)(m0 + lr1) * K + kk + lc1 * 8;
        size_t goB0 = (size_t)(n0 + lr0) * K + kk + lc0 * 8;
        size_t goB1 = (size_t)(n0 + lr1) * K + kk + lc1 * 8;
        cp_async16(sb + lsw0,         Ahi + goA0);
        cp_async16(sb + 8192 + lsw0,  Alo + goA0);
        cp_async16(sb + 16384 + lsw0, Bhi + goB0);
        cp_async16(sb + lsw1,         Ahi + goA1);
        cp_async16(sb + 8192 + lsw1,  Alo + goA1);
        cp_async16(sb + 16384 + lsw1, Bhi + goB1);
        cp_commit();
    };

    const int lr = lane & 15;
    const int lseg = lane >> 4;
    int arow[2], brow[4];
    #pragma unroll
    for (int t = 0; t < 2; t++) arow[t] = warp_m * 32 + t * 16 + lr;
    #pragma unroll
    for (int u = 0; u < 4; u++) brow[u] = warp_n * 64 + u * 16 + lr;

    const int nch = K >> 5;
    stage_load(0, 0);
    stage_load(1, 1);
    stage_load(2, 2);

    for (int i = 0; i < nch; i++) {
        if (i <= nch - 3)      asm volatile("cp.async.wait_group 2;" ::: "memory");
        else if (i == nch - 2) asm volatile("cp.async.wait_group 1;" ::: "memory");
        else                   asm volatile("cp.async.wait_group 0;" ::: "memory");
        __syncthreads();
        if (i + 3 < nch) stage_load(i + 3, (i + 3) & 3);

        const uint32_t sb = sbase + (i & 3) * G_STAGE;
        #pragma unroll
        for (int s = 0; s < 2; s++) {
            const int chunk = 2 * s + lseg;
            uint32_t ah[2][4], al[2][4], bh[4][4];
            #pragma unroll
            for (int t = 0; t < 2; t++) {
                uint32_t a = sb + arow[t] * 64 + ((chunk ^ ((arow[t] >> 1) & 3)) << 4);
                ldsm_x4(ah[t], a);
                ldsm_x4(al[t], a + 8192);
            }
            #pragma unroll
            for (int u = 0; u < 4; u++) {
                uint32_t a = sb + 16384 + brow[u] * 64 + ((chunk ^ ((brow[u] >> 1) & 3)) << 4);
                ldsm_x4(bh[u], a);
            }
            #pragma unroll
            for (int t = 0; t < 2; t++)
                #pragma unroll
                for (int u = 0; u < 4; u++) {
                    mma16816(acc[t][2 * u],     ah[t], bh[u][0], bh[u][2]);
                    mma16816(acc[t][2 * u + 1], ah[t], bh[u][1], bh[u][3]);
                }
            #pragma unroll
            for (int t = 0; t < 2; t++)
                #pragma unroll
                for (int u = 0; u < 4; u++) {
                    mma16816(acc[t][2 * u],     al[t], bh[u][0], bh[u][2]);
                    mma16816(acc[t][2 * u + 1], al[t], bh[u][1], bh[u][3]);
                }
        }
    }

    #pragma unroll
    for (int t = 0; t < 2; t++) {
        const int rbase = m0 + warp_m * 32 + t * 16 + (lane >> 2);
        #pragma unroll
        for (int j = 0; j < 8; j++) {
            const int col = n0 + warp_n * 64 + j * 8 + 2 * (lane & 3);
            const float b0 = __ldg(bias + col), b1 = __ldg(bias + col + 1);
            #pragma unroll
            for (int half = 0; half < 2; half++) {
                const int row = rbase + 8 * half;
                float v0 = acc[t][j][2 * half]     + b0;
                float v1 = acc[t][j][2 * half + 1] + b1;
                if (act) {
                    v0 = 0.5f * v0 * (1.0f + erff(v0 * 0.70710678118654752f));
                    v1 = 0.5f * v1 * (1.0f + erff(v1 * 0.70710678118654752f));
                }
                const size_t off = (size_t)row * N + col;
                if (Cf) {
                    *(float2*)(Cf + off) = make_float2(v0, v1);
                } else {
                    __half h0 = __float2half_rn(v0);
                    __half h1 = __float2half_rn(v1);
                    *(uint32_t*)(Ohi + off) =
                        (uint32_t)__half_as_ushort(h0) | ((uint32_t)__half_as_ushort(h1) << 16);
                    if (Olo)
                        *(uint32_t*)(Olo + off) =
                            pack_h2(v0 - __half2float(h0), v1 - __half2float(h1));
                }
            }
        }
    }
}

// ================= FA2-style attention (fp16, 2-term) =================
// Buffers: Khi@0 (8K), Vhi@8K per 64-key tile; 3 stages x 16KB.
// Q (hi+lo) staged once into buffer 0 area then held in registers.
#define AT_BUF  16384
#define AT_SMEM (3 * AT_BUF)

__global__ __launch_bounds__(128) void attn_mma(
    const __half* __restrict__ Qhi, const __half* __restrict__ Qlo, int ldq, int qoff,
    const __half* __restrict__ Khi, int ldk, int koff,
    const __half* __restrict__ Vhi, int ldv, int voff,
    __half* __restrict__ Ohi, __half* __restrict__ Olo,
    const float* __restrict__ bias, float scale)
{
    extern __shared__ __align__(128) char smem[];
    const uint32_t sbase = smem_u32(smem);
    const int tid = threadIdx.x, lane = tid & 31, w = tid >> 5;
    const int qt = blockIdx.x, bh = blockIdx.y;
    const int b = bh & (BATCH - 1), h = bh >> 5;

    #pragma unroll
    for (int it = 0; it < 4; it++) {
        int idx = tid + it * 128, r = idx >> 3, c = idx & 7;
        uint32_t sw = r * 128 + ((c ^ (r & 7)) << 4);
        size_t g = (size_t)((qt * 64 + r) * BATCH + b) * ldq + qoff + h * HDIM + c * 8;
        cp_async16(sbase + sw,        Qhi + g);
        cp_async16(sbase + 8192 + sw, Qlo + g);
    }
    cp_commit();
    asm volatile("cp.async.wait_group 0;" ::: "memory");
    __syncthreads();

    const int lr = lane & 15, ls = lane >> 4;
    uint32_t qh[4][4], ql[4][4];
    {
        int qrow = w * 16 + lr;
        #pragma unroll
        for (int kc = 0; kc < 4; kc++) {
            int chunk = 2 * kc + ls;
            uint32_t a = sbase + qrow * 128 + ((chunk ^ (qrow & 7)) << 4);
            ldsm_x4(qh[kc], a);
            ldsm_x4(ql[kc], a + 8192);
        }
    }
    __syncthreads();

    auto load_kt = [&](int kt, int st) {
        uint32_t sb = sbase + st * AT_BUF;
        #pragma unroll
        for (int it = 0; it < 4; it++) {
            int idx = tid + it * 128, r = idx >> 3, c = idx & 7;
            uint32_t sw = r * 128 + ((c ^ (r & 7)) << 4);
            size_t rowi = (size_t)((kt * 64 + r) * BATCH + b);
            cp_async16(sb + sw,        Khi + rowi * ldk + koff + h * HDIM + c * 8);
            cp_async16(sb + 8192 + sw, Vhi + rowi * ldv + voff + h * HDIM + c * 8);
        }
        cp_commit();
    };
    load_kt(0, 0);
    load_kt(1, 1);

    float o[8][4];
    #pragma unroll
    for (int t = 0; t < 8; t++)
        #pragma unroll
        for (int e = 0; e < 4; e++) o[t][e] = 0.0f;
    float mrow0 = -1e30f, mrow1 = -1e30f, lsum0 = 0.0f, lsum1 = 0.0f;

    const int vkbase = ((lane & 16) ? 8 : 0) + (lane & 7);
    const int vcsel  = (lane >> 3) & 1;

    for (int kt = 0; kt < 8; kt++) {
        if (kt < 7) asm volatile("cp.async.wait_group 1;" ::: "memory");
        else        asm volatile("cp.async.wait_group 0;" ::: "memory");
        __syncthreads();
        if (kt + 2 < 8) load_kt(kt + 2, (kt + 2) % 3);
        const uint32_t sb = sbase + (kt % 3) * AT_BUF;

        float s[8][4];
        #pragma unroll
        for (int t = 0; t < 8; t++)
            #pragma unroll
            for (int e = 0; e < 4; e++) s[t][e] = 0.0f;
        #pragma unroll
        for (int kc = 0; kc < 4; kc++) {
            uint32_t kh[4][4];
            #pragma unroll
            for (int u = 0; u < 4; u++) {
                int krow = u * 16 + lr, chunk = 2 * kc + ls;
                uint32_t a = sb + krow * 128 + ((chunk ^ (krow & 7)) << 4);
                ldsm_x4(kh[u], a);
            }
            #pragma unroll
            for (int u = 0; u < 4; u++) {
                mma16816(s[2 * u],     qh[kc], kh[u][0], kh[u][2]);
                mma16816(s[2 * u + 1], qh[kc], kh[u][1], kh[u][3]);
            }
            #pragma unroll
            for (int u = 0; u < 4; u++) {
                mma16816(s[2 * u],     ql[kc], kh[u][0], kh[u][2]);
                mma16816(s[2 * u + 1], ql[kc], kh[u][1], kh[u][3]);
            }
        }

        const int row0 = qt * 64 + w * 16 + (lane >> 2);
        if (bias) {
            #pragma unroll
            for (int t = 0; t < 8; t++) {
                int col = kt * 64 + t * 8 + 2 * (lane & 3);
                float2 b0 = *(const float2*)(bias + (size_t)row0 * TA + col);
                float2 b1 = *(const float2*)(bias + (size_t)(row0 + 8) * TA + col);
                s[t][0] = s[t][0] * scale + b0.x; s[t][1] = s[t][1] * scale + b0.y;
                s[t][2] = s[t][2] * scale + b1.x; s[t][3] = s[t][3] * scale + b1.y;
            }
        } else {
            #pragma unroll
            for (int t = 0; t < 8; t++)
                #pragma unroll
                for (int e = 0; e < 4; e++) s[t][e] *= scale;
        }

        float mx0 = -1e30f, mx1 = -1e30f;
        #pragma unroll
        for (int t = 0; t < 8; t++) {
            mx0 = fmaxf(mx0, fmaxf(s[t][0], s[t][1]));
            mx1 = fmaxf(mx1, fmaxf(s[t][2], s[t][3]));
        }
        mx0 = fmaxf(mx0, __shfl_xor_sync(0xffffffffu, mx0, 1));
        mx0 = fmaxf(mx0, __shfl_xor_sync(0xffffffffu, mx0, 2));
        mx1 = fmaxf(mx1, __shfl_xor_sync(0xffffffffu, mx1, 1));
        mx1 = fmaxf(mx1, __shfl_xor_sync(0xffffffffu, mx1, 2));
        float mn0 = fmaxf(mrow0, mx0), mn1 = fmaxf(mrow1, mx1);
        float a0 = __expf(mrow0 - mn0), a1 = __expf(mrow1 - mn1);
        mrow0 = mn0; mrow1 = mn1;

        float sum0 = 0.0f, sum1 = 0.0f;
        uint32_t phi[4][4], plo[4][4];
        #pragma unroll
        for (int t = 0; t < 8; t++) {
            float p0 = __expf(s[t][0] - mn0), p1 = __expf(s[t][1] - mn0);
            float p2 = __expf(s[t][2] - mn1), p3 = __expf(s[t][3] - mn1);
            sum0 += p0 + p1; sum1 += p2 + p3;
            __half h0 = __float2half_rn(p0), h1 = __float2half_rn(p1);
            __half h2 = __float2half_rn(p2), h3 = __float2half_rn(p3);
            const int kc = t >> 1, j = (t & 1) * 2;
            phi[kc][j]     = (uint32_t)__half_as_ushort(h0) | ((uint32_t)__half_as_ushort(h1) << 16);
            phi[kc][j + 1] = (uint32_t)__half_as_ushort(h2) | ((uint32_t)__half_as_ushort(h3) << 16);
            plo[kc][j]     = pack_h2(p0 - __half2float(h0), p1 - __half2float(h1));
            plo[kc][j + 1] = pack_h2(p2 - __half2float(h2), p3 - __half2float(h3));
        }
        sum0 += __shfl_xor_sync(0xffffffffu, sum0, 1);
        sum0 += __shfl_xor_sync(0xffffffffu, sum0, 2);
        sum1 += __shfl_xor_sync(0xffffffffu, sum1, 1);
        sum1 += __shfl_xor_sync(0xffffffffu, sum1, 2);
        lsum0 = lsum0 * a0 + sum0;
        lsum1 = lsum1 * a1 + sum1;
        #pragma unroll
        for (int t = 0; t < 8; t++) {
            o[t][0] *= a0; o[t][1] *= a0;
            o[t][2] *= a1; o[t][3] *= a1;
        }

        #pragma unroll
        for (int kc = 0; kc < 4; kc++) {
            int vkey = kc * 16 + vkbase;
            uint32_t vh[4][4];
            #pragma unroll
            for (int du = 0; du < 4; du++) {
                int chunk = 2 * du + vcsel;
                uint32_t a = sb + 8192 + vkey * 128 + ((chunk ^ (vkey & 7)) << 4);
                ldsm_x4_t(vh[du], a);
            }
            #pragma unroll
            for (int du = 0; du < 4; du++) {
                mma16816(o[2 * du],     phi[kc], vh[du][0], vh[du][2]);
                mma16816(o[2 * du + 1], phi[kc], vh[du][1], vh[du][3]);
            }
            #pragma unroll
            for (int du = 0; du < 4; du++) {
                mma16816(o[2 * du],     plo[kc], vh[du][0], vh[du][2]);
                mma16816(o[2 * du + 1], plo[kc], vh[du][1], vh[du][3]);
            }
        }
    }

    float inv0 = 1.0f / lsum0, inv1 = 1.0f / lsum1;
    const int row0 = qt * 64 + w * 16 + (lane >> 2);
    #pragma unroll
    for (int t = 0; t < 8; t++) {
        int col = t * 8 + 2 * (lane & 3);
        float v0 = o[t][0] * inv0, v1 = o[t][1] * inv0;
        float v2 = o[t][2] * inv1, v3 = o[t][3] * inv1;
        size_t off0 = (size_t)(row0 * BATCH + b) * D_MODEL + h * HDIM + col;
        size_t off1 = (size_t)((row0 + 8) * BATCH + b) * D_MODEL + h * HDIM + col;
        __half h0 = __float2half_rn(v0), h1 = __float2half_rn(v1);
        __half h2 = __float2half_rn(v2), h3 = __float2half_rn(v3);
        *(uint32_t*)(Ohi + off0) = (uint32_t)__half_as_ushort(h0) | ((uint32_t)__half_as_ushort(h1) << 16);
        *(uint32_t*)(Olo + off0) = pack_h2(v0 - __half2float(h0), v1 - __half2float(h1));
        *(uint32_t*)(Ohi + off1) = (uint32_t)__half_as_ushort(h2) | ((uint32_t)__half_as_ushort(h3) << 16);
        *(uint32_t*)(Olo + off1) = pack_h2(v2 - __half2float(h2), v3 - __half2float(h3));
    }
}

// ---------------- Bias precompute ----------------
__global__ void bias_kernel(const int* __restrict__ beats, float* __restrict__ out) {
    __shared__ int sb[NBEATS];
    int i = blockIdx.x;
    int j = threadIdx.x;
    if (threadIdx.x < NBEATS) sb[threadIdx.x] = beats[threadIdx.x];
    __syncthreads();
    float bb = 0.0f;
    #pragma unroll 8
    for (int n = 0; n < NBEATS; n++) {
        int bf = sb[n];
        if (j == bf) bb = fmaxf(bb, 2.0f);
        if (bf > 0      && j == bf - 1) bb = fmaxf(bb, 1.0f);
        if (bf < TA - 1 && j == bf + 1) bb = fmaxf(bb, 1.0f);
    }
    float scale = (float)(TA - 1) / (float)(TM - 1);
    float d = (float)i * scale - (float)j;
    out[i * TA + j] = -(d * d) * (1.0f / 32.0f) + bb;
}

// ---------------- Fused residual + LayerNorm (+ optional fp16 split out) ----------------
__global__ __launch_bounds__(256) void add_ln_kernel(
    const float* __restrict__ A, const float* __restrict__ Bv,
    const float* __restrict__ gatePtr,
    const float* __restrict__ gamma, const float* __restrict__ beta,
    float* __restrict__ out,
    __half* __restrict__ ohi, __half* __restrict__ olo)
{
    int t = blockIdx.x;
    int tid = threadIdx.x;
    float gscale = gatePtr ? tanhf(*gatePtr) : 1.0f;
    const float4* a4 = (const float4*)(A  + (size_t)t * D_MODEL);
    const float4* b4 = (const float4*)(Bv + (size_t)t * D_MODEL);
    float4 av = a4[tid], bv = b4[tid];
    float x0 = av.x + gscale * bv.x;
    float x1 = av.y + gscale * bv.y;
    float x2 = av.z + gscale * bv.z;
    float x3 = av.w + gscale * bv.w;
    float s  = x0 + x1 + x2 + x3;
    float ss = x0 * x0 + x1 * x1 + x2 * x2 + x3 * x3;

    __shared__ float rs[8], rss[8];
    #pragma unroll
    for (int o = 16; o > 0; o >>= 1) {
        s  += __shfl_xor_sync(0xffffffffu, s,  o);
        ss += __shfl_xor_sync(0xffffffffu, ss, o);
    }
    if ((tid & 31) == 0) { rs[tid >> 5] = s; rss[tid >> 5] = ss; }
    __syncthreads();
    float stot = 0.0f, sstot = 0.0f;
    #pragma unroll
    for (int i = 0; i < 8; i++) { stot += rs[i]; sstot += rss[i]; }
    float mean = stot * (1.0f / D_MODEL);
    float var  = sstot * (1.0f / D_MODEL) - mean * mean;
    float rstd = rsqrtf(var + LN_EPS);

    const float4* g4 = (const float4*)gamma;
    const float4* be4 = (const float4*)beta;
    float4 g = g4[tid], be = be4[tid];
    float4 o;
    o.x = (x0 - mean) * rstd * g.x + be.x;
    o.y = (x1 - mean) * rstd * g.y + be.y;
    o.z = (x2 - mean) * rstd * g.z + be.z;
    o.w = (x3 - mean) * rstd * g.w + be.w;
    ((float4*)(out + (size_t)t * D_MODEL))[tid] = o;
    if (ohi) {
        uint2 uh, ul;
        split4h(o, uh, ul);
        ((uint2*)(ohi + (size_t)t * D_MODEL))[tid] = uh;
        ((uint2*)(olo + (size_t)t * D_MODEL))[tid] = ul;
    }
}

// ---------------- Launch ----------------
extern "C" void kernel_launch(void* const* d_in, const int* in_sizes, int n_in,
                              void* d_out, int out_size) {
    const float* src      = (const float*)d_in[0];
    const float* audio    = (const float*)d_in[1];
    const int*   beats    = (const int*)  d_in[2];
    const float* sa_in_w  = (const float*)d_in[3];
    const float* sa_in_b  = (const float*)d_in[4];
    const float* sa_out_w = (const float*)d_in[5];
    const float* sa_out_b = (const float*)d_in[6];
    const float* ca_in_w  = (const float*)d_in[7];
    const float* ca_in_b  = (const float*)d_in[8];
    const float* ca_out_w = (const float*)d_in[9];
    const float* ca_out_b = (const float*)d_in[10];
    const float* gate     = (const float*)d_in[11];
    const float* n1_g     = (const float*)d_in[12];
    const float* n1_b     = (const float*)d_in[13];
    const float* nc_g     = (const float*)d_in[14];
    const float* nc_b     = (const float*)d_in[15];
    const float* n2_g     = (const float*)d_in[16];
    const float* n2_b     = (const float*)d_in[17];
    const float* lin1_w   = (const float*)d_in[18];
    const float* lin1_b   = (const float*)d_in[19];
    const float* lin2_w   = (const float*)d_in[20];
    const float* lin2_b   = (const float*)d_in[21];
    float* out = (float*)d_out;

    float *tmp, *x1, *x2, *ff2, *bias;
    __half *Xhi, *Xlo, *AUhi, *AUlo, *Hhi, *Hlo, *Whi;
    __half *QKVhi, *QKVlo, *KVhi, *CQhi, *CQlo;
    cudaGetSymbolAddress((void**)&tmp,  g_tmp);
    cudaGetSymbolAddress((void**)&x1,   g_x1);
    cudaGetSymbolAddress((void**)&x2,   g_x2);
    cudaGetSymbolAddress((void**)&ff2,  g_ff2);
    cudaGetSymbolAddress((void**)&bias, g_bias);
    cudaGetSymbolAddress((void**)&Xhi,  g_Xhi);
    cudaGetSymbolAddress((void**)&Xlo,  g_Xlo);
    cudaGetSymbolAddress((void**)&AUhi, g_AUhi);
    cudaGetSymbolAddress((void**)&AUlo, g_AUlo);
    cudaGetSymbolAddress((void**)&Hhi,  g_Hhi);
    cudaGetSymbolAddress((void**)&Hlo,  g_Hlo);
    cudaGetSymbolAddress((void**)&Whi,  g_Whi);
    cudaGetSymbolAddress((void**)&QKVhi, g_QKVhi);
    cudaGetSymbolAddress((void**)&QKVlo, g_QKVlo);
    cudaGetSymbolAddress((void**)&KVhi,  g_KVhi);
    cudaGetSymbolAddress((void**)&CQhi,  g_CQhi);
    cudaGetSymbolAddress((void**)&CQlo,  g_CQlo);

    cudaFuncSetAttribute(gemm_mma, cudaFuncAttributeMaxDynamicSharedMemorySize, G_SMEM);
    cudaFuncSetAttribute(attn_mma, cudaFuncAttributeMaxDynamicSharedMemorySize, AT_SMEM);

    const int CVT_B = 256 * 4;
    #define CVT(srcp, hip, lop, n) cvt_kernel<<<(n) / CVT_B, 256>>>(srcp, hip, lop, n)
    #define GEMM(ahi, alo, bhi, bp, cf, ohi, olo, Nn, Kk, act) \
        gemm_mma<<<dim3((Nn) / 128, NTOK / 128), 256, G_SMEM>>>(ahi, alo, bhi, bp, cf, ohi, olo, Nn, Kk, act)
    #define H_NULL (__half*)nullptr

    // 0-3) bias, weights (hi only), src + audio converts
    bias_kernel<<<TM, TA>>>(beats, bias);
    wcvt_kernel<<<W_TOTAL / CVT_B, 256>>>(sa_in_w, sa_out_w, ca_in_w, ca_out_w,
                                          lin1_w, lin2_w, Whi);
    CVT(src, Xhi, Xlo, NTOK * D_MODEL);
    CVT(audio, AUhi, AUlo, NTOK * D_MODEL);

    // 4) SA packed QKV (fp16 split output)
    GEMM(Xhi, Xlo, Whi + W_SAIN, sa_in_b, (float*)nullptr,
         QKVhi, QKVlo, 3 * D_MODEL, D_MODEL, 0);

    // 5) CA KV-proj (hi only — attention consumes K/V as hi)
    GEMM(AUhi, AUlo, Whi + W_CAIN + (size_t)D_MODEL * D_MODEL,
         ca_in_b + D_MODEL, (float*)nullptr, KVhi, H_NULL, 2 * D_MODEL, D_MODEL, 0);

    // 6) SA attention
    attn_mma<<<dim3(TM / 64, BATCH * NHEAD), 128, AT_SMEM>>>(
        QKVhi, QKVlo, 3 * D_MODEL, 0,
        QKVhi, 3 * D_MODEL, D_MODEL,
        QKVhi, 3 * D_MODEL, 2 * D_MODEL,
        Xhi, Xlo, nullptr, 0.125f);

    // 7) SA out-proj
    GEMM(Xhi, Xlo, Whi + W_SAOUT, sa_out_b, tmp, H_NULL, H_NULL, D_MODEL, D_MODEL, 0);

    // 8) x1 = LN1(src + sa), fused split
    add_ln_kernel<<<NTOK, 256>>>(src, tmp, nullptr, n1_g, n1_b, x1, Xhi, Xlo);

    // 9) CA Q-proj
    GEMM(Xhi, Xlo, Whi + W_CAIN, ca_in_b, (float*)nullptr, CQhi, CQlo, D_MODEL, D_MODEL, 0);

    // 10) CA attention (biased)
    attn_mma<<<dim3(TM / 64, BATCH * NHEAD), 128, AT_SMEM>>>(
        CQhi, CQlo, D_MODEL, 0,
        KVhi, 2 * D_MODEL, 0,
        KVhi, 2 * D_MODEL, D_MODEL,
        Xhi, Xlo, bias, 0.125f);

    // 11) CA out-proj
    GEMM(Xhi, Xlo, Whi + W_CAOUT, ca_out_b, tmp, H_NULL, H_NULL, D_MODEL, D_MODEL, 0);

    // 12) x2 = LNc(x1 + tanh(gate)*cross), fused split
    add_ln_kernel<<<NTOK, 256>>>(x1, tmp, gate, nc_g, nc_b, x2, Xhi, Xlo);

    // 13-14) FFN
    GEMM(Xhi, Xlo, Whi + W_LIN1, lin1_b, (float*)nullptr, Hhi, Hlo, DFF, D_MODEL, 1);
    GEMM(Hhi, Hlo, Whi + W_LIN2, lin2_b, ff2, H_NULL, H_NULL, D_MODEL, DFF, 0);

    // 15) out = LN2(x2 + ff)
    add_ln_kernel<<<NTOK, 256>>>(x2, ff2, nullptr, n2_g, n2_b, out, H_NULL, H_NULL);
}

// round 11
// speedup vs baseline: 2.9859x; 1.6762x over previous
#include <cuda_runtime.h>
#include <cuda_fp16.h>
#include <math.h>
#include <stdint.h>

// ---------------- Problem constants ----------------
#define D_MODEL 1024
#define NHEAD   16
#define HDIM    64
#define DFF     4096
#define TM      512
#define TA      512
#define BATCH   32
#define NTOK    (TM * BATCH)   // 16384
#define NBEATS  64
#define LN_EPS  1e-5f

// ---------------- fp32 scratch ----------------
__device__ float g_tmp [NTOK * D_MODEL];
__device__ float g_x1  [NTOK * D_MODEL];
__device__ float g_x2  [NTOK * D_MODEL];
__device__ float g_ff2 [NTOK * D_MODEL];
__device__ float g_bias[TM * TA];

// ---------------- fp16 scratch (1-term: hi only) ----------------
__device__ __half g_X  [NTOK * D_MODEL];
__device__ __half g_AU [NTOK * D_MODEL];
__device__ __half g_H  [NTOK * DFF];
__device__ __half g_QKV[NTOK * 3 * D_MODEL];
__device__ __half g_KV [NTOK * 2 * D_MODEL];
__device__ __half g_CQ [NTOK * D_MODEL];
__device__ __half g_W  [16777216];

#define W_SAIN   0
#define W_SAOUT  3145728
#define W_CAIN   4194304
#define W_CAOUT  7340032
#define W_LIN1   8388608
#define W_LIN2  12582912
#define W_TOTAL 16777216

// ================= helpers (non-'a' PTX only) =================
__device__ __forceinline__ uint32_t smem_u32(const void* p) {
    uint32_t a;
    asm("{ .reg .u64 t; cvta.to.shared.u64 t, %1; cvt.u32.u64 %0, t; }" : "=r"(a) : "l"(p));
    return a;
}
__device__ __forceinline__ void cp_async16(uint32_t saddr, const void* g) {
    asm volatile("cp.async.cg.shared.global [%0], [%1], 16;" :: "r"(saddr), "l"(g));
}
__device__ __forceinline__ void cp_commit() {
    asm volatile("cp.async.commit_group;" ::: "memory");
}
__device__ __forceinline__ void ldsm_x4(uint32_t (&r)[4], uint32_t addr) {
    asm volatile("ldmatrix.sync.aligned.m8n8.x4.shared.b16 {%0,%1,%2,%3}, [%4];"
                 : "=r"(r[0]), "=r"(r[1]), "=r"(r[2]), "=r"(r[3]) : "r"(addr));
}
__device__ __forceinline__ void ldsm_x4_t(uint32_t (&r)[4], uint32_t addr) {
    asm volatile("ldmatrix.sync.aligned.m8n8.x4.trans.shared.b16 {%0,%1,%2,%3}, [%4];"
                 : "=r"(r[0]), "=r"(r[1]), "=r"(r[2]), "=r"(r[3]) : "r"(addr));
}
__device__ __forceinline__ void mma16816(float (&d)[4], const uint32_t (&a)[4],
                                         uint32_t b0, uint32_t b1) {
    asm volatile(
        "mma.sync.aligned.m16n8k16.row.col.f32.f16.f16.f32 "
        "{%0,%1,%2,%3}, {%4,%5,%6,%7}, {%8,%9}, {%0,%1,%2,%3};"
        : "+f"(d[0]), "+f"(d[1]), "+f"(d[2]), "+f"(d[3])
        : "r"(a[0]), "r"(a[1]), "r"(a[2]), "r"(a[3]), "r"(b0), "r"(b1));
}
__device__ __forceinline__ uint32_t pack_h2(float x, float y) {
    return (uint32_t)__half_as_ushort(__float2half_rn(x)) |
           ((uint32_t)__half_as_ushort(__float2half_rn(y)) << 16);
}

// ================= converts (hi only) =================
__global__ __launch_bounds__(256) void cvt_kernel(
    const float* __restrict__ src, __half* __restrict__ hi, int n)
{
    int i = (blockIdx.x * 256 + threadIdx.x) * 4;
    if (i >= n) return;
    float4 v = *(const float4*)(src + i);
    uint2 uh;
    uh.x = pack_h2(v.x, v.y);
    uh.y = pack_h2(v.z, v.w);
    *(uint2*)(hi + i) = uh;
}

__global__ __launch_bounds__(256) void wcvt_kernel(
    const float* __restrict__ w0, const float* __restrict__ w1,
    const float* __restrict__ w2, const float* __restrict__ w3,
    const float* __restrict__ w4, const float* __restrict__ w5,
    __half* __restrict__ hi)
{
    int i = (blockIdx.x * 256 + threadIdx.x) * 4;
    const float* src; int off;
    if      (i < W_SAOUT) { src = w0; off = W_SAIN; }
    else if (i < W_CAIN)  { src = w1; off = W_SAOUT; }
    else if (i < W_CAOUT) { src = w2; off = W_CAIN; }
    else if (i < W_LIN1)  { src = w3; off = W_CAOUT; }
    else if (i < W_LIN2)  { src = w4; off = W_LIN1; }
    else                  { src = w5; off = W_LIN2; }
    float4 v = *(const float4*)(src + (i - off));
    uint2 uh;
    uh.x = pack_h2(v.x, v.y);
    uh.y = pack_h2(v.z, v.w);
    *(uint2*)(hi + i) = uh;
}

// ================= mma.sync GEMM (fp16, 1-term) =================
// C[M,N] = A[M,K]*B[N,K]^T + bias. CTA 128x128 (warp 32x64), BK=32,
// 4 stages x 16KB, 2 CTAs/SM.
// Stage: A@0 (8K), B@8K (8K). Rows 64B; chunk c of row r at
// r*64 + ((c^((r>>1)&3))<<4).
#define G_STAGE 16384
#define G_SMEM  (4 * G_STAGE)

__global__ __launch_bounds__(256, 2) void gemm_mma(
    const __half* __restrict__ A, const __half* __restrict__ B,
    const float* __restrict__ bias, float* __restrict__ Cf,
    __half* __restrict__ Oh,
    int N, int K, int act)
{
    extern __shared__ __align__(128) char smem[];
    const uint32_t sbase = smem_u32(smem);
    const int tid = threadIdx.x;
    const int lane = tid & 31, wid = tid >> 5;
    const int warp_m = wid & 3, warp_n = wid >> 2;
    const int m0 = blockIdx.y * 128, n0 = blockIdx.x * 128;

    float acc[2][8][4];
    #pragma unroll
    for (int t = 0; t < 2; t++)
        #pragma unroll
        for (int j = 0; j < 8; j++)
            #pragma unroll
            for (int e = 0; e < 4; e++) acc[t][j][e] = 0.0f;

    int lr0 = tid >> 2,         lc0 = tid & 3;
    int lr1 = (tid + 256) >> 2, lc1 = tid & 3;
    uint32_t lsw0 = lr0 * 64 + ((lc0 ^ ((lr0 >> 1) & 3)) << 4);
    uint32_t lsw1 = lr1 * 64 + ((lc1 ^ ((lr1 >> 1) & 3)) << 4);

    auto stage_load = [&](int ci, int st) {
        const uint32_t sb = sbase + st * G_STAGE;
        const int kk = ci * 32;
        size_t goA0 = (size_t)(m0 + lr0) * K + kk + lc0 * 8;
        size_t goA1 = (size_t)(m0 + lr1) * K + kk + lc1 * 8;
        size_t goB0 = (size_t)(n0 + lr0) * K + kk + lc0 * 8;
        size_t goB1 = (size_t)(n0 + lr1) * K + kk + lc1 * 8;
        cp_async16(sb + lsw0,        A + goA0);
        cp_async16(sb + lsw1,        A + goA1);
        cp_async16(sb + 8192 + lsw0, B + goB0);
        cp_async16(sb + 8192 + lsw1, B + goB1);
        cp_commit();
    };

    const int lr = lane & 15;
    const int lseg = lane >> 4;
    int arow[2], brow[4];
    #pragma unroll
    for (int t = 0; t < 2; t++) arow[t] = warp_m * 32 + t * 16 + lr;
    #pragma unroll
    for (int u = 0; u < 4; u++) brow[u] = warp_n * 64 + u * 16 + lr;

    const int nch = K >> 5;
    stage_load(0, 0);
    stage_load(1, 1);
    stage_load(2, 2);

    for (int i = 0; i < nch; i++) {
        if (i <= nch - 3)      asm volatile("cp.async.wait_group 2;" ::: "memory");
        else if (i == nch - 2) asm volatile("cp.async.wait_group 1;" ::: "memory");
        else                   asm volatile("cp.async.wait_group 0;" ::: "memory");
        __syncthreads();
        if (i + 3 < nch) stage_load(i + 3, (i + 3) & 3);

        const uint32_t sb = sbase + (i & 3) * G_STAGE;
        #pragma unroll
        for (int s = 0; s < 2; s++) {
            const int chunk = 2 * s + lseg;
            uint32_t ah[2][4], bh[4][4];
            #pragma unroll
            for (int t = 0; t < 2; t++) {
                uint32_t a = sb + arow[t] * 64 + ((chunk ^ ((arow[t] >> 1) & 3)) << 4);
                ldsm_x4(ah[t], a);
            }
            #pragma unroll
            for (int u = 0; u < 4; u++) {
                uint32_t a = sb + 8192 + brow[u] * 64 + ((chunk ^ ((brow[u] >> 1) & 3)) << 4);
                ldsm_x4(bh[u], a);
            }
            #pragma unroll
            for (int t = 0; t < 2; t++)
                #pragma unroll
                for (int u = 0; u < 4; u++) {
                    mma16816(acc[t][2 * u],     ah[t], bh[u][0], bh[u][2]);
                    mma16816(acc[t][2 * u + 1], ah[t], bh[u][1], bh[u][3]);
                }
        }
    }

    #pragma unroll
    for (int t = 0; t < 2; t++) {
        const int rbase = m0 + warp_m * 32 + t * 16 + (lane >> 2);
        #pragma unroll
        for (int j = 0; j < 8; j++) {
            const int col = n0 + warp_n * 64 + j * 8 + 2 * (lane & 3);
            const float b0 = __ldg(bias + col), b1 = __ldg(bias + col + 1);
            #pragma unroll
            for (int half = 0; half < 2; half++) {
                const int row = rbase + 8 * half;
                float v0 = acc[t][j][2 * half]     + b0;
                float v1 = acc[t][j][2 * half + 1] + b1;
                if (act) {
                    v0 = 0.5f * v0 * (1.0f + erff(v0 * 0.70710678118654752f));
                    v1 = 0.5f * v1 * (1.0f + erff(v1 * 0.70710678118654752f));
                }
                const size_t off = (size_t)row * N + col;
                if (Cf) *(float2*)(Cf + off) = make_float2(v0, v1);
                else    *(uint32_t*)(Oh + off) = pack_h2(v0, v1);
            }
        }
    }
}

// ================= FA2-style attention (fp16, 1-term) =================
// Buffers: K@0 (8K), V@8K per 64-key tile; 3 stages x 16KB.
#define AT_BUF  16384
#define AT_SMEM (3 * AT_BUF)

__global__ __launch_bounds__(128) void attn_mma(
    const __half* __restrict__ Q, int ldq, int qoff,
    const __half* __restrict__ Kb, int ldk, int koff,
    const __half* __restrict__ Vb, int ldv, int voff,
    __half* __restrict__ Oh,
    const float* __restrict__ bias, float scale)
{
    extern __shared__ __align__(128) char smem[];
    const uint32_t sbase = smem_u32(smem);
    const int tid = threadIdx.x, lane = tid & 31, w = tid >> 5;
    const int qt = blockIdx.x, bh = blockIdx.y;
    const int b = bh & (BATCH - 1), h = bh >> 5;

    // stage Q into buffer 0 (8K), read fragments, then release
    #pragma unroll
    for (int it = 0; it < 4; it++) {
        int idx = tid + it * 128, r = idx >> 3, c = idx & 7;
        uint32_t sw = r * 128 + ((c ^ (r & 7)) << 4);
        size_t g = (size_t)((qt * 64 + r) * BATCH + b) * ldq + qoff + h * HDIM + c * 8;
        cp_async16(sbase + sw, Q + g);
    }
    cp_commit();
    asm volatile("cp.async.wait_group 0;" ::: "memory");
    __syncthreads();

    const int lr = lane & 15, ls = lane >> 4;
    uint32_t qh[4][4];
    {
        int qrow = w * 16 + lr;
        #pragma unroll
        for (int kc = 0; kc < 4; kc++) {
            int chunk = 2 * kc + ls;
            uint32_t a = sbase + qrow * 128 + ((chunk ^ (qrow & 7)) << 4);
            ldsm_x4(qh[kc], a);
        }
    }
    __syncthreads();

    auto load_kt = [&](int kt, int st) {
        uint32_t sb = sbase + st * AT_BUF;
        #pragma unroll
        for (int it = 0; it < 4; it++) {
            int idx = tid + it * 128, r = idx >> 3, c = idx & 7;
            uint32_t sw = r * 128 + ((c ^ (r & 7)) << 4);
            size_t rowi = (size_t)((kt * 64 + r) * BATCH + b);
            cp_async16(sb + sw,        Kb + rowi * ldk + koff + h * HDIM + c * 8);
            cp_async16(sb + 8192 + sw, Vb + rowi * ldv + voff + h * HDIM + c * 8);
        }
        cp_commit();
    };
    load_kt(0, 0);
    load_kt(1, 1);

    float o[8][4];
    #pragma unroll
    for (int t = 0; t < 8; t++)
        #pragma unroll
        for (int e = 0; e < 4; e++) o[t][e] = 0.0f;
    float mrow0 = -1e30f, mrow1 = -1e30f, lsum0 = 0.0f, lsum1 = 0.0f;

    const int vkbase = ((lane & 16) ? 8 : 0) + (lane & 7);
    const int vcsel  = (lane >> 3) & 1;

    for (int kt = 0; kt < 8; kt++) {
        if (kt < 7) asm volatile("cp.async.wait_group 1;" ::: "memory");
        else        asm volatile("cp.async.wait_group 0;" ::: "memory");
        __syncthreads();
        if (kt + 2 < 8) load_kt(kt + 2, (kt + 2) % 3);
        const uint32_t sb = sbase + (kt % 3) * AT_BUF;

        float s[8][4];
        #pragma unroll
        for (int t = 0; t < 8; t++)
            #pragma unroll
            for (int e = 0; e < 4; e++) s[t][e] = 0.0f;
        #pragma unroll
        for (int kc = 0; kc < 4; kc++) {
            uint32_t kh[4][4];
            #pragma unroll
            for (int u = 0; u < 4; u++) {
                int krow = u * 16 + lr, chunk = 2 * kc + ls;
                uint32_t a = sb + krow * 128 + ((chunk ^ (krow & 7)) << 4);
                ldsm_x4(kh[u], a);
            }
            #pragma unroll
            for (int u = 0; u < 4; u++) {
                mma16816(s[2 * u],     qh[kc], kh[u][0], kh[u][2]);
                mma16816(s[2 * u + 1], qh[kc], kh[u][1], kh[u][3]);
            }
        }

        const int row0 = qt * 64 + w * 16 + (lane >> 2);
        if (bias) {
            #pragma unroll
            for (int t = 0; t < 8; t++) {
                int col = kt * 64 + t * 8 + 2 * (lane & 3);
                float2 b0 = *(const float2*)(bias + (size_t)row0 * TA + col);
                float2 b1 = *(const float2*)(bias + (size_t)(row0 + 8) * TA + col);
                s[t][0] = s[t][0] * scale + b0.x; s[t][1] = s[t][1] * scale + b0.y;
                s[t][2] = s[t][2] * scale + b1.x; s[t][3] = s[t][3] * scale + b1.y;
            }
        } else {
            #pragma unroll
            for (int t = 0; t < 8; t++)
                #pragma unroll
                for (int e = 0; e < 4; e++) s[t][e] *= scale;
        }

        float mx0 = -1e30f, mx1 = -1e30f;
        #pragma unroll
        for (int t = 0; t < 8; t++) {
            mx0 = fmaxf(mx0, fmaxf(s[t][0], s[t][1]));
            mx1 = fmaxf(mx1, fmaxf(s[t][2], s[t][3]));
        }
        mx0 = fmaxf(mx0, __shfl_xor_sync(0xffffffffu, mx0, 1));
        mx0 = fmaxf(mx0, __shfl_xor_sync(0xffffffffu, mx0, 2));
        mx1 = fmaxf(mx1, __shfl_xor_sync(0xffffffffu, mx1, 1));
        mx1 = fmaxf(mx1, __shfl_xor_sync(0xffffffffu, mx1, 2));
        float mn0 = fmaxf(mrow0, mx0), mn1 = fmaxf(mrow1, mx1);
        float a0 = __expf(mrow0 - mn0), a1 = __expf(mrow1 - mn1);
        mrow0 = mn0; mrow1 = mn1;

        float sum0 = 0.0f, sum1 = 0.0f;
        uint32_t phi[4][4];
        #pragma unroll
        for (int t = 0; t < 8; t++) {
            float p0 = __expf(s[t][0] - mn0), p1 = __expf(s[t][1] - mn0);
            float p2 = __expf(s[t][2] - mn1), p3 = __expf(s[t][3] - mn1);
            sum0 += p0 + p1; sum1 += p2 + p3;
            const int kc = t >> 1, j = (t & 1) * 2;
            phi[kc][j]     = pack_h2(p0, p1);
            phi[kc][j + 1] = pack_h2(p2, p3);
        }
        sum0 += __shfl_xor_sync(0xffffffffu, sum0, 1);
        sum0 += __shfl_xor_sync(0xffffffffu, sum0, 2);
        sum1 += __shfl_xor_sync(0xffffffffu, sum1, 1);
        sum1 += __shfl_xor_sync(0xffffffffu, sum1, 2);
        lsum0 = lsum0 * a0 + sum0;
        lsum1 = lsum1 * a1 + sum1;
        #pragma unroll
        for (int t = 0; t < 8; t++) {
            o[t][0] *= a0; o[t][1] *= a0;
            o[t][2] *= a1; o[t][3] *= a1;
        }

        #pragma unroll
        for (int kc = 0; kc < 4; kc++) {
            int vkey = kc * 16 + vkbase;
            uint32_t vh[4][4];
            #pragma unroll
            for (int du = 0; du < 4; du++) {
                int chunk = 2 * du + vcsel;
                uint32_t a = sb + 8192 + vkey * 128 + ((chunk ^ (vkey & 7)) << 4);
                ldsm_x4_t(vh[du], a);
            }
            #pragma unroll
            for (int du = 0; du < 4; du++) {
                mma16816(o[2 * du],     phi[kc], vh[du][0], vh[du][2]);
                mma16816(o[2 * du + 1], phi[kc], vh[du][1], vh[du][3]);
            }
        }
    }

    float inv0 = 1.0f / lsum0, inv1 = 1.0f / lsum1;
    const int row0 = qt * 64 + w * 16 + (lane >> 2);
    #pragma unroll
    for (int t = 0; t < 8; t++) {
        int col = t * 8 + 2 * (lane & 3);
        size_t off0 = (size_t)(row0 * BATCH + b) * D_MODEL + h * HDIM + col;
        size_t off1 = (size_t)((row0 + 8) * BATCH + b) * D_MODEL + h * HDIM + col;
        *(uint32_t*)(Oh + off0) = pack_h2(o[t][0] * inv0, o[t][1] * inv0);
        *(uint32_t*)(Oh + off1) = pack_h2(o[t][2] * inv1, o[t][3] * inv1);
    }
}

// ---------------- Bias precompute ----------------
__global__ void bias_kernel(const int* __restrict__ beats, float* __restrict__ out) {
    __shared__ int sb[NBEATS];
    int i = blockIdx.x;
    int j = threadIdx.x;
    if (threadIdx.x < NBEATS) sb[threadIdx.x] = beats[threadIdx.x];
    __syncthreads();
    float bb = 0.0f;
    #pragma unroll 8
    for (int n = 0; n < NBEATS; n++) {
        int bf = sb[n];
        if (j == bf) bb = fmaxf(bb, 2.0f);
        if (bf > 0      && j == bf - 1) bb = fmaxf(bb, 1.0f);
        if (bf < TA - 1 && j == bf + 1) bb = fmaxf(bb, 1.0f);
    }
    float scale = (float)(TA - 1) / (float)(TM - 1);
    float d = (float)i * scale - (float)j;
    out[i * TA + j] = -(d * d) * (1.0f / 32.0f) + bb;
}

// ---------------- Fused residual + LayerNorm (+ optional fp16 out) ----------------
__global__ __launch_bounds__(256) void add_ln_kernel(
    const float* __restrict__ A, const float* __restrict__ Bv,
    const float* __restrict__ gatePtr,
    const float* __restrict__ gamma, const float* __restrict__ beta,
    float* __restrict__ out, __half* __restrict__ oh)
{
    int t = blockIdx.x;
    int tid = threadIdx.x;
    float gscale = gatePtr ? tanhf(*gatePtr) : 1.0f;
    const float4* a4 = (const float4*)(A  + (size_t)t * D_MODEL);
    const float4* b4 = (const float4*)(Bv + (size_t)t * D_MODEL);
    float4 av = a4[tid], bv = b4[tid];
    float x0 = av.x + gscale * bv.x;
    float x1 = av.y + gscale * bv.y;
    float x2 = av.z + gscale * bv.z;
    float x3 = av.w + gscale * bv.w;
    float s  = x0 + x1 + x2 + x3;
    float ss = x0 * x0 + x1 * x1 + x2 * x2 + x3 * x3;

    __shared__ float rs[8], rss[8];
    #pragma unroll
    for (int o = 16; o > 0; o >>= 1) {
        s  += __shfl_xor_sync(0xffffffffu, s,  o);
        ss += __shfl_xor_sync(0xffffffffu, ss, o);
    }
    if ((tid & 31) == 0) { rs[tid >> 5] = s; rss[tid >> 5] = ss; }
    __syncthreads();
    float stot = 0.0f, sstot = 0.0f;
    #pragma unroll
    for (int i = 0; i < 8; i++) { stot += rs[i]; sstot += rss[i]; }
    float mean = stot * (1.0f / D_MODEL);
    float var  = sstot * (1.0f / D_MODEL) - mean * mean;
    float rstd = rsqrtf(var + LN_EPS);

    const float4* g4 = (const float4*)gamma;
    const float4* be4 = (const float4*)beta;
    float4 g = g4[tid], be = be4[tid];
    float4 o;
    o.x = (x0 - mean) * rstd * g.x + be.x;
    o.y = (x1 - mean) * rstd * g.y + be.y;
    o.z = (x2 - mean) * rstd * g.z + be.z;
    o.w = (x3 - mean) * rstd * g.w + be.w;
    ((float4*)(out + (size_t)t * D_MODEL))[tid] = o;
    if (oh) {
        uint2 uh;
        uh.x = pack_h2(o.x, o.y);
        uh.y = pack_h2(o.z, o.w);
        ((uint2*)(oh + (size_t)t * D_MODEL))[tid] = uh;
    }
}

// ---------------- Launch ----------------
extern "C" void kernel_launch(void* const* d_in, const int* in_sizes, int n_in,
                              void* d_out, int out_size) {
    const float* src      = (const float*)d_in[0];
    const float* audio    = (const float*)d_in[1];
    const int*   beats    = (const int*)  d_in[2];
    const float* sa_in_w  = (const float*)d_in[3];
    const float* sa_in_b  = (const float*)d_in[4];
    const float* sa_out_w = (const float*)d_in[5];
    const float* sa_out_b = (const float*)d_in[6];
    const float* ca_in_w  = (const float*)d_in[7];
    const float* ca_in_b  = (const float*)d_in[8];
    const float* ca_out_w = (const float*)d_in[9];
    const float* ca_out_b = (const float*)d_in[10];
    const float* gate     = (const float*)d_in[11];
    const float* n1_g     = (const float*)d_in[12];
    const float* n1_b     = (const float*)d_in[13];
    const float* nc_g     = (const float*)d_in[14];
    const float* nc_b     = (const float*)d_in[15];
    const float* n2_g     = (const float*)d_in[16];
    const float* n2_b     = (const float*)d_in[17];
    const float* lin1_w   = (const float*)d_in[18];
    const float* lin1_b   = (const float*)d_in[19];
    const float* lin2_w   = (const float*)d_in[20];
    const float* lin2_b   = (const float*)d_in[21];
    float* out = (float*)d_out;

    float *tmp, *x1, *x2, *ff2, *bias;
    __half *X, *AU, *H, *W, *QKV, *KV, *CQ;
    cudaGetSymbolAddress((void**)&tmp,  g_tmp);
    cudaGetSymbolAddress((void**)&x1,   g_x1);
    cudaGetSymbolAddress((void**)&x2,   g_x2);
    cudaGetSymbolAddress((void**)&ff2,  g_ff2);
    cudaGetSymbolAddress((void**)&bias, g_bias);
    cudaGetSymbolAddress((void**)&X,    g_X);
    cudaGetSymbolAddress((void**)&AU,   g_AU);
    cudaGetSymbolAddress((void**)&H,    g_H);
    cudaGetSymbolAddress((void**)&W,    g_W);
    cudaGetSymbolAddress((void**)&QKV,  g_QKV);
    cudaGetSymbolAddress((void**)&KV,   g_KV);
    cudaGetSymbolAddress((void**)&CQ,   g_CQ);

    cudaFuncSetAttribute(gemm_mma, cudaFuncAttributeMaxDynamicSharedMemorySize, G_SMEM);
    cudaFuncSetAttribute(attn_mma, cudaFuncAttributeMaxDynamicSharedMemorySize, AT_SMEM);

    const int CVT_B = 256 * 4;
    #define GEMM(a, bw, bp, cf, oh, Nn, Kk, act) \
        gemm_mma<<<dim3((Nn) / 128, NTOK / 128), 256, G_SMEM>>>(a, bw, bp, cf, oh, Nn, Kk, act)
    #define H_NULL (__half*)nullptr

    // 0-3) bias, weights, src + audio converts
    bias_kernel<<<TM, TA>>>(beats, bias);
    wcvt_kernel<<<W_TOTAL / CVT_B, 256>>>(sa_in_w, sa_out_w, ca_in_w, ca_out_w,
                                          lin1_w, lin2_w, W);
    cvt_kernel<<<NTOK * D_MODEL / CVT_B, 256>>>(src, X, NTOK * D_MODEL);
    cvt_kernel<<<NTOK * D_MODEL / CVT_B, 256>>>(audio, AU, NTOK * D_MODEL);

    // 4) SA packed QKV
    GEMM(X, W + W_SAIN, sa_in_b, (float*)nullptr, QKV, 3 * D_MODEL, D_MODEL, 0);

    // 5) CA KV-proj (independent; fills QKV tail)
    GEMM(AU, W + W_CAIN + (size_t)D_MODEL * D_MODEL,
         ca_in_b + D_MODEL, (float*)nullptr, KV, 2 * D_MODEL, D_MODEL, 0);

    // 6) SA attention
    attn_mma<<<dim3(TM / 64, BATCH * NHEAD), 128, AT_SMEM>>>(
        QKV, 3 * D_MODEL, 0,
        QKV, 3 * D_MODEL, D_MODEL,
        QKV, 3 * D_MODEL, 2 * D_MODEL,
        X, nullptr, 0.125f);

    // 7) SA out-proj
    GEMM(X, W + W_SAOUT, sa_out_b, tmp, H_NULL, D_MODEL, D_MODEL, 0);

    // 8) x1 = LN1(src + sa), fused fp16 out
    add_ln_kernel<<<NTOK, 256>>>(src, tmp, nullptr, n1_g, n1_b, x1, X);

    // 9) CA Q-proj
    GEMM(X, W + W_CAIN, ca_in_b, (float*)nullptr, CQ, D_MODEL, D_MODEL, 0);

    // 10) CA attention (biased)
    attn_mma<<<dim3(TM / 64, BATCH * NHEAD), 128, AT_SMEM>>>(
        CQ, D_MODEL, 0,
        KV, 2 * D_MODEL, 0,
        KV, 2 * D_MODEL, D_MODEL,
        X, bias, 0.125f);

    // 11) CA out-proj
    GEMM(X, W + W_CAOUT, ca_out_b, tmp, H_NULL, D_MODEL, D_MODEL, 0);

    // 12) x2 = LNc(x1 + tanh(gate)*cross), fused fp16 out
    add_ln_kernel<<<NTOK, 256>>>(x1, tmp, gate, nc_g, nc_b, x2, X);

    // 13-14) FFN
    GEMM(X, W + W_LIN1, lin1_b, (float*)nullptr, H, DFF, D_MODEL, 1);
    GEMM(H, W + W_LIN2, lin2_b, ff2, H_NULL, D_MODEL, DFF, 0);

    // 15) out = LN2(x2 + ff)
    add_ln_kernel<<<NTOK, 256>>>(x2, ff2, nullptr, n2_g, n2_b, out, H_NULL);
}

// round 12
// speedup vs baseline: 3.1495x; 1.0548x over previous
#include <cuda_runtime.h>
#include <cuda_fp16.h>
#include <math.h>
#include <stdint.h>

// ---------------- Problem constants ----------------
#define D_MODEL 1024
#define NHEAD   16
#define HDIM    64
#define DFF     4096
#define TM      512
#define TA      512
#define BATCH   32
#define NTOK    (TM * BATCH)   // 16384
#define NBEATS  64
#define LN_EPS  1e-5f

// ---------------- fp32 scratch ----------------
__device__ float g_tmp [NTOK * D_MODEL];
__device__ float g_x1  [NTOK * D_MODEL];
__device__ float g_x2  [NTOK * D_MODEL];
__device__ float g_ff2 [NTOK * D_MODEL];
__device__ float g_bias[TM * TA];

// ---------------- fp16 scratch ----------------
__device__ __half g_X  [NTOK * D_MODEL];
__device__ __half g_AU [NTOK * D_MODEL];
__device__ __half g_H  [NTOK * DFF];
__device__ __half g_QKV[NTOK * 3 * D_MODEL];
__device__ __half g_KV [NTOK * 2 * D_MODEL];
__device__ __half g_CQ [NTOK * D_MODEL];
__device__ __half g_W  [16777216];

#define W_SAIN   0
#define W_SAOUT  3145728
#define W_CAIN   4194304
#define W_CAOUT  7340032
#define W_LIN1   8388608
#define W_LIN2  12582912
#define W_TOTAL 16777216

// ================= helpers (non-'a' PTX only) =================
__device__ __forceinline__ uint32_t smem_u32(const void* p) {
    uint32_t a;
    asm("{ .reg .u64 t; cvta.to.shared.u64 t, %1; cvt.u32.u64 %0, t; }" : "=r"(a) : "l"(p));
    return a;
}
__device__ __forceinline__ void cp_async16(uint32_t saddr, const void* g) {
    asm volatile("cp.async.cg.shared.global [%0], [%1], 16;" :: "r"(saddr), "l"(g));
}
__device__ __forceinline__ void cp_commit() {
    asm volatile("cp.async.commit_group;" ::: "memory");
}
__device__ __forceinline__ void ldsm_x4(uint32_t (&r)[4], uint32_t addr) {
    asm volatile("ldmatrix.sync.aligned.m8n8.x4.shared.b16 {%0,%1,%2,%3}, [%4];"
                 : "=r"(r[0]), "=r"(r[1]), "=r"(r[2]), "=r"(r[3]) : "r"(addr));
}
__device__ __forceinline__ void ldsm_x4_t(uint32_t (&r)[4], uint32_t addr) {
    asm volatile("ldmatrix.sync.aligned.m8n8.x4.trans.shared.b16 {%0,%1,%2,%3}, [%4];"
                 : "=r"(r[0]), "=r"(r[1]), "=r"(r[2]), "=r"(r[3]) : "r"(addr));
}
__device__ __forceinline__ void mma16816(float (&d)[4], const uint32_t (&a)[4],
                                         uint32_t b0, uint32_t b1) {
    asm volatile(
        "mma.sync.aligned.m16n8k16.row.col.f32.f16.f16.f32 "
        "{%0,%1,%2,%3}, {%4,%5,%6,%7}, {%8,%9}, {%0,%1,%2,%3};"
        : "+f"(d[0]), "+f"(d[1]), "+f"(d[2]), "+f"(d[3])
        : "r"(a[0]), "r"(a[1]), "r"(a[2]), "r"(a[3]), "r"(b0), "r"(b1));
}
__device__ __forceinline__ uint32_t pack_h2(float x, float y) {
    return (uint32_t)__half_as_ushort(__float2half_rn(x)) |
           ((uint32_t)__half_as_ushort(__float2half_rn(y)) << 16);
}

// ================= converts =================
__global__ __launch_bounds__(256) void cvt_kernel(
    const float* __restrict__ src, __half* __restrict__ hi, int n)
{
    int i = (blockIdx.x * 256 + threadIdx.x) * 4;
    if (i >= n) return;
    float4 v = *(const float4*)(src + i);
    uint2 uh;
    uh.x = pack_h2(v.x, v.y);
    uh.y = pack_h2(v.z, v.w);
    *(uint2*)(hi + i) = uh;
}

__global__ __launch_bounds__(256) void wcvt_kernel(
    const float* __restrict__ w0, const float* __restrict__ w1,
    const float* __restrict__ w2, const float* __restrict__ w3,
    const float* __restrict__ w4, const float* __restrict__ w5,
    __half* __restrict__ hi)
{
    int i = (blockIdx.x * 256 + threadIdx.x) * 4;
    const float* src; int off;
    if      (i < W_SAOUT) { src = w0; off = W_SAIN; }
    else if (i < W_CAIN)  { src = w1; off = W_SAOUT; }
    else if (i < W_CAOUT) { src = w2; off = W_CAIN; }
    else if (i < W_LIN1)  { src = w3; off = W_CAOUT; }
    else if (i < W_LIN2)  { src = w4; off = W_LIN1; }
    else                  { src = w5; off = W_LIN2; }
    float4 v = *(const float4*)(src + (i - off));
    uint2 uh;
    uh.x = pack_h2(v.x, v.y);
    uh.y = pack_h2(v.z, v.w);
    *(uint2*)(hi + i) = uh;
}

// ================= mma.sync GEMM (fp16, BK=64) =================
// C[M,N] = A[M,K]*B[N,K]^T + bias. CTA 128x128 (warp 32x64), BK=64,
// 3 stages x 32KB, 2 CTAs/SM. Stage: A@0 (16K, 128 rows x 128B), B@16K.
// 16B chunk c (0..7) of row r at r*128 + ((c^(r&7))<<4).
#define G_STAGE 32768
#define G_SMEM  (3 * G_STAGE)

__global__ __launch_bounds__(256, 2) void gemm_mma(
    const __half* __restrict__ A, const __half* __restrict__ B,
    const float* __restrict__ bias, float* __restrict__ Cf,
    __half* __restrict__ Oh,
    int N, int K, int act)
{
    extern __shared__ __align__(128) char smem[];
    const uint32_t sbase = smem_u32(smem);
    const int tid = threadIdx.x;
    const int lane = tid & 31, wid = tid >> 5;
    const int warp_m = wid & 3, warp_n = wid >> 2;
    const int m0 = blockIdx.y * 128, n0 = blockIdx.x * 128;

    float acc[2][8][4];
    #pragma unroll
    for (int t = 0; t < 2; t++)
        #pragma unroll
        for (int j = 0; j < 8; j++)
            #pragma unroll
            for (int e = 0; e < 4; e++) acc[t][j][e] = 0.0f;

    auto stage_load = [&](int ci, int st) {
        const uint32_t sb = sbase + st * G_STAGE;
        const int kk = ci * 64;
        #pragma unroll
        for (int it = 0; it < 4; it++) {
            int idx = tid + it * 256;           // 0..1023
            int r = idx >> 3, c = idx & 7;
            uint32_t sw = r * 128 + ((c ^ (r & 7)) << 4);
            cp_async16(sb + sw, A + (size_t)(m0 + r) * K + kk + c * 8);
        }
        #pragma unroll
        for (int it = 0; it < 4; it++) {
            int idx = tid + it * 256;
            int r = idx >> 3, c = idx & 7;
            uint32_t sw = r * 128 + ((c ^ (r & 7)) << 4);
            cp_async16(sb + 16384 + sw, B + (size_t)(n0 + r) * K + kk + c * 8);
        }
        cp_commit();
    };

    const int lr = lane & 15;
    const int lseg = lane >> 4;
    int arow[2], brow[4];
    #pragma unroll
    for (int t = 0; t < 2; t++) arow[t] = warp_m * 32 + t * 16 + lr;
    #pragma unroll
    for (int u = 0; u < 4; u++) brow[u] = warp_n * 64 + u * 16 + lr;

    const int nch = K >> 6;
    stage_load(0, 0);
    stage_load(1, 1);

    for (int i = 0; i < nch; i++) {
        if (i < nch - 1) asm volatile("cp.async.wait_group 1;" ::: "memory");
        else             asm volatile("cp.async.wait_group 0;" ::: "memory");
        __syncthreads();
        if (i + 2 < nch) stage_load(i + 2, (i + 2) % 3);   // stage consumed at i-1

        const uint32_t sb = sbase + (i % 3) * G_STAGE;
        #pragma unroll
        for (int kc = 0; kc < 4; kc++) {
            const int chunk = 2 * kc + lseg;
            uint32_t ah[2][4], bh[4][4];
            #pragma unroll
            for (int t = 0; t < 2; t++) {
                uint32_t a = sb + arow[t] * 128 + ((chunk ^ (arow[t] & 7)) << 4);
                ldsm_x4(ah[t], a);
            }
            #pragma unroll
            for (int u = 0; u < 4; u++) {
                uint32_t a = sb + 16384 + brow[u] * 128 + ((chunk ^ (brow[u] & 7)) << 4);
                ldsm_x4(bh[u], a);
            }
            #pragma unroll
            for (int t = 0; t < 2; t++)
                #pragma unroll
                for (int u = 0; u < 4; u++) {
                    mma16816(acc[t][2 * u],     ah[t], bh[u][0], bh[u][2]);
                    mma16816(acc[t][2 * u + 1], ah[t], bh[u][1], bh[u][3]);
                }
        }
    }

    #pragma unroll
    for (int t = 0; t < 2; t++) {
        const int rbase = m0 + warp_m * 32 + t * 16 + (lane >> 2);
        #pragma unroll
        for (int j = 0; j < 8; j++) {
            const int col = n0 + warp_n * 64 + j * 8 + 2 * (lane & 3);
            const float b0 = __ldg(bias + col), b1 = __ldg(bias + col + 1);
            #pragma unroll
            for (int half = 0; half < 2; half++) {
                const int row = rbase + 8 * half;
                float v0 = acc[t][j][2 * half]     + b0;
                float v1 = acc[t][j][2 * half + 1] + b1;
                if (act) {
                    v0 = 0.5f * v0 * (1.0f + erff(v0 * 0.70710678118654752f));
                    v1 = 0.5f * v1 * (1.0f + erff(v1 * 0.70710678118654752f));
                }
                const size_t off = (size_t)row * N + col;
                if (Cf) *(float2*)(Cf + off) = make_float2(v0, v1);
                else    *(uint32_t*)(Oh + off) = pack_h2(v0, v1);
            }
        }
    }
}

// ================= FA2-style attention (fp16) =================
#define AT_BUF  16384
#define AT_SMEM (3 * AT_BUF)

__global__ __launch_bounds__(128) void attn_mma(
    const __half* __restrict__ Q, int ldq, int qoff,
    const __half* __restrict__ Kb, int ldk, int koff,
    const __half* __restrict__ Vb, int ldv, int voff,
    __half* __restrict__ Oh,
    const float* __restrict__ bias, float scale)
{
    extern __shared__ __align__(128) char smem[];
    const uint32_t sbase = smem_u32(smem);
    const int tid = threadIdx.x, lane = tid & 31, w = tid >> 5;
    const int qt = blockIdx.x, bh = blockIdx.y;
    const int b = bh & (BATCH - 1), h = bh >> 5;

    #pragma unroll
    for (int it = 0; it < 4; it++) {
        int idx = tid + it * 128, r = idx >> 3, c = idx & 7;
        uint32_t sw = r * 128 + ((c ^ (r & 7)) << 4);
        size_t g = (size_t)((qt * 64 + r) * BATCH + b) * ldq + qoff + h * HDIM + c * 8;
        cp_async16(sbase + sw, Q + g);
    }
    cp_commit();
    asm volatile("cp.async.wait_group 0;" ::: "memory");
    __syncthreads();

    const int lr = lane & 15, ls = lane >> 4;
    uint32_t qh[4][4];
    {
        int qrow = w * 16 + lr;
        #pragma unroll
        for (int kc = 0; kc < 4; kc++) {
            int chunk = 2 * kc + ls;
            uint32_t a = sbase + qrow * 128 + ((chunk ^ (qrow & 7)) << 4);
            ldsm_x4(qh[kc], a);
        }
    }
    __syncthreads();

    auto load_kt = [&](int kt, int st) {
        uint32_t sb = sbase + st * AT_BUF;
        #pragma unroll
        for (int it = 0; it < 4; it++) {
            int idx = tid + it * 128, r = idx >> 3, c = idx & 7;
            uint32_t sw = r * 128 + ((c ^ (r & 7)) << 4);
            size_t rowi = (size_t)((kt * 64 + r) * BATCH + b);
            cp_async16(sb + sw,        Kb + rowi * ldk + koff + h * HDIM + c * 8);
            cp_async16(sb + 8192 + sw, Vb + rowi * ldv + voff + h * HDIM + c * 8);
        }
        cp_commit();
    };
    load_kt(0, 0);
    load_kt(1, 1);

    float o[8][4];
    #pragma unroll
    for (int t = 0; t < 8; t++)
        #pragma unroll
        for (int e = 0; e < 4; e++) o[t][e] = 0.0f;
    float mrow0 = -1e30f, mrow1 = -1e30f, lsum0 = 0.0f, lsum1 = 0.0f;

    const int vkbase = ((lane & 16) ? 8 : 0) + (lane & 7);
    const int vcsel  = (lane >> 3) & 1;

    for (int kt = 0; kt < 8; kt++) {
        if (kt < 7) asm volatile("cp.async.wait_group 1;" ::: "memory");
        else        asm volatile("cp.async.wait_group 0;" ::: "memory");
        __syncthreads();
        if (kt + 2 < 8) load_kt(kt + 2, (kt + 2) % 3);
        const uint32_t sb = sbase + (kt % 3) * AT_BUF;

        float s[8][4];
        #pragma unroll
        for (int t = 0; t < 8; t++)
            #pragma unroll
            for (int e = 0; e < 4; e++) s[t][e] = 0.0f;
        #pragma unroll
        for (int kc = 0; kc < 4; kc++) {
            uint32_t kh[4][4];
            #pragma unroll
            for (int u = 0; u < 4; u++) {
                int krow = u * 16 + lr, chunk = 2 * kc + ls;
                uint32_t a = sb + krow * 128 + ((chunk ^ (krow & 7)) << 4);
                ldsm_x4(kh[u], a);
            }
            #pragma unroll
            for (int u = 0; u < 4; u++) {
                mma16816(s[2 * u],     qh[kc], kh[u][0], kh[u][2]);
                mma16816(s[2 * u + 1], qh[kc], kh[u][1], kh[u][3]);
            }
        }

        const int row0 = qt * 64 + w * 16 + (lane >> 2);
        if (bias) {
            #pragma unroll
            for (int t = 0; t < 8; t++) {
                int col = kt * 64 + t * 8 + 2 * (lane & 3);
                float2 b0 = *(const float2*)(bias + (size_t)row0 * TA + col);
                float2 b1 = *(const float2*)(bias + (size_t)(row0 + 8) * TA + col);
                s[t][0] = s[t][0] * scale + b0.x; s[t][1] = s[t][1] * scale + b0.y;
                s[t][2] = s[t][2] * scale + b1.x; s[t][3] = s[t][3] * scale + b1.y;
            }
        } else {
            #pragma unroll
            for (int t = 0; t < 8; t++)
                #pragma unroll
                for (int e = 0; e < 4; e++) s[t][e] *= scale;
        }

        float mx0 = -1e30f, mx1 = -1e30f;
        #pragma unroll
        for (int t = 0; t < 8; t++) {
            mx0 = fmaxf(mx0, fmaxf(s[t][0], s[t][1]));
            mx1 = fmaxf(mx1, fmaxf(s[t][2], s[t][3]));
        }
        mx0 = fmaxf(mx0, __shfl_xor_sync(0xffffffffu, mx0, 1));
        mx0 = fmaxf(mx0, __shfl_xor_sync(0xffffffffu, mx0, 2));
        mx1 = fmaxf(mx1, __shfl_xor_sync(0xffffffffu, mx1, 1));
        mx1 = fmaxf(mx1, __shfl_xor_sync(0xffffffffu, mx1, 2));
        float mn0 = fmaxf(mrow0, mx0), mn1 = fmaxf(mrow1, mx1);
        float a0 = __expf(mrow0 - mn0), a1 = __expf(mrow1 - mn1);
        mrow0 = mn0; mrow1 = mn1;

        float sum0 = 0.0f, sum1 = 0.0f;
        uint32_t phi[4][4];
        #pragma unroll
        for (int t = 0; t < 8; t++) {
            float p0 = __expf(s[t][0] - mn0), p1 = __expf(s[t][1] - mn0);
            float p2 = __expf(s[t][2] - mn1), p3 = __expf(s[t][3] - mn1);
            sum0 += p0 + p1; sum1 += p2 + p3;
            const int kc = t >> 1, j = (t & 1) * 2;
            phi[kc][j]     = pack_h2(p0, p1);
            phi[kc][j + 1] = pack_h2(p2, p3);
        }
        sum0 += __shfl_xor_sync(0xffffffffu, sum0, 1);
        sum0 += __shfl_xor_sync(0xffffffffu, sum0, 2);
        sum1 += __shfl_xor_sync(0xffffffffu, sum1, 1);
        sum1 += __shfl_xor_sync(0xffffffffu, sum1, 2);
        lsum0 = lsum0 * a0 + sum0;
        lsum1 = lsum1 * a1 + sum1;
        #pragma unroll
        for (int t = 0; t < 8; t++) {
            o[t][0] *= a0; o[t][1] *= a0;
            o[t][2] *= a1; o[t][3] *= a1;
        }

        #pragma unroll
        for (int kc = 0; kc < 4; kc++) {
            int vkey = kc * 16 + vkbase;
            uint32_t vh[4][4];
            #pragma unroll
            for (int du = 0; du < 4; du++) {
                int chunk = 2 * du + vcsel;
                uint32_t a = sb + 8192 + vkey * 128 + ((chunk ^ (vkey & 7)) << 4);
                ldsm_x4_t(vh[du], a);
            }
            #pragma unroll
            for (int du = 0; du < 4; du++) {
                mma16816(o[2 * du],     phi[kc], vh[du][0], vh[du][2]);
                mma16816(o[2 * du + 1], phi[kc], vh[du][1], vh[du][3]);
            }
        }
    }

    float inv0 = 1.0f / lsum0, inv1 = 1.0f / lsum1;
    const int row0 = qt * 64 + w * 16 + (lane >> 2);
    #pragma unroll
    for (int t = 0; t < 8; t++) {
        int col = t * 8 + 2 * (lane & 3);
        size_t off0 = (size_t)(row0 * BATCH + b) * D_MODEL + h * HDIM + col;
        size_t off1 = (size_t)((row0 + 8) * BATCH + b) * D_MODEL + h * HDIM + col;
        *(uint32_t*)(Oh + off0) = pack_h2(o[t][0] * inv0, o[t][1] * inv0);
        *(uint32_t*)(Oh + off1) = pack_h2(o[t][2] * inv1, o[t][3] * inv1);
    }
}

// ---------------- Bias precompute ----------------
__global__ void bias_kernel(const int* __restrict__ beats, float* __restrict__ out) {
    __shared__ int sb[NBEATS];
    int i = blockIdx.x;
    int j = threadIdx.x;
    if (threadIdx.x < NBEATS) sb[threadIdx.x] = beats[threadIdx.x];
    __syncthreads();
    float bb = 0.0f;
    #pragma unroll 8
    for (int n = 0; n < NBEATS; n++) {
        int bf = sb[n];
        if (j == bf) bb = fmaxf(bb, 2.0f);
        if (bf > 0      && j == bf - 1) bb = fmaxf(bb, 1.0f);
        if (bf < TA - 1 && j == bf + 1) bb = fmaxf(bb, 1.0f);
    }
    float scale = (float)(TA - 1) / (float)(TM - 1);
    float d = (float)i * scale - (float)j;
    out[i * TA + j] = -(d * d) * (1.0f / 32.0f) + bb;
}

// ---------------- Fused residual + LayerNorm (+ optional fp16 out) ----------------
__global__ __launch_bounds__(256) void add_ln_kernel(
    const float* __restrict__ A, const float* __restrict__ Bv,
    const float* __restrict__ gatePtr,
    const float* __restrict__ gamma, const float* __restrict__ beta,
    float* __restrict__ out, __half* __restrict__ oh)
{
    int t = blockIdx.x;
    int tid = threadIdx.x;
    float gscale = gatePtr ? tanhf(*gatePtr) : 1.0f;
    const float4* a4 = (const float4*)(A  + (size_t)t * D_MODEL);
    const float4* b4 = (const float4*)(Bv + (size_t)t * D_MODEL);
    float4 av = a4[tid], bv = b4[tid];
    float x0 = av.x + gscale * bv.x;
    float x1 = av.y + gscale * bv.y;
    float x2 = av.z + gscale * bv.z;
    float x3 = av.w + gscale * bv.w;
    float s  = x0 + x1 + x2 + x3;
    float ss = x0 * x0 + x1 * x1 + x2 * x2 + x3 * x3;

    __shared__ float rs[8], rss[8];
    #pragma unroll
    for (int o = 16; o > 0; o >>= 1) {
        s  += __shfl_xor_sync(0xffffffffu, s,  o);
        ss += __shfl_xor_sync(0xffffffffu, ss, o);
    }
    if ((tid & 31) == 0) { rs[tid >> 5] = s; rss[tid >> 5] = ss; }
    __syncthreads();
    float stot = 0.0f, sstot = 0.0f;
    #pragma unroll
    for (int i = 0; i < 8; i++) { stot += rs[i]; sstot += rss[i]; }
    float mean = stot * (1.0f / D_MODEL);
    float var  = sstot * (1.0f / D_MODEL) - mean * mean;
    float rstd = rsqrtf(var + LN_EPS);

    const float4* g4 = (const float4*)gamma;
    const float4* be4 = (const float4*)beta;
    float4 g = g4[tid], be = be4[tid];
    float4 o;
    o.x = (x0 - mean) * rstd * g.x + be.x;
    o.y = (x1 - mean) * rstd * g.y + be.y;
    o.z = (x2 - mean) * rstd * g.z + be.z;
    o.w = (x3 - mean) * rstd * g.w + be.w;
    ((float4*)(out + (size_t)t * D_MODEL))[tid] = o;
    if (oh) {
        uint2 uh;
        uh.x = pack_h2(o.x, o.y);
        uh.y = pack_h2(o.z, o.w);
        ((uint2*)(oh + (size_t)t * D_MODEL))[tid] = uh;
    }
}

// ---------------- Launch ----------------
extern "C" void kernel_launch(void* const* d_in, const int* in_sizes, int n_in,
                              void* d_out, int out_size) {
    const float* src      = (const float*)d_in[0];
    const float* audio    = (const float*)d_in[1];
    const int*   beats    = (const int*)  d_in[2];
    const float* sa_in_w  = (const float*)d_in[3];
    const float* sa_in_b  = (const float*)d_in[4];
    const float* sa_out_w = (const float*)d_in[5];
    const float* sa_out_b = (const float*)d_in[6];
    const float* ca_in_w  = (const float*)d_in[7];
    const float* ca_in_b  = (const float*)d_in[8];
    const float* ca_out_w = (const float*)d_in[9];
    const float* ca_out_b = (const float*)d_in[10];
    const float* gate     = (const float*)d_in[11];
    const float* n1_g     = (const float*)d_in[12];
    const float* n1_b     = (const float*)d_in[13];
    const float* nc_g     = (const float*)d_in[14];
    const float* nc_b     = (const float*)d_in[15];
    const float* n2_g     = (const float*)d_in[16];
    const float* n2_b     = (const float*)d_in[17];
    const float* lin1_w   = (const float*)d_in[18];
    const float* lin1_b   = (const float*)d_in[19];
    const float* lin2_w   = (const float*)d_in[20];
    const float* lin2_b   = (const float*)d_in[21];
    float* out = (float*)d_out;

    float *tmp, *x1, *x2, *ff2, *bias;
    __half *X, *AU, *H, *W, *QKV, *KV, *CQ;
    cudaGetSymbolAddress((void**)&tmp,  g_tmp);
    cudaGetSymbolAddress((void**)&x1,   g_x1);
    cudaGetSymbolAddress((void**)&x2,   g_x2);
    cudaGetSymbolAddress((void**)&ff2,  g_ff2);
    cudaGetSymbolAddress((void**)&bias, g_bias);
    cudaGetSymbolAddress((void**)&X,    g_X);
    cudaGetSymbolAddress((void**)&AU,   g_AU);
    cudaGetSymbolAddress((void**)&H,    g_H);
    cudaGetSymbolAddress((void**)&W,    g_W);
    cudaGetSymbolAddress((void**)&QKV,  g_QKV);
    cudaGetSymbolAddress((void**)&KV,   g_KV);
    cudaGetSymbolAddress((void**)&CQ,   g_CQ);

    cudaFuncSetAttribute(gemm_mma, cudaFuncAttributeMaxDynamicSharedMemorySize, G_SMEM);
    cudaFuncSetAttribute(attn_mma, cudaFuncAttributeMaxDynamicSharedMemorySize, AT_SMEM);

    const int CVT_B = 256 * 4;
    #define GEMM(a, bw, bp, cf, oh, Nn, Kk, act) \
        gemm_mma<<<dim3((Nn) / 128, NTOK / 128), 256, G_SMEM>>>(a, bw, bp, cf, oh, Nn, Kk, act)
    #define H_NULL (__half*)nullptr

    // 0-3) bias, weights, src + audio converts
    bias_kernel<<<TM, TA>>>(beats, bias);
    wcvt_kernel<<<W_TOTAL / CVT_B, 256>>>(sa_in_w, sa_out_w, ca_in_w, ca_out_w,
                                          lin1_w, lin2_w, W);
    cvt_kernel<<<NTOK * D_MODEL / CVT_B, 256>>>(src, X, NTOK * D_MODEL);
    cvt_kernel<<<NTOK * D_MODEL / CVT_B, 256>>>(audio, AU, NTOK * D_MODEL);

    // 4) SA packed QKV
    GEMM(X, W + W_SAIN, sa_in_b, (float*)nullptr, QKV, 3 * D_MODEL, D_MODEL, 0);

    // 5) CA KV-proj (independent; fills QKV tail)
    GEMM(AU, W + W_CAIN + (size_t)D_MODEL * D_MODEL,
         ca_in_b + D_MODEL, (float*)nullptr, KV, 2 * D_MODEL, D_MODEL, 0);

    // 6) SA attention
    attn_mma<<<dim3(TM / 64, BATCH * NHEAD), 128, AT_SMEM>>>(
        QKV, 3 * D_MODEL, 0,
        QKV, 3 * D_MODEL, D_MODEL,
        QKV, 3 * D_MODEL, 2 * D_MODEL,
        X, nullptr, 0.125f);

    // 7) SA out-proj
    GEMM(X, W + W_SAOUT, sa_out_b, tmp, H_NULL, D_MODEL, D_MODEL, 0);

    // 8) x1 = LN1(src + sa), fused fp16 out
    add_ln_kernel<<<NTOK, 256>>>(src, tmp, nullptr, n1_g, n1_b, x1, X);

    // 9) CA Q-proj
    GEMM(X, W + W_CAIN, ca_in_b, (float*)nullptr, CQ, D_MODEL, D_MODEL, 0);

    // 10) CA attention (biased)
    attn_mma<<<dim3(TM / 64, BATCH * NHEAD), 128, AT_SMEM>>>(
        CQ, D_MODEL, 0,
        KV, 2 * D_MODEL, 0,
        KV, 2 * D_MODEL, D_MODEL,
        X, bias, 0.125f);

    // 11) CA out-proj
    GEMM(X, W + W_CAOUT, ca_out_b, tmp, H_NULL, D_MODEL, D_MODEL, 0);

    // 12) x2 = LNc(x1 + tanh(gate)*cross), fused fp16 out
    add_ln_kernel<<<NTOK, 256>>>(x1, tmp, gate, nc_g, nc_b, x2, X);

    // 13-14) FFN
    GEMM(X, W + W_LIN1, lin1_b, (float*)nullptr, H, DFF, D_MODEL, 1);
    GEMM(H, W + W_LIN2, lin2_b, ff2, H_NULL, D_MODEL, DFF, 0);

    // 15) out = LN2(x2 + ff)
    add_ln_kernel<<<NTOK, 256>>>(x2, ff2, nullptr, n2_g, n2_b, out, H_NULL);
}

// round 13
// speedup vs baseline: 3.2507x; 1.0321x over previous
#include <cuda_runtime.h>
#include <cuda_fp16.h>
#include <math.h>
#include <stdint.h>

// ---------------- Problem constants ----------------
#define D_MODEL 1024
#define NHEAD   16
#define HDIM    64
#define DFF     4096
#define TM      512
#define TA      512
#define BATCH   32
#define NTOK    (TM * BATCH)   // 16384
#define NBEATS  64
#define LN_EPS  1e-5f

// ---------------- fp32 scratch ----------------
__device__ float g_x1  [NTOK * D_MODEL];
__device__ float g_x2  [NTOK * D_MODEL];
__device__ float g_bias[TM * TA];

// ---------------- fp16 scratch ----------------
__device__ __half g_X  [NTOK * D_MODEL];
__device__ __half g_AU [NTOK * D_MODEL];
__device__ __half g_TMP[NTOK * D_MODEL];
__device__ __half g_H  [NTOK * DFF];
__device__ __half g_QKV[NTOK * 3 * D_MODEL];
__device__ __half g_KV [NTOK * 2 * D_MODEL];
__device__ __half g_CQ [NTOK * D_MODEL];
__device__ __half g_W  [16777216];

#define W_SAIN   0
#define W_SAOUT  3145728
#define W_CAIN   4194304
#define W_CAOUT  7340032
#define W_LIN1   8388608
#define W_LIN2  12582912
#define W_TOTAL 16777216

// ================= helpers (non-'a' PTX only) =================
__device__ __forceinline__ uint32_t smem_u32(const void* p) {
    uint32_t a;
    asm("{ .reg .u64 t; cvta.to.shared.u64 t, %1; cvt.u32.u64 %0, t; }" : "=r"(a) : "l"(p));
    return a;
}
__device__ __forceinline__ void cp_async16(uint32_t saddr, const void* g) {
    asm volatile("cp.async.cg.shared.global [%0], [%1], 16;" :: "r"(saddr), "l"(g));
}
__device__ __forceinline__ void cp_commit() {
    asm volatile("cp.async.commit_group;" ::: "memory");
}
__device__ __forceinline__ void ldsm_x4(uint32_t (&r)[4], uint32_t addr) {
    asm volatile("ldmatrix.sync.aligned.m8n8.x4.shared.b16 {%0,%1,%2,%3}, [%4];"
                 : "=r"(r[0]), "=r"(r[1]), "=r"(r[2]), "=r"(r[3]) : "r"(addr));
}
__device__ __forceinline__ void ldsm_x4_t(uint32_t (&r)[4], uint32_t addr) {
    asm volatile("ldmatrix.sync.aligned.m8n8.x4.trans.shared.b16 {%0,%1,%2,%3}, [%4];"
                 : "=r"(r[0]), "=r"(r[1]), "=r"(r[2]), "=r"(r[3]) : "r"(addr));
}
__device__ __forceinline__ void mma16816(float (&d)[4], const uint32_t (&a)[4],
                                         uint32_t b0, uint32_t b1) {
    asm volatile(
        "mma.sync.aligned.m16n8k16.row.col.f32.f16.f16.f32 "
        "{%0,%1,%2,%3}, {%4,%5,%6,%7}, {%8,%9}, {%0,%1,%2,%3};"
        : "+f"(d[0]), "+f"(d[1]), "+f"(d[2]), "+f"(d[3])
        : "r"(a[0]), "r"(a[1]), "r"(a[2]), "r"(a[3]), "r"(b0), "r"(b1));
}
__device__ __forceinline__ uint32_t pack_h2(float x, float y) {
    return (uint32_t)__half_as_ushort(__float2half_rn(x)) |
           ((uint32_t)__half_as_ushort(__float2half_rn(y)) << 16);
}

// ================= converts =================
__global__ __launch_bounds__(256) void cvt_kernel(
    const float* __restrict__ src, __half* __restrict__ hi, int n)
{
    int i = (blockIdx.x * 256 + threadIdx.x) * 4;
    if (i >= n) return;
    float4 v = *(const float4*)(src + i);
    uint2 uh;
    uh.x = pack_h2(v.x, v.y);
    uh.y = pack_h2(v.z, v.w);
    *(uint2*)(hi + i) = uh;
}

__global__ __launch_bounds__(256) void wcvt_kernel(
    const float* __restrict__ w0, const float* __restrict__ w1,
    const float* __restrict__ w2, const float* __restrict__ w3,
    const float* __restrict__ w4, const float* __restrict__ w5,
    __half* __restrict__ hi)
{
    int i = (blockIdx.x * 256 + threadIdx.x) * 4;
    const float* src; int off;
    if      (i < W_SAOUT) { src = w0; off = W_SAIN; }
    else if (i < W_CAIN)  { src = w1; off = W_SAOUT; }
    else if (i < W_CAOUT) { src = w2; off = W_CAIN; }
    else if (i < W_LIN1)  { src = w3; off = W_CAOUT; }
    else if (i < W_LIN2)  { src = w4; off = W_LIN1; }
    else                  { src = w5; off = W_LIN2; }
    float4 v = *(const float4*)(src + (i - off));
    uint2 uh;
    uh.x = pack_h2(v.x, v.y);
    uh.y = pack_h2(v.z, v.w);
    *(uint2*)(hi + i) = uh;
}

// ================= mma.sync GEMM (fp16, BK=64, fp16 out, dual param-set) =================
// Set 1 covers blockIdx.x < nx1; if A2 != null, remaining tiles run GEMM 2.
#define G_STAGE 32768
#define G_SMEM  (3 * G_STAGE)

__global__ __launch_bounds__(256, 2) void gemm_mma(
    const __half* __restrict__ A, const __half* __restrict__ B,
    const float* __restrict__ bias, __half* __restrict__ Oh,
    int N, int K, int act,
    const __half* A2, const __half* B2, const float* bias2,
    __half* Oh2, int N2, int nx1)
{
    extern __shared__ __align__(128) char smem[];
    const uint32_t sbase = smem_u32(smem);
    const int tid = threadIdx.x;
    const int lane = tid & 31, wid = tid >> 5;
    const int warp_m = wid & 3, warp_n = wid >> 2;

    int bx = blockIdx.x;
    if (A2 && bx >= nx1) {
        A = A2; B = B2; bias = bias2; Oh = Oh2; N = N2;
        bx -= nx1;
    }
    const int m0 = blockIdx.y * 128, n0 = bx * 128;

    float acc[2][8][4];
    #pragma unroll
    for (int t = 0; t < 2; t++)
        #pragma unroll
        for (int j = 0; j < 8; j++)
            #pragma unroll
            for (int e = 0; e < 4; e++) acc[t][j][e] = 0.0f;

    auto stage_load = [&](int ci, int st) {
        const uint32_t sb = sbase + st * G_STAGE;
        const int kk = ci * 64;
        #pragma unroll
        for (int it = 0; it < 4; it++) {
            int idx = tid + it * 256;
            int r = idx >> 3, c = idx & 7;
            uint32_t sw = r * 128 + ((c ^ (r & 7)) << 4);
            cp_async16(sb + sw, A + (size_t)(m0 + r) * K + kk + c * 8);
        }
        #pragma unroll
        for (int it = 0; it < 4; it++) {
            int idx = tid + it * 256;
            int r = idx >> 3, c = idx & 7;
            uint32_t sw = r * 128 + ((c ^ (r & 7)) << 4);
            cp_async16(sb + 16384 + sw, B + (size_t)(n0 + r) * K + kk + c * 8);
        }
        cp_commit();
    };

    const int lr = lane & 15;
    const int lseg = lane >> 4;
    int arow[2], brow[4];
    #pragma unroll
    for (int t = 0; t < 2; t++) arow[t] = warp_m * 32 + t * 16 + lr;
    #pragma unroll
    for (int u = 0; u < 4; u++) brow[u] = warp_n * 64 + u * 16 + lr;

    const int nch = K >> 6;
    stage_load(0, 0);
    stage_load(1, 1);

    for (int i = 0; i < nch; i++) {
        if (i < nch - 1) asm volatile("cp.async.wait_group 1;" ::: "memory");
        else             asm volatile("cp.async.wait_group 0;" ::: "memory");
        __syncthreads();
        if (i + 2 < nch) stage_load(i + 2, (i + 2) % 3);

        const uint32_t sb = sbase + (i % 3) * G_STAGE;
        #pragma unroll
        for (int kc = 0; kc < 4; kc++) {
            const int chunk = 2 * kc + lseg;
            uint32_t ah[2][4], bh[4][4];
            #pragma unroll
            for (int t = 0; t < 2; t++) {
                uint32_t a = sb + arow[t] * 128 + ((chunk ^ (arow[t] & 7)) << 4);
                ldsm_x4(ah[t], a);
            }
            #pragma unroll
            for (int u = 0; u < 4; u++) {
                uint32_t a = sb + 16384 + brow[u] * 128 + ((chunk ^ (brow[u] & 7)) << 4);
                ldsm_x4(bh[u], a);
            }
            #pragma unroll
            for (int t = 0; t < 2; t++)
                #pragma unroll
                for (int u = 0; u < 4; u++) {
                    mma16816(acc[t][2 * u],     ah[t], bh[u][0], bh[u][2]);
                    mma16816(acc[t][2 * u + 1], ah[t], bh[u][1], bh[u][3]);
                }
        }
    }

    #pragma unroll
    for (int t = 0; t < 2; t++) {
        const int rbase = m0 + warp_m * 32 + t * 16 + (lane >> 2);
        #pragma unroll
        for (int j = 0; j < 8; j++) {
            const int col = n0 + warp_n * 64 + j * 8 + 2 * (lane & 3);
            const float b0 = __ldg(bias + col), b1 = __ldg(bias + col + 1);
            #pragma unroll
            for (int half = 0; half < 2; half++) {
                const int row = rbase + 8 * half;
                float v0 = acc[t][j][2 * half]     + b0;
                float v1 = acc[t][j][2 * half + 1] + b1;
                if (act) {
                    v0 = 0.5f * v0 * (1.0f + erff(v0 * 0.70710678118654752f));
                    v1 = 0.5f * v1 * (1.0f + erff(v1 * 0.70710678118654752f));
                }
                *(uint32_t*)(Oh + (size_t)row * N + col) = pack_h2(v0, v1);
            }
        }
    }
}

// ================= FA2-style attention (fp16) =================
#define AT_BUF  16384
#define AT_SMEM (3 * AT_BUF)

__global__ __launch_bounds__(128) void attn_mma(
    const __half* __restrict__ Q, int ldq, int qoff,
    const __half* __restrict__ Kb, int ldk, int koff,
    const __half* __restrict__ Vb, int ldv, int voff,
    __half* __restrict__ Oh,
    const float* __restrict__ bias, float scale)
{
    extern __shared__ __align__(128) char smem[];
    const uint32_t sbase = smem_u32(smem);
    const int tid = threadIdx.x, lane = tid & 31, w = tid >> 5;
    const int qt = blockIdx.x, bh = blockIdx.y;
    const int b = bh & (BATCH - 1), h = bh >> 5;

    #pragma unroll
    for (int it = 0; it < 4; it++) {
        int idx = tid + it * 128, r = idx >> 3, c = idx & 7;
        uint32_t sw = r * 128 + ((c ^ (r & 7)) << 4);
        size_t g = (size_t)((qt * 64 + r) * BATCH + b) * ldq + qoff + h * HDIM + c * 8;
        cp_async16(sbase + sw, Q + g);
    }
    cp_commit();
    asm volatile("cp.async.wait_group 0;" ::: "memory");
    __syncthreads();

    const int lr = lane & 15, ls = lane >> 4;
    uint32_t qh[4][4];
    {
        int qrow = w * 16 + lr;
        #pragma unroll
        for (int kc = 0; kc < 4; kc++) {
            int chunk = 2 * kc + ls;
            uint32_t a = sbase + qrow * 128 + ((chunk ^ (qrow & 7)) << 4);
            ldsm_x4(qh[kc], a);
        }
    }
    __syncthreads();

    auto load_kt = [&](int kt, int st) {
        uint32_t sb = sbase + st * AT_BUF;
        #pragma unroll
        for (int it = 0; it < 4; it++) {
            int idx = tid + it * 128, r = idx >> 3, c = idx & 7;
            uint32_t sw = r * 128 + ((c ^ (r & 7)) << 4);
            size_t rowi = (size_t)((kt * 64 + r) * BATCH + b);
            cp_async16(sb + sw,        Kb + rowi * ldk + koff + h * HDIM + c * 8);
            cp_async16(sb + 8192 + sw, Vb + rowi * ldv + voff + h * HDIM + c * 8);
        }
        cp_commit();
    };
    load_kt(0, 0);
    load_kt(1, 1);

    float o[8][4];
    #pragma unroll
    for (int t = 0; t < 8; t++)
        #pragma unroll
        for (int e = 0; e < 4; e++) o[t][e] = 0.0f;
    float mrow0 = -1e30f, mrow1 = -1e30f, lsum0 = 0.0f, lsum1 = 0.0f;

    const int vkbase = ((lane & 16) ? 8 : 0) + (lane & 7);
    const int vcsel  = (lane >> 3) & 1;

    for (int kt = 0; kt < 8; kt++) {
        if (kt < 7) asm volatile("cp.async.wait_group 1;" ::: "memory");
        else        asm volatile("cp.async.wait_group 0;" ::: "memory");
        __syncthreads();
        if (kt + 2 < 8) load_kt(kt + 2, (kt + 2) % 3);
        const uint32_t sb = sbase + (kt % 3) * AT_BUF;

        float s[8][4];
        #pragma unroll
        for (int t = 0; t < 8; t++)
            #pragma unroll
            for (int e = 0; e < 4; e++) s[t][e] = 0.0f;
        #pragma unroll
        for (int kc = 0; kc < 4; kc++) {
            uint32_t kh[4][4];
            #pragma unroll
            for (int u = 0; u < 4; u++) {
                int krow = u * 16 + lr, chunk = 2 * kc + ls;
                uint32_t a = sb + krow * 128 + ((chunk ^ (krow & 7)) << 4);
                ldsm_x4(kh[u], a);
            }
            #pragma unroll
            for (int u = 0; u < 4; u++) {
                mma16816(s[2 * u],     qh[kc], kh[u][0], kh[u][2]);
                mma16816(s[2 * u + 1], qh[kc], kh[u][1], kh[u][3]);
            }
        }

        const int row0 = qt * 64 + w * 16 + (lane >> 2);
        if (bias) {
            #pragma unroll
            for (int t = 0; t < 8; t++) {
                int col = kt * 64 + t * 8 + 2 * (lane & 3);
                float2 b0 = *(const float2*)(bias + (size_t)row0 * TA + col);
                float2 b1 = *(const float2*)(bias + (size_t)(row0 + 8) * TA + col);
                s[t][0] = s[t][0] * scale + b0.x; s[t][1] = s[t][1] * scale + b0.y;
                s[t][2] = s[t][2] * scale + b1.x; s[t][3] = s[t][3] * scale + b1.y;
            }
        } else {
            #pragma unroll
            for (int t = 0; t < 8; t++)
                #pragma unroll
                for (int e = 0; e < 4; e++) s[t][e] *= scale;
        }

        float mx0 = -1e30f, mx1 = -1e30f;
        #pragma unroll
        for (int t = 0; t < 8; t++) {
            mx0 = fmaxf(mx0, fmaxf(s[t][0], s[t][1]));
            mx1 = fmaxf(mx1, fmaxf(s[t][2], s[t][3]));
        }
        mx0 = fmaxf(mx0, __shfl_xor_sync(0xffffffffu, mx0, 1));
        mx0 = fmaxf(mx0, __shfl_xor_sync(0xffffffffu, mx0, 2));
        mx1 = fmaxf(mx1, __shfl_xor_sync(0xffffffffu, mx1, 1));
        mx1 = fmaxf(mx1, __shfl_xor_sync(0xffffffffu, mx1, 2));
        float mn0 = fmaxf(mrow0, mx0), mn1 = fmaxf(mrow1, mx1);
        float a0 = __expf(mrow0 - mn0), a1 = __expf(mrow1 - mn1);
        mrow0 = mn0; mrow1 = mn1;

        float sum0 = 0.0f, sum1 = 0.0f;
        uint32_t phi[4][4];
        #pragma unroll
        for (int t = 0; t < 8; t++) {
            float p0 = __expf(s[t][0] - mn0), p1 = __expf(s[t][1] - mn0);
            float p2 = __expf(s[t][2] - mn1), p3 = __expf(s[t][3] - mn1);
            sum0 += p0 + p1; sum1 += p2 + p3;
            const int kc = t >> 1, j = (t & 1) * 2;
            phi[kc][j]     = pack_h2(p0, p1);
            phi[kc][j + 1] = pack_h2(p2, p3);
        }
        sum0 += __shfl_xor_sync(0xffffffffu, sum0, 1);
        sum0 += __shfl_xor_sync(0xffffffffu, sum0, 2);
        sum1 += __shfl_xor_sync(0xffffffffu, sum1, 1);
        sum1 += __shfl_xor_sync(0xffffffffu, sum1, 2);
        lsum0 = lsum0 * a0 + sum0;
        lsum1 = lsum1 * a1 + sum1;
        #pragma unroll
        for (int t = 0; t < 8; t++) {
            o[t][0] *= a0; o[t][1] *= a0;
            o[t][2] *= a1; o[t][3] *= a1;
        }

        #pragma unroll
        for (int kc = 0; kc < 4; kc++) {
            int vkey = kc * 16 + vkbase;
            uint32_t vh[4][4];
            #pragma unroll
            for (int du = 0; du < 4; du++) {
                int chunk = 2 * du + vcsel;
                uint32_t a = sb + 8192 + vkey * 128 + ((chunk ^ (vkey & 7)) << 4);
                ldsm_x4_t(vh[du], a);
            }
            #pragma unroll
            for (int du = 0; du < 4; du++) {
                mma16816(o[2 * du],     phi[kc], vh[du][0], vh[du][2]);
                mma16816(o[2 * du + 1], phi[kc], vh[du][1], vh[du][3]);
            }
        }
    }

    float inv0 = 1.0f / lsum0, inv1 = 1.0f / lsum1;
    const int row0 = qt * 64 + w * 16 + (lane >> 2);
    #pragma unroll
    for (int t = 0; t < 8; t++) {
        int col = t * 8 + 2 * (lane & 3);
        size_t off0 = (size_t)(row0 * BATCH + b) * D_MODEL + h * HDIM + col;
        size_t off1 = (size_t)((row0 + 8) * BATCH + b) * D_MODEL + h * HDIM + col;
        *(uint32_t*)(Oh + off0) = pack_h2(o[t][0] * inv0, o[t][1] * inv0);
        *(uint32_t*)(Oh + off1) = pack_h2(o[t][2] * inv1, o[t][3] * inv1);
    }
}

// ---------------- Bias precompute ----------------
__global__ void bias_kernel(const int* __restrict__ beats, float* __restrict__ out) {
    __shared__ int sb[NBEATS];
    int i = blockIdx.x;
    int j = threadIdx.x;
    if (threadIdx.x < NBEATS) sb[threadIdx.x] = beats[threadIdx.x];
    __syncthreads();
    float bb = 0.0f;
    #pragma unroll 8
    for (int n = 0; n < NBEATS; n++) {
        int bf = sb[n];
        if (j == bf) bb = fmaxf(bb, 2.0f);
        if (bf > 0      && j == bf - 1) bb = fmaxf(bb, 1.0f);
        if (bf < TA - 1 && j == bf + 1) bb = fmaxf(bb, 1.0f);
    }
    float scale = (float)(TA - 1) / (float)(TM - 1);
    float d = (float)i * scale - (float)j;
    out[i * TA + j] = -(d * d) * (1.0f / 32.0f) + bb;
}

// ---------------- Fused residual + LayerNorm (fp16 branch in, optional fp16 out) ----------------
__global__ __launch_bounds__(256) void add_ln_kernel(
    const float* __restrict__ A, const __half* __restrict__ Bv,
    const float* __restrict__ gatePtr,
    const float* __restrict__ gamma, const float* __restrict__ beta,
    float* __restrict__ out, __half* __restrict__ oh)
{
    int t = blockIdx.x;
    int tid = threadIdx.x;
    float gscale = gatePtr ? tanhf(*gatePtr) : 1.0f;
    const float4* a4 = (const float4*)(A + (size_t)t * D_MODEL);
    const uint2*  b2 = (const uint2*)(Bv + (size_t)t * D_MODEL);
    float4 av = a4[tid];
    uint2 ub = b2[tid];
    __half2 h01 = *(__half2*)&ub.x;
    __half2 h23 = *(__half2*)&ub.y;
    float x0 = av.x + gscale * __low2float(h01);
    float x1 = av.y + gscale * __high2float(h01);
    float x2 = av.z + gscale * __low2float(h23);
    float x3 = av.w + gscale * __high2float(h23);
    float s  = x0 + x1 + x2 + x3;
    float ss = x0 * x0 + x1 * x1 + x2 * x2 + x3 * x3;

    __shared__ float rs[8], rss[8];
    #pragma unroll
    for (int o = 16; o > 0; o >>= 1) {
        s  += __shfl_xor_sync(0xffffffffu, s,  o);
        ss += __shfl_xor_sync(0xffffffffu, ss, o);
    }
    if ((tid & 31) == 0) { rs[tid >> 5] = s; rss[tid >> 5] = ss; }
    __syncthreads();
    float stot = 0.0f, sstot = 0.0f;
    #pragma unroll
    for (int i = 0; i < 8; i++) { stot += rs[i]; sstot += rss[i]; }
    float mean = stot * (1.0f / D_MODEL);
    float var  = sstot * (1.0f / D_MODEL) - mean * mean;
    float rstd = rsqrtf(var + LN_EPS);

    const float4* g4 = (const float4*)gamma;
    const float4* be4 = (const float4*)beta;
    float4 g = g4[tid], be = be4[tid];
    float4 o;
    o.x = (x0 - mean) * rstd * g.x + be.x;
    o.y = (x1 - mean) * rstd * g.y + be.y;
    o.z = (x2 - mean) * rstd * g.z + be.z;
    o.w = (x3 - mean) * rstd * g.w + be.w;
    ((float4*)(out + (size_t)t * D_MODEL))[tid] = o;
    if (oh) {
        uint2 uh;
        uh.x = pack_h2(o.x, o.y);
        uh.y = pack_h2(o.z, o.w);
        ((uint2*)(oh + (size_t)t * D_MODEL))[tid] = uh;
    }
}

// ---------------- Launch ----------------
extern "C" void kernel_launch(void* const* d_in, const int* in_sizes, int n_in,
                              void* d_out, int out_size) {
    const float* src      = (const float*)d_in[0];
    const float* audio    = (const float*)d_in[1];
    const int*   beats    = (const int*)  d_in[2];
    const float* sa_in_w  = (const float*)d_in[3];
    const float* sa_in_b  = (const float*)d_in[4];
    const float* sa_out_w = (const float*)d_in[5];
    const float* sa_out_b = (const float*)d_in[6];
    const float* ca_in_w  = (const float*)d_in[7];
    const float* ca_in_b  = (const float*)d_in[8];
    const float* ca_out_w = (const float*)d_in[9];
    const float* ca_out_b = (const float*)d_in[10];
    const float* gate     = (const float*)d_in[11];
    const float* n1_g     = (const float*)d_in[12];
    const float* n1_b     = (const float*)d_in[13];
    const float* nc_g     = (const float*)d_in[14];
    const float* nc_b     = (const float*)d_in[15];
    const float* n2_g     = (const float*)d_in[16];
    const float* n2_b     = (const float*)d_in[17];
    const float* lin1_w   = (const float*)d_in[18];
    const float* lin1_b   = (const float*)d_in[19];
    const float* lin2_w   = (const float*)d_in[20];
    const float* lin2_b   = (const float*)d_in[21];
    float* out = (float*)d_out;

    float *x1, *x2, *bias;
    __half *X, *AU, *TMP, *H, *W, *QKV, *KV, *CQ;
    cudaGetSymbolAddress((void**)&x1,   g_x1);
    cudaGetSymbolAddress((void**)&x2,   g_x2);
    cudaGetSymbolAddress((void**)&bias, g_bias);
    cudaGetSymbolAddress((void**)&X,    g_X);
    cudaGetSymbolAddress((void**)&AU,   g_AU);
    cudaGetSymbolAddress((void**)&TMP,  g_TMP);
    cudaGetSymbolAddress((void**)&H,    g_H);
    cudaGetSymbolAddress((void**)&W,    g_W);
    cudaGetSymbolAddress((void**)&QKV,  g_QKV);
    cudaGetSymbolAddress((void**)&KV,   g_KV);
    cudaGetSymbolAddress((void**)&CQ,   g_CQ);

    cudaFuncSetAttribute(gemm_mma, cudaFuncAttributeMaxDynamicSharedMemorySize, G_SMEM);
    cudaFuncSetAttribute(attn_mma, cudaFuncAttributeMaxDynamicSharedMemorySize, AT_SMEM);

    const int CVT_B = 256 * 4;
    #define H_NULL (__half*)nullptr
    #define GEMM1(a, bw, bp, oh, Nn, Kk, act) \
        gemm_mma<<<dim3((Nn) / 128, NTOK / 128), 256, G_SMEM>>>( \
            a, bw, bp, oh, Nn, Kk, act, H_NULL, H_NULL, nullptr, H_NULL, 0, 0)

    // 0-3) bias, weights, src + audio converts
    bias_kernel<<<TM, TA>>>(beats, bias);
    wcvt_kernel<<<W_TOTAL / CVT_B, 256>>>(sa_in_w, sa_out_w, ca_in_w, ca_out_w,
                                          lin1_w, lin2_w, W);
    cvt_kernel<<<NTOK * D_MODEL / CVT_B, 256>>>(src, X, NTOK * D_MODEL);
    cvt_kernel<<<NTOK * D_MODEL / CVT_B, 256>>>(audio, AU, NTOK * D_MODEL);

    // 4) fused: SA packed QKV (24 tiles) + CA KV-proj (16 tiles) in one grid
    gemm_mma<<<dim3(40, NTOK / 128), 256, G_SMEM>>>(
        X, W + W_SAIN, sa_in_b, QKV, 3 * D_MODEL, D_MODEL, 0,
        AU, W + W_CAIN + (size_t)D_MODEL * D_MODEL, ca_in_b + D_MODEL,
        KV, 2 * D_MODEL, 24);

    // 5) SA attention
    attn_mma<<<dim3(TM / 64, BATCH * NHEAD), 128, AT_SMEM>>>(
        QKV, 3 * D_MODEL, 0,
        QKV, 3 * D_MODEL, D_MODEL,
        QKV, 3 * D_MODEL, 2 * D_MODEL,
        X, nullptr, 0.125f);

    // 6) SA out-proj (fp16 out)
    GEMM1(X, W + W_SAOUT, sa_out_b, TMP, D_MODEL, D_MODEL, 0);

    // 7) x1 = LN1(src + sa), fused fp16 out
    add_ln_kernel<<<NTOK, 256>>>(src, TMP, nullptr, n1_g, n1_b, x1, X);

    // 8) CA Q-proj
    GEMM1(X, W + W_CAIN, ca_in_b, CQ, D_MODEL, D_MODEL, 0);

    // 9) CA attention (biased)
    attn_mma<<<dim3(TM / 64, BATCH * NHEAD), 128, AT_SMEM>>>(
        CQ, D_MODEL, 0,
        KV, 2 * D_MODEL, 0,
        KV, 2 * D_MODEL, D_MODEL,
        X, bias, 0.125f);

    // 10) CA out-proj (fp16 out)
    GEMM1(X, W + W_CAOUT, ca_out_b, TMP, D_MODEL, D_MODEL, 0);

    // 11) x2 = LNc(x1 + tanh(gate)*cross), fused fp16 out
    add_ln_kernel<<<NTOK, 256>>>(x1, TMP, gate, nc_g, nc_b, x2, X);

    // 12-13) FFN
    GEMM1(X, W + W_LIN1, lin1_b, H, DFF, D_MODEL, 1);
    GEMM1(H, W + W_LIN2, lin2_b, TMP, D_MODEL, DFF, 0);

    // 14) out = LN2(x2 + ff)
    add_ln_kernel<<<NTOK, 256>>>(x2, TMP, nullptr, n2_g, n2_b, out, H_NULL);
}